// round 6
// baseline (speedup 1.0000x reference)
#include <cuda_runtime.h>
#include <cuda_fp16.h>
#include <cstdint>

#define BLD   1024
#define DIM   768
#define LSEQ  512
#define NSTATE 16
#define NVOC  50257

// ---------------- fp32 scratch ----------------------------------------------
__device__ float g_x [BLD*DIM];
__device__ float g_xr[BLD*2*DIM];
__device__ float g_xc[BLD*DIM];
__device__ float g_dt[BLD*DIM];
// ---------------- split-fp16 activations -------------------------------------
__device__ __half g_ah_xn[BLD*DIM], g_al_xn[BLD*DIM];
__device__ __half g_ah_xc[BLD*DIM], g_al_xc[BLD*DIM];
__device__ __half g_ah_y [BLD*DIM], g_al_y [BLD*DIM];
// ---------------- split-fp16 weights (prepass output) ------------------------
__device__ __half g_wh_in [4*2*DIM*DIM], g_wl_in [4*2*DIM*DIM];
__device__ __half g_wh_dt [4*DIM*DIM],   g_wl_dt [4*DIM*DIM];
__device__ __half g_wh_out[4*DIM*DIM],   g_wl_out[4*DIM*DIM];
__device__ __half g_wh_hd [NVOC*DIM],    g_wl_hd [NVOC*DIM];

__device__ __forceinline__ float fast_sigmoid(float z) {
    return 1.0f / (1.0f + __expf(-z));
}
__device__ __forceinline__ void split_store(__half* ph, __half* pl, size_t i, float v) {
    __half h = __float2half_rn(v);
    ph[i] = h;
    pl[i] = __float2half_rn(v - __half2float(h));
}

// ---------------- weight split prepass ---------------------------------------
__global__ void wsplit_kernel(const float4* __restrict__ src,
                              uint2* __restrict__ dh, uint2* __restrict__ dl,
                              int n4) {
    int i = blockIdx.x * blockDim.x + threadIdx.x;
    if (i >= n4) return;
    float4 v = src[i];
    __half2 h01 = __floats2half2_rn(v.x, v.y);
    __half2 h23 = __floats2half2_rn(v.z, v.w);
    float2 f01 = __half22float2(h01), f23 = __half22float2(h23);
    __half2 l01 = __floats2half2_rn(v.x - f01.x, v.y - f01.y);
    __half2 l23 = __floats2half2_rn(v.z - f23.x, v.w - f23.y);
    dh[i] = make_uint2(*(unsigned*)&h01, *(unsigned*)&h23);
    dl[i] = make_uint2(*(unsigned*)&l01, *(unsigned*)&l23);
}

// ---------------- embedding gather --------------------------------------------
__global__ void embed_kernel(const int* __restrict__ tokens,
                             const float* __restrict__ emb) {
    int row = blockIdx.x;
    int tok = tokens[row];
    const float4* src = (const float4*)(emb + (size_t)tok * DIM);
    float4* dst = (float4*)(g_x + (size_t)row * DIM);
    dst[threadIdx.x] = src[threadIdx.x];
}

// ---------------- layernorm -> split fp16 --------------------------------------
__global__ void ln_kernel(const float* __restrict__ x,
                          const float* __restrict__ g,
                          const float* __restrict__ b,
                          __half* __restrict__ oh, __half* __restrict__ ol) {
    int row = blockIdx.x;
    const float* xp = x + (size_t)row * DIM;
    float s = 0.f, s2 = 0.f;
    for (int i = threadIdx.x; i < DIM; i += 256) {
        float v = xp[i];
        s += v; s2 += v * v;
    }
#pragma unroll
    for (int o = 16; o; o >>= 1) {
        s  += __shfl_xor_sync(0xffffffffu, s,  o);
        s2 += __shfl_xor_sync(0xffffffffu, s2, o);
    }
    __shared__ float sh[16];
    int w = threadIdx.x >> 5, lane = threadIdx.x & 31;
    if (lane == 0) { sh[w] = s; sh[8 + w] = s2; }
    __syncthreads();
    s = 0.f; s2 = 0.f;
#pragma unroll
    for (int i = 0; i < 8; i++) { s += sh[i]; s2 += sh[8 + i]; }
    float m   = s * (1.0f / DIM);
    float var = s2 * (1.0f / DIM) - m * m;
    float inv = rsqrtf(var + 1e-5f);
    for (int i = threadIdx.x; i < DIM; i += 256) {
        float v = (xp[i] - m) * inv * g[i] + b[i];
        split_store(oh, ol, (size_t)row * DIM + i, v);
    }
}

// ---------------- depthwise conv(3) + silu -------------------------------------
__global__ void conv_silu_kernel(const float* __restrict__ cw,
                                 const float* __restrict__ cb) {
    int idx = blockIdx.x * blockDim.x + threadIdx.x;
    if (idx >= BLD * DIM) return;
    int d = idx % DIM;
    int l = (idx / DIM) % LSEQ;
    int b = idx / (DIM * LSEQ);
    const float* base = g_xr + (size_t)b * LSEQ * (2 * DIM);
    float xm = (l > 0)        ? base[(size_t)(l - 1) * 2 * DIM + d] : 0.f;
    float x0 =                  base[(size_t)l       * 2 * DIM + d];
    float xp = (l < LSEQ - 1) ? base[(size_t)(l + 1) * 2 * DIM + d] : 0.f;
    float z = xm * cw[d * 3 + 0] + x0 * cw[d * 3 + 1] + xp * cw[d * 3 + 2] + cb[d];
    float v = z * fast_sigmoid(z);
    g_xc[idx] = v;
    split_store(g_ah_xc, g_al_xc, idx, v);
}

// ---------------- selective scan (exp hoisted off the h-chain) -----------------
__global__ void scan_kernel(const float* __restrict__ A_log,
                            const float* __restrict__ Dp) {
    int tid = blockIdx.x * blockDim.x + threadIdx.x;   // 24576
    int s = tid & (NSTATE - 1);
    int d = (tid >> 4) % DIM;
    int b = tid / (DIM * NSTATE);
    float A  = -__expf(A_log[d * NSTATE + s]);
    float Dd = Dp[d];
    const float* dtp  = g_dt + (size_t)b * LSEQ * DIM + d;
    const float* xcp  = g_xc + (size_t)b * LSEQ * DIM + d;
    const float* resp = g_xr + (size_t)b * LSEQ * (2 * DIM) + DIM + d;
    size_t ybase = (size_t)b * LSEQ * DIM + d;
    float h = 0.f;
    float e = __expf(A * dtp[0]);              // decay for step 0
    for (int l = 0; l < LSEQ; l++) {
        float enext = (l + 1 < LSEQ) ? __expf(A * dtp[(size_t)(l + 1) * DIM]) : 0.f;
        float xv = xcp[(size_t)l * DIM];
        h = h * e + xv;                        // only serial dependence
        e = enext;
        float sum = h;
        sum += __shfl_xor_sync(0xffffffffu, sum, 1);
        sum += __shfl_xor_sync(0xffffffffu, sum, 2);
        sum += __shfl_xor_sync(0xffffffffu, sum, 4);
        sum += __shfl_xor_sync(0xffffffffu, sum, 8);
        if (s == 0) {
            float r = resp[(size_t)l * 2 * DIM];
            float v = sum * Dd * (r * fast_sigmoid(r));
            split_store(g_ah_y, g_al_y, ybase + (size_t)l * DIM, v);
        }
    }
}

// ============ fp16 split-3-term mma.sync GEMM, 512 threads, no spills =========
// C[M,N] = epi(A[M,K]*B[N,K]^T), A=Ah+Al, B=Bh+Bl. acc = AhBh + AhBl + AlBh.
// 128x128 tile, BK=32, 16 warps 4(m)x4(n), warp tile 32x32, 2-stage cp.async.

#define STAGE_B 40960            // 4 matrices * 128 rows * 40hw * 2B
#define GEMM_SMEM (2 * STAGE_B)

__device__ __forceinline__ void ldsm4(unsigned r[4], unsigned a) {
    asm volatile("ldmatrix.sync.aligned.m8n8.x4.shared.b16 {%0,%1,%2,%3}, [%4];"
                 : "=r"(r[0]), "=r"(r[1]), "=r"(r[2]), "=r"(r[3]) : "r"(a));
}
__device__ __forceinline__ void mma_f16(float c[4], const unsigned a[4],
                                        const unsigned b[2]) {
    asm volatile(
        "mma.sync.aligned.m16n8k16.row.col.f32.f16.f16.f32 "
        "{%0,%1,%2,%3}, {%4,%5,%6,%7}, {%8,%9}, {%0,%1,%2,%3};"
        : "+f"(c[0]), "+f"(c[1]), "+f"(c[2]), "+f"(c[3])
        : "r"(a[0]), "r"(a[1]), "r"(a[2]), "r"(a[3]), "r"(b[0]), "r"(b[1]));
}
__device__ __forceinline__ void cpa16(unsigned dst, const void* src, int sz) {
    asm volatile("cp.async.cg.shared.global [%0], [%1], 16, %2;"
                 :: "r"(dst), "l"(src), "r"(sz));
}

template <int MODE>
__global__ void __launch_bounds__(512)
gemm_mma(const __half* __restrict__ Ah, const __half* __restrict__ Al,
         const __half* __restrict__ Bh, const __half* __restrict__ Bl,
         const float* __restrict__ bias, float* __restrict__ C,
         int N, int K) {
    extern __shared__ char smc[];
    unsigned sbase = (unsigned)__cvta_generic_to_shared(smc);
    int tid = threadIdx.x, lane = tid & 31, warp = tid >> 5;
    int wm = warp >> 2, wn = warp & 3;            // 4x4 warp grid
    int bm = blockIdx.x * 128, bn = blockIdx.y * 128;

    // ldsm byte offsets within a stage (stride 40 halves = conflict-free)
    unsigned aoff[2][2];
#pragma unroll
    for (int mi = 0; mi < 2; mi++)
#pragma unroll
        for (int ks = 0; ks < 2; ks++) {
            int row = wm * 32 + mi * 16 + (lane & 15);
            int col = ks * 16 + ((lane & 16) ? 8 : 0);
            aoff[mi][ks] = (unsigned)(row * 40 + col) * 2;
        }
    unsigned boff[4];
#pragma unroll
    for (int ni = 0; ni < 4; ni++) {
        int row = wn * 32 + ni * 8 + (lane & 7);
        int col = (lane >> 3) * 8;
        boff[ni] = 20480u + (unsigned)(row * 40 + col) * 2;
    }

    // cp.async mapping: one 16B chunk per matrix per thread
    int r  = tid >> 2;               // 0..127
    int cc = (tid & 3) * 8;          // halfword offset 0,8,16,24

    float acc[2][4][4];
#pragma unroll
    for (int mi = 0; mi < 2; mi++)
#pragma unroll
        for (int ni = 0; ni < 4; ni++)
#pragma unroll
            for (int q = 0; q < 4; q++) acc[mi][ni][q] = 0.f;

    int T = K / 32;
    int brow = bn + r;
    int crow = brow < N ? brow : (N - 1);
    int bsz  = brow < N ? 16 : 0;

#define FETCH(s, kt) do {                                                      \
        int k0 = (kt) * 32;                                                    \
        unsigned dst = sbase + (unsigned)(s) * STAGE_B +                       \
                       (unsigned)(r * 40 + cc) * 2;                            \
        cpa16(dst,           Ah + (size_t)(bm + r) * K + k0 + cc, 16);         \
        cpa16(dst + 10240u,  Al + (size_t)(bm + r) * K + k0 + cc, 16);         \
        cpa16(dst + 20480u,  Bh + (size_t)crow * K + k0 + cc, bsz);            \
        cpa16(dst + 30720u,  Bl + (size_t)crow * K + k0 + cc, bsz);            \
    } while (0)

    FETCH(0, 0);
    asm volatile("cp.async.commit_group;" ::: "memory");

    for (int i = 0; i < T; i++) {
        asm volatile("cp.async.wait_group 0;" ::: "memory");
        __syncthreads();                       // stage i%2 visible to all

        if (i + 1 < T) FETCH((i + 1) & 1, i + 1);
        asm volatile("cp.async.commit_group;" ::: "memory");

        unsigned st = sbase + (unsigned)(i & 1) * STAGE_B;
        unsigned Bhf[4][4], Blf[4][4];
#pragma unroll
        for (int ni = 0; ni < 4; ni++) {
            ldsm4(Bhf[ni], st + boff[ni]);
            ldsm4(Blf[ni], st + boff[ni] + 10240u);
        }
#pragma unroll
        for (int ks = 0; ks < 2; ks++) {
            unsigned Ahf[2][4], Alf[2][4];
#pragma unroll
            for (int mi = 0; mi < 2; mi++) {
                ldsm4(Ahf[mi], st + aoff[mi][ks]);
                ldsm4(Alf[mi], st + aoff[mi][ks] + 10240u);
            }
#pragma unroll
            for (int mi = 0; mi < 2; mi++)
#pragma unroll
                for (int ni = 0; ni < 4; ni++) {
                    mma_f16(acc[mi][ni], Ahf[mi], &Bhf[ni][2 * ks]);
                    mma_f16(acc[mi][ni], Ahf[mi], &Blf[ni][2 * ks]);
                    mma_f16(acc[mi][ni], Alf[mi], &Bhf[ni][2 * ks]);
                }
        }
    }
#undef FETCH

    // epilogue
#pragma unroll
    for (int mi = 0; mi < 2; mi++) {
        int rr = bm + wm * 32 + mi * 16 + (lane >> 2);
#pragma unroll
        for (int ni = 0; ni < 4; ni++) {
            int c0 = bn + wn * 32 + ni * 8 + (lane & 3) * 2;
            float* p0 = C + (size_t)rr * N + c0;
            float* p1 = C + (size_t)(rr + 8) * N + c0;
            float v0 = acc[mi][ni][0], v1 = acc[mi][ni][1];
            float v2 = acc[mi][ni][2], v3 = acc[mi][ni][3];
            if (MODE == 1) {
                float b0 = (c0 < N) ? bias[c0] : 0.f;
                float b1 = (c0 + 1 < N) ? bias[c0 + 1] : 0.f;
                v0 = fast_sigmoid(v0 + b0); v1 = fast_sigmoid(v1 + b1);
                v2 = fast_sigmoid(v2 + b0); v3 = fast_sigmoid(v3 + b1);
            }
            if (MODE == 2) {
                if (c0 < N)     { p0[0] += v0; p1[0] += v2; }
                if (c0 + 1 < N) { p0[1] += v1; p1[1] += v3; }
            } else {
                if (c0 < N)     { p0[0] = v0; p1[0] = v2; }
                if (c0 + 1 < N) { p0[1] = v1; p1[1] = v3; }
            }
        }
    }
}

// ---------------- driver ---------------------------------------------------------
extern "C" void kernel_launch(void* const* d_in, const int* in_sizes, int n_in,
                              void* d_out, int out_size) {
    const int*   tokens = (const int*)  d_in[0];
    const float* emb    = (const float*)d_in[1];
    const float* ln_g   = (const float*)d_in[2];
    const float* ln_b   = (const float*)d_in[3];
    const float* in_w   = (const float*)d_in[4];
    const float* conv_w = (const float*)d_in[5];
    const float* conv_b = (const float*)d_in[6];
    const float* dt_w   = (const float*)d_in[7];
    const float* dt_b   = (const float*)d_in[8];
    const float* A_log  = (const float*)d_in[9];
    const float* D_par  = (const float*)d_in[10];
    const float* out_w  = (const float*)d_in[11];
    const float* lnf_g  = (const float*)d_in[12];
    const float* lnf_b  = (const float*)d_in[13];
    const float* head_w = (const float*)d_in[14];
    float* out = (float*)d_out;

    float *x, *xr, *xc, *dt;
    cudaGetSymbolAddress((void**)&x,  g_x);
    cudaGetSymbolAddress((void**)&xr, g_xr);
    cudaGetSymbolAddress((void**)&xc, g_xc);
    cudaGetSymbolAddress((void**)&dt, g_dt);
    __half *ah_xn, *al_xn, *ah_xc, *al_xc, *ah_y, *al_y;
    cudaGetSymbolAddress((void**)&ah_xn, g_ah_xn);
    cudaGetSymbolAddress((void**)&al_xn, g_al_xn);
    cudaGetSymbolAddress((void**)&ah_xc, g_ah_xc);
    cudaGetSymbolAddress((void**)&al_xc, g_al_xc);
    cudaGetSymbolAddress((void**)&ah_y,  g_ah_y);
    cudaGetSymbolAddress((void**)&al_y,  g_al_y);
    __half *wh_in, *wl_in, *wh_dt, *wl_dt, *wh_out, *wl_out, *wh_hd, *wl_hd;
    cudaGetSymbolAddress((void**)&wh_in,  g_wh_in);
    cudaGetSymbolAddress((void**)&wl_in,  g_wl_in);
    cudaGetSymbolAddress((void**)&wh_dt,  g_wh_dt);
    cudaGetSymbolAddress((void**)&wl_dt,  g_wl_dt);
    cudaGetSymbolAddress((void**)&wh_out, g_wh_out);
    cudaGetSymbolAddress((void**)&wl_out, g_wl_out);
    cudaGetSymbolAddress((void**)&wh_hd,  g_wh_hd);
    cudaGetSymbolAddress((void**)&wl_hd,  g_wl_hd);

    cudaFuncSetAttribute(gemm_mma<0>, cudaFuncAttributeMaxDynamicSharedMemorySize, GEMM_SMEM);
    cudaFuncSetAttribute(gemm_mma<1>, cudaFuncAttributeMaxDynamicSharedMemorySize, GEMM_SMEM);
    cudaFuncSetAttribute(gemm_mma<2>, cudaFuncAttributeMaxDynamicSharedMemorySize, GEMM_SMEM);

    int n4_in = 4 * 2 * DIM * DIM / 4, n4_dt = 4 * DIM * DIM / 4;
    int n4_hd = NVOC * DIM / 4;

    // launch order chosen so an ncu capture lands on a GEMM (launch #4)
    wsplit_kernel<<<(n4_in + 255) / 256, 256>>>((const float4*)in_w,
                                                (uint2*)wh_in, (uint2*)wl_in, n4_in);
    embed_kernel<<<BLD, 192>>>(tokens, emb);

    for (int l = 0; l < 4; l++) {
        ln_kernel<<<BLD, 256>>>(x, ln_g + l * DIM, ln_b + l * DIM, ah_xn, al_xn);
        gemm_mma<0><<<dim3(8, 12), 512, GEMM_SMEM>>>(
            ah_xn, al_xn, wh_in + (size_t)l * 2 * DIM * DIM,
            wl_in + (size_t)l * 2 * DIM * DIM, nullptr, xr, 2 * DIM, DIM);
        if (l == 0) {
            wsplit_kernel<<<(n4_dt + 255) / 256, 256>>>((const float4*)dt_w,
                                                        (uint2*)wh_dt, (uint2*)wl_dt, n4_dt);
        }
        conv_silu_kernel<<<(BLD * DIM + 255) / 256, 256>>>(conv_w + l * DIM * 3,
                                                           conv_b + l * DIM);
        gemm_mma<1><<<dim3(8, 6), 512, GEMM_SMEM>>>(
            ah_xc, al_xc, wh_dt + (size_t)l * DIM * DIM,
            wl_dt + (size_t)l * DIM * DIM, dt_b + l * DIM, dt, DIM, DIM);
        if (l == 0) {
            wsplit_kernel<<<(n4_dt + 255) / 256, 256>>>((const float4*)out_w,
                                                        (uint2*)wh_out, (uint2*)wl_out, n4_dt);
        }
        scan_kernel<<<192, 128>>>(A_log + l * DIM * NSTATE, D_par + l * DIM);
        gemm_mma<2><<<dim3(8, 6), 512, GEMM_SMEM>>>(
            ah_y, al_y, wh_out + (size_t)l * DIM * DIM,
            wl_out + (size_t)l * DIM * DIM, nullptr, x, DIM, DIM);
        if (l == 0) {
            wsplit_kernel<<<(n4_hd + 255) / 256, 256>>>((const float4*)head_w,
                                                        (uint2*)wh_hd, (uint2*)wl_hd, n4_hd);
        }
    }

    ln_kernel<<<BLD, 256>>>(x, lnf_g, lnf_b, ah_xn, al_xn);
    gemm_mma<0><<<dim3(8, (NVOC + 127) / 128), 512, GEMM_SMEM>>>(
        ah_xn, al_xn, wh_hd, wl_hd, nullptr, out, NVOC, DIM);
    (void)in_sizes; (void)n_in; (void)out_size;
}

// round 7
// speedup vs baseline: 1.0053x; 1.0053x over previous
#include <cuda_runtime.h>
#include <cuda_fp16.h>
#include <cstdint>

#define BLD   1024
#define DIM   768
#define LSEQ  512
#define NSTATE 16
#define NVOC  50257

// ---------------- fp32 scratch ----------------------------------------------
__device__ float g_x [BLD*DIM];
__device__ float g_xr[BLD*2*DIM];
__device__ float g_xc[BLD*DIM];
__device__ float g_dt[BLD*DIM];
// ---------------- split-fp16 activations -------------------------------------
__device__ __half g_ah_xn[BLD*DIM], g_al_xn[BLD*DIM];
__device__ __half g_ah_xc[BLD*DIM], g_al_xc[BLD*DIM];
__device__ __half g_ah_y [BLD*DIM], g_al_y [BLD*DIM];
// ---------------- split-fp16 weights (prepass output) ------------------------
__device__ __half g_wh_in [4*2*DIM*DIM], g_wl_in [4*2*DIM*DIM];
__device__ __half g_wh_dt [4*DIM*DIM],   g_wl_dt [4*DIM*DIM];
__device__ __half g_wh_out[4*DIM*DIM],   g_wl_out[4*DIM*DIM];
__device__ __half g_wh_hd [NVOC*DIM],    g_wl_hd [NVOC*DIM];

__device__ __forceinline__ float fast_sigmoid(float z) {
    return 1.0f / (1.0f + __expf(-z));
}
__device__ __forceinline__ void split_store(__half* ph, __half* pl, size_t i, float v) {
    __half h = __float2half_rn(v);
    ph[i] = h;
    pl[i] = __float2half_rn(v - __half2float(h));
}

// ---------------- weight split prepass ---------------------------------------
__global__ void wsplit_kernel(const float4* __restrict__ src,
                              uint2* __restrict__ dh, uint2* __restrict__ dl,
                              int n4) {
    int i = blockIdx.x * blockDim.x + threadIdx.x;
    if (i >= n4) return;
    float4 v = src[i];
    __half2 h01 = __floats2half2_rn(v.x, v.y);
    __half2 h23 = __floats2half2_rn(v.z, v.w);
    float2 f01 = __half22float2(h01), f23 = __half22float2(h23);
    __half2 l01 = __floats2half2_rn(v.x - f01.x, v.y - f01.y);
    __half2 l23 = __floats2half2_rn(v.z - f23.x, v.w - f23.y);
    dh[i] = make_uint2(*(unsigned*)&h01, *(unsigned*)&h23);
    dl[i] = make_uint2(*(unsigned*)&l01, *(unsigned*)&l23);
}

// ---------------- embedding gather --------------------------------------------
__global__ void embed_kernel(const int* __restrict__ tokens,
                             const float* __restrict__ emb) {
    int row = blockIdx.x;
    int tok = tokens[row];
    const float4* src = (const float4*)(emb + (size_t)tok * DIM);
    float4* dst = (float4*)(g_x + (size_t)row * DIM);
    dst[threadIdx.x] = src[threadIdx.x];
}

// ---------------- layernorm -> split fp16 --------------------------------------
__global__ void ln_kernel(const float* __restrict__ x,
                          const float* __restrict__ g,
                          const float* __restrict__ b,
                          __half* __restrict__ oh, __half* __restrict__ ol) {
    int row = blockIdx.x;
    const float* xp = x + (size_t)row * DIM;
    float s = 0.f, s2 = 0.f;
    for (int i = threadIdx.x; i < DIM; i += 256) {
        float v = xp[i];
        s += v; s2 += v * v;
    }
#pragma unroll
    for (int o = 16; o; o >>= 1) {
        s  += __shfl_xor_sync(0xffffffffu, s,  o);
        s2 += __shfl_xor_sync(0xffffffffu, s2, o);
    }
    __shared__ float sh[16];
    int w = threadIdx.x >> 5, lane = threadIdx.x & 31;
    if (lane == 0) { sh[w] = s; sh[8 + w] = s2; }
    __syncthreads();
    s = 0.f; s2 = 0.f;
#pragma unroll
    for (int i = 0; i < 8; i++) { s += sh[i]; s2 += sh[8 + i]; }
    float m   = s * (1.0f / DIM);
    float var = s2 * (1.0f / DIM) - m * m;
    float inv = rsqrtf(var + 1e-5f);
    for (int i = threadIdx.x; i < DIM; i += 256) {
        float v = (xp[i] - m) * inv * g[i] + b[i];
        split_store(oh, ol, (size_t)row * DIM + i, v);
    }
}

// ---------------- depthwise conv(3) + silu -------------------------------------
__global__ void conv_silu_kernel(const float* __restrict__ cw,
                                 const float* __restrict__ cb) {
    int idx = blockIdx.x * blockDim.x + threadIdx.x;
    if (idx >= BLD * DIM) return;
    int d = idx % DIM;
    int l = (idx / DIM) % LSEQ;
    int b = idx / (DIM * LSEQ);
    const float* base = g_xr + (size_t)b * LSEQ * (2 * DIM);
    float xm = (l > 0)        ? base[(size_t)(l - 1) * 2 * DIM + d] : 0.f;
    float x0 =                  base[(size_t)l       * 2 * DIM + d];
    float xp = (l < LSEQ - 1) ? base[(size_t)(l + 1) * 2 * DIM + d] : 0.f;
    float z = xm * cw[d * 3 + 0] + x0 * cw[d * 3 + 1] + xp * cw[d * 3 + 2] + cb[d];
    float v = z * fast_sigmoid(z);
    g_xc[idx] = v;
    split_store(g_ah_xc, g_al_xc, idx, v);
}

// ---------------- selective scan (exp hoisted off the h-chain) -----------------
__global__ void scan_kernel(const float* __restrict__ A_log,
                            const float* __restrict__ Dp) {
    int tid = blockIdx.x * blockDim.x + threadIdx.x;   // 24576
    int s = tid & (NSTATE - 1);
    int d = (tid >> 4) % DIM;
    int b = tid / (DIM * NSTATE);
    float A  = -__expf(A_log[d * NSTATE + s]);
    float Dd = Dp[d];
    const float* dtp  = g_dt + (size_t)b * LSEQ * DIM + d;
    const float* xcp  = g_xc + (size_t)b * LSEQ * DIM + d;
    const float* resp = g_xr + (size_t)b * LSEQ * (2 * DIM) + DIM + d;
    size_t ybase = (size_t)b * LSEQ * DIM + d;
    float h = 0.f;
    float e = __expf(A * dtp[0]);              // decay for step 0
    for (int l = 0; l < LSEQ; l++) {
        float enext = (l + 1 < LSEQ) ? __expf(A * dtp[(size_t)(l + 1) * DIM]) : 0.f;
        float xv = xcp[(size_t)l * DIM];
        h = h * e + xv;                        // only serial dependence
        e = enext;
        float sum = h;
        sum += __shfl_xor_sync(0xffffffffu, sum, 1);
        sum += __shfl_xor_sync(0xffffffffu, sum, 2);
        sum += __shfl_xor_sync(0xffffffffu, sum, 4);
        sum += __shfl_xor_sync(0xffffffffu, sum, 8);
        if (s == 0) {
            float r = resp[(size_t)l * 2 * DIM];
            float v = sum * Dd * (r * fast_sigmoid(r));
            split_store(g_ah_y, g_al_y, ybase + (size_t)l * DIM, v);
        }
    }
}

// ====== fp16 split-3-term mma.sync GEMM, 512 threads, 4-stage cp.async =======
// C[M,N] = epi(A[M,K]*B[N,K]^T), A=Ah+Al, B=Bh+Bl. acc = AhBh + AhBl + AlBh.
// 128x128 tile, BK=32, 16 warps 4(m)x4(n), warp tile 32x32.
// 4 stages + wait_group 2 -> ~3 compute phases to hide fetch latency.

#define STAGE_B 40960            // 4 matrices * 128 rows * 40hw * 2B
#define NSTG    4
#define GEMM_SMEM (NSTG * STAGE_B)

__device__ __forceinline__ void ldsm4(unsigned r[4], unsigned a) {
    asm volatile("ldmatrix.sync.aligned.m8n8.x4.shared.b16 {%0,%1,%2,%3}, [%4];"
                 : "=r"(r[0]), "=r"(r[1]), "=r"(r[2]), "=r"(r[3]) : "r"(a));
}
__device__ __forceinline__ void mma_f16(float c[4], const unsigned a[4],
                                        const unsigned b[2]) {
    asm volatile(
        "mma.sync.aligned.m16n8k16.row.col.f32.f16.f16.f32 "
        "{%0,%1,%2,%3}, {%4,%5,%6,%7}, {%8,%9}, {%0,%1,%2,%3};"
        : "+f"(c[0]), "+f"(c[1]), "+f"(c[2]), "+f"(c[3])
        : "r"(a[0]), "r"(a[1]), "r"(a[2]), "r"(a[3]), "r"(b[0]), "r"(b[1]));
}
__device__ __forceinline__ void cpa16(unsigned dst, const void* src, int sz) {
    asm volatile("cp.async.cg.shared.global [%0], [%1], 16, %2;"
                 :: "r"(dst), "l"(src), "r"(sz));
}

template <int MODE>
__global__ void __launch_bounds__(512)
gemm_mma(const __half* __restrict__ Ah, const __half* __restrict__ Al,
         const __half* __restrict__ Bh, const __half* __restrict__ Bl,
         const float* __restrict__ bias, float* __restrict__ C,
         int N, int K) {
    extern __shared__ char smc[];
    unsigned sbase = (unsigned)__cvta_generic_to_shared(smc);
    int tid = threadIdx.x, lane = tid & 31, warp = tid >> 5;
    int wm = warp >> 2, wn = warp & 3;            // 4x4 warp grid
    int bm = blockIdx.x * 128, bn = blockIdx.y * 128;

    // ldsm byte offsets within a stage (stride 40 halves = conflict-free)
    unsigned aoff[2][2];
#pragma unroll
    for (int mi = 0; mi < 2; mi++)
#pragma unroll
        for (int ks = 0; ks < 2; ks++) {
            int row = wm * 32 + mi * 16 + (lane & 15);
            int col = ks * 16 + ((lane & 16) ? 8 : 0);
            aoff[mi][ks] = (unsigned)(row * 40 + col) * 2;
        }
    unsigned boff[4];
#pragma unroll
    for (int ni = 0; ni < 4; ni++) {
        int row = wn * 32 + ni * 8 + (lane & 7);
        int col = (lane >> 3) * 8;
        boff[ni] = 20480u + (unsigned)(row * 40 + col) * 2;
    }

    // cp.async mapping: one 16B chunk per matrix per thread
    int r  = tid >> 2;               // 0..127
    int cc = (tid & 3) * 8;          // halfword offset 0,8,16,24

    float acc[2][4][4];
#pragma unroll
    for (int mi = 0; mi < 2; mi++)
#pragma unroll
        for (int ni = 0; ni < 4; ni++)
#pragma unroll
            for (int q = 0; q < 4; q++) acc[mi][ni][q] = 0.f;

    int T = K / 32;
    int brow = bn + r;
    int crow = brow < N ? brow : (N - 1);
    int bsz  = brow < N ? 16 : 0;

#define FETCH(s, kt) do {                                                      \
        int k0 = (kt) * 32;                                                    \
        unsigned dst = sbase + (unsigned)(s) * STAGE_B +                       \
                       (unsigned)(r * 40 + cc) * 2;                            \
        cpa16(dst,           Ah + (size_t)(bm + r) * K + k0 + cc, 16);         \
        cpa16(dst + 10240u,  Al + (size_t)(bm + r) * K + k0 + cc, 16);         \
        cpa16(dst + 20480u,  Bh + (size_t)crow * K + k0 + cc, bsz);            \
        cpa16(dst + 30720u,  Bl + (size_t)crow * K + k0 + cc, bsz);            \
    } while (0)

    FETCH(0, 0);
    asm volatile("cp.async.commit_group;" ::: "memory");
    FETCH(1, 1);
    asm volatile("cp.async.commit_group;" ::: "memory");
    FETCH(2, 2);
    asm volatile("cp.async.commit_group;" ::: "memory");

    for (int i = 0; i < T; i++) {
        asm volatile("cp.async.wait_group 2;" ::: "memory");  // stage i ready
        __syncthreads();

        // write stage (i+3)%4 == (i-1)%4: its readers passed the barrier above
        if (i + 3 < T) FETCH((i + 3) & (NSTG - 1), i + 3);
        asm volatile("cp.async.commit_group;" ::: "memory");

        unsigned st = sbase + (unsigned)(i & (NSTG - 1)) * STAGE_B;
        unsigned Bhf[4][4], Blf[4][4];
#pragma unroll
        for (int ni = 0; ni < 4; ni++) {
            ldsm4(Bhf[ni], st + boff[ni]);
            ldsm4(Blf[ni], st + boff[ni] + 10240u);
        }
#pragma unroll
        for (int ks = 0; ks < 2; ks++) {
            unsigned Ahf[2][4], Alf[2][4];
#pragma unroll
            for (int mi = 0; mi < 2; mi++) {
                ldsm4(Ahf[mi], st + aoff[mi][ks]);
                ldsm4(Alf[mi], st + aoff[mi][ks] + 10240u);
            }
#pragma unroll
            for (int mi = 0; mi < 2; mi++)
#pragma unroll
                for (int ni = 0; ni < 4; ni++) {
                    mma_f16(acc[mi][ni], Ahf[mi], &Bhf[ni][2 * ks]);
                    mma_f16(acc[mi][ni], Ahf[mi], &Blf[ni][2 * ks]);
                    mma_f16(acc[mi][ni], Alf[mi], &Bhf[ni][2 * ks]);
                }
        }
    }
#undef FETCH

    // epilogue
#pragma unroll
    for (int mi = 0; mi < 2; mi++) {
        int rr = bm + wm * 32 + mi * 16 + (lane >> 2);
#pragma unroll
        for (int ni = 0; ni < 4; ni++) {
            int c0 = bn + wn * 32 + ni * 8 + (lane & 3) * 2;
            float* p0 = C + (size_t)rr * N + c0;
            float* p1 = C + (size_t)(rr + 8) * N + c0;
            float v0 = acc[mi][ni][0], v1 = acc[mi][ni][1];
            float v2 = acc[mi][ni][2], v3 = acc[mi][ni][3];
            if (MODE == 1) {
                float b0 = (c0 < N) ? bias[c0] : 0.f;
                float b1 = (c0 + 1 < N) ? bias[c0 + 1] : 0.f;
                v0 = fast_sigmoid(v0 + b0); v1 = fast_sigmoid(v1 + b1);
                v2 = fast_sigmoid(v2 + b0); v3 = fast_sigmoid(v3 + b1);
            }
            if (MODE == 2) {
                if (c0 < N)     { p0[0] += v0; p1[0] += v2; }
                if (c0 + 1 < N) { p0[1] += v1; p1[1] += v3; }
            } else {
                if (c0 < N)     { p0[0] = v0; p1[0] = v2; }
                if (c0 + 1 < N) { p0[1] = v1; p1[1] = v3; }
            }
        }
    }
}

// ---------------- driver ---------------------------------------------------------
extern "C" void kernel_launch(void* const* d_in, const int* in_sizes, int n_in,
                              void* d_out, int out_size) {
    const int*   tokens = (const int*)  d_in[0];
    const float* emb    = (const float*)d_in[1];
    const float* ln_g   = (const float*)d_in[2];
    const float* ln_b   = (const float*)d_in[3];
    const float* in_w   = (const float*)d_in[4];
    const float* conv_w = (const float*)d_in[5];
    const float* conv_b = (const float*)d_in[6];
    const float* dt_w   = (const float*)d_in[7];
    const float* dt_b   = (const float*)d_in[8];
    const float* A_log  = (const float*)d_in[9];
    const float* D_par  = (const float*)d_in[10];
    const float* out_w  = (const float*)d_in[11];
    const float* lnf_g  = (const float*)d_in[12];
    const float* lnf_b  = (const float*)d_in[13];
    const float* head_w = (const float*)d_in[14];
    float* out = (float*)d_out;

    float *x, *xr, *xc, *dt;
    cudaGetSymbolAddress((void**)&x,  g_x);
    cudaGetSymbolAddress((void**)&xr, g_xr);
    cudaGetSymbolAddress((void**)&xc, g_xc);
    cudaGetSymbolAddress((void**)&dt, g_dt);
    __half *ah_xn, *al_xn, *ah_xc, *al_xc, *ah_y, *al_y;
    cudaGetSymbolAddress((void**)&ah_xn, g_ah_xn);
    cudaGetSymbolAddress((void**)&al_xn, g_al_xn);
    cudaGetSymbolAddress((void**)&ah_xc, g_ah_xc);
    cudaGetSymbolAddress((void**)&al_xc, g_al_xc);
    cudaGetSymbolAddress((void**)&ah_y,  g_ah_y);
    cudaGetSymbolAddress((void**)&al_y,  g_al_y);
    __half *wh_in, *wl_in, *wh_dt, *wl_dt, *wh_out, *wl_out, *wh_hd, *wl_hd;
    cudaGetSymbolAddress((void**)&wh_in,  g_wh_in);
    cudaGetSymbolAddress((void**)&wl_in,  g_wl_in);
    cudaGetSymbolAddress((void**)&wh_dt,  g_wh_dt);
    cudaGetSymbolAddress((void**)&wl_dt,  g_wl_dt);
    cudaGetSymbolAddress((void**)&wh_out, g_wh_out);
    cudaGetSymbolAddress((void**)&wl_out, g_wl_out);
    cudaGetSymbolAddress((void**)&wh_hd,  g_wh_hd);
    cudaGetSymbolAddress((void**)&wl_hd,  g_wl_hd);

    cudaFuncSetAttribute(gemm_mma<0>, cudaFuncAttributeMaxDynamicSharedMemorySize, GEMM_SMEM);
    cudaFuncSetAttribute(gemm_mma<1>, cudaFuncAttributeMaxDynamicSharedMemorySize, GEMM_SMEM);
    cudaFuncSetAttribute(gemm_mma<2>, cudaFuncAttributeMaxDynamicSharedMemorySize, GEMM_SMEM);

    int n4_in = 4 * 2 * DIM * DIM / 4, n4_dt = 4 * DIM * DIM / 4;
    int n4_hd = NVOC * DIM / 4;

    // launch order chosen so an ncu capture lands on a GEMM (launch #4)
    wsplit_kernel<<<(n4_in + 255) / 256, 256>>>((const float4*)in_w,
                                                (uint2*)wh_in, (uint2*)wl_in, n4_in);
    embed_kernel<<<BLD, 192>>>(tokens, emb);

    for (int l = 0; l < 4; l++) {
        ln_kernel<<<BLD, 256>>>(x, ln_g + l * DIM, ln_b + l * DIM, ah_xn, al_xn);
        gemm_mma<0><<<dim3(8, 12), 512, GEMM_SMEM>>>(
            ah_xn, al_xn, wh_in + (size_t)l * 2 * DIM * DIM,
            wl_in + (size_t)l * 2 * DIM * DIM, nullptr, xr, 2 * DIM, DIM);
        if (l == 0) {
            wsplit_kernel<<<(n4_dt + 255) / 256, 256>>>((const float4*)dt_w,
                                                        (uint2*)wh_dt, (uint2*)wl_dt, n4_dt);
        }
        conv_silu_kernel<<<(BLD * DIM + 255) / 256, 256>>>(conv_w + l * DIM * 3,
                                                           conv_b + l * DIM);
        gemm_mma<1><<<dim3(8, 6), 512, GEMM_SMEM>>>(
            ah_xc, al_xc, wh_dt + (size_t)l * DIM * DIM,
            wl_dt + (size_t)l * DIM * DIM, dt_b + l * DIM, dt, DIM, DIM);
        if (l == 0) {
            wsplit_kernel<<<(n4_dt + 255) / 256, 256>>>((const float4*)out_w,
                                                        (uint2*)wh_out, (uint2*)wl_out, n4_dt);
        }
        scan_kernel<<<192, 128>>>(A_log + l * DIM * NSTATE, D_par + l * DIM);
        gemm_mma<2><<<dim3(8, 6), 512, GEMM_SMEM>>>(
            ah_y, al_y, wh_out + (size_t)l * DIM * DIM,
            wl_out + (size_t)l * DIM * DIM, nullptr, x, DIM, DIM);
        if (l == 0) {
            wsplit_kernel<<<(n4_hd + 255) / 256, 256>>>((const float4*)head_w,
                                                        (uint2*)wh_hd, (uint2*)wl_hd, n4_hd);
        }
    }

    ln_kernel<<<BLD, 256>>>(x, lnf_g, lnf_b, ah_xn, al_xn);
    gemm_mma<0><<<dim3(8, (NVOC + 127) / 128), 512, GEMM_SMEM>>>(
        ah_xn, al_xn, wh_hd, wl_hd, nullptr, out, NVOC, DIM);
    (void)in_sizes; (void)n_in; (void)out_size;
}

// round 9
// speedup vs baseline: 1.0862x; 1.0805x over previous
#include <cuda_runtime.h>
#include <cuda_fp16.h>
#include <cstdint>

#define BLD   1024
#define DIM   768
#define LSEQ  512
#define NSTATE 16
#define NVOC  50257

// ---------------- fp32 scratch ----------------------------------------------
__device__ float g_x [BLD*DIM];
__device__ float g_xr[BLD*2*DIM];
__device__ float g_xc[BLD*DIM];
__device__ float g_dt[BLD*DIM];
// ---------------- split-fp16 activations -------------------------------------
__device__ __half g_ah_xn[BLD*DIM], g_al_xn[BLD*DIM];
__device__ __half g_ah_xc[BLD*DIM], g_al_xc[BLD*DIM];
__device__ __half g_ah_y [BLD*DIM], g_al_y [BLD*DIM];
// ---------------- fp16 weights (prepass output) ------------------------------
__device__ __half g_wh_in [4*2*DIM*DIM], g_wl_in [4*2*DIM*DIM];
__device__ __half g_wh_dt [4*DIM*DIM],   g_wl_dt [4*DIM*DIM];
__device__ __half g_wh_out[4*DIM*DIM],   g_wl_out[4*DIM*DIM];
__device__ __half g_wh_hd [NVOC*DIM];    // head: hi only (2-term split-A)

__device__ __forceinline__ float fast_sigmoid(float z) {
    return 1.0f / (1.0f + __expf(-z));
}
__device__ __forceinline__ void split_store(__half* ph, __half* pl, size_t i, float v) {
    __half h = __float2half_rn(v);
    ph[i] = h;
    pl[i] = __float2half_rn(v - __half2float(h));
}

// ---------------- weight prepasses --------------------------------------------
__global__ void wsplit2_kernel(const float4* __restrict__ src,
                               uint2* __restrict__ dh, uint2* __restrict__ dl,
                               int n4) {
    int i = blockIdx.x * blockDim.x + threadIdx.x;
    if (i >= n4) return;
    float4 v = src[i];
    __half2 h01 = __floats2half2_rn(v.x, v.y);
    __half2 h23 = __floats2half2_rn(v.z, v.w);
    float2 f01 = __half22float2(h01), f23 = __half22float2(h23);
    __half2 l01 = __floats2half2_rn(v.x - f01.x, v.y - f01.y);
    __half2 l23 = __floats2half2_rn(v.z - f23.x, v.w - f23.y);
    dh[i] = make_uint2(*(unsigned*)&h01, *(unsigned*)&h23);
    dl[i] = make_uint2(*(unsigned*)&l01, *(unsigned*)&l23);
}
__global__ void wsplit1_kernel(const float4* __restrict__ src,
                               uint2* __restrict__ dh, int n4) {
    int i = blockIdx.x * blockDim.x + threadIdx.x;
    if (i >= n4) return;
    float4 v = src[i];
    __half2 h01 = __floats2half2_rn(v.x, v.y);
    __half2 h23 = __floats2half2_rn(v.z, v.w);
    dh[i] = make_uint2(*(unsigned*)&h01, *(unsigned*)&h23);
}

// ---------------- embedding gather --------------------------------------------
__global__ void embed_kernel(const int* __restrict__ tokens,
                             const float* __restrict__ emb) {
    int row = blockIdx.x;
    int tok = tokens[row];
    const float4* src = (const float4*)(emb + (size_t)tok * DIM);
    float4* dst = (float4*)(g_x + (size_t)row * DIM);
    dst[threadIdx.x] = src[threadIdx.x];
}

// ---------------- layernorm -> split fp16 --------------------------------------
__global__ void ln_kernel(const float* __restrict__ x,
                          const float* __restrict__ g,
                          const float* __restrict__ b,
                          __half* __restrict__ oh, __half* __restrict__ ol) {
    int row = blockIdx.x;
    const float* xp = x + (size_t)row * DIM;
    float s = 0.f, s2 = 0.f;
    for (int i = threadIdx.x; i < DIM; i += 256) {
        float v = xp[i];
        s += v; s2 += v * v;
    }
#pragma unroll
    for (int o = 16; o; o >>= 1) {
        s  += __shfl_xor_sync(0xffffffffu, s,  o);
        s2 += __shfl_xor_sync(0xffffffffu, s2, o);
    }
    __shared__ float sh[16];
    int w = threadIdx.x >> 5, lane = threadIdx.x & 31;
    if (lane == 0) { sh[w] = s; sh[8 + w] = s2; }
    __syncthreads();
    s = 0.f; s2 = 0.f;
#pragma unroll
    for (int i = 0; i < 8; i++) { s += sh[i]; s2 += sh[8 + i]; }
    float m   = s * (1.0f / DIM);
    float var = s2 * (1.0f / DIM) - m * m;
    float inv = rsqrtf(var + 1e-5f);
    for (int i = threadIdx.x; i < DIM; i += 256) {
        float v = (xp[i] - m) * inv * g[i] + b[i];
        split_store(oh, ol, (size_t)row * DIM + i, v);
    }
}

// ---------------- depthwise conv(3) + silu -------------------------------------
__global__ void conv_silu_kernel(const float* __restrict__ cw,
                                 const float* __restrict__ cb) {
    int idx = blockIdx.x * blockDim.x + threadIdx.x;
    if (idx >= BLD * DIM) return;
    int d = idx % DIM;
    int l = (idx / DIM) % LSEQ;
    int b = idx / (DIM * LSEQ);
    const float* base = g_xr + (size_t)b * LSEQ * (2 * DIM);
    float xm = (l > 0)        ? base[(size_t)(l - 1) * 2 * DIM + d] : 0.f;
    float x0 =                  base[(size_t)l       * 2 * DIM + d];
    float xp = (l < LSEQ - 1) ? base[(size_t)(l + 1) * 2 * DIM + d] : 0.f;
    float z = xm * cw[d * 3 + 0] + x0 * cw[d * 3 + 1] + xp * cw[d * 3 + 2] + cb[d];
    float v = z * fast_sigmoid(z);
    g_xc[idx] = v;
    split_store(g_ah_xc, g_al_xc, idx, v);
}

// ---------------- selective scan (exp hoisted off the h-chain) -----------------
__global__ void scan_kernel(const float* __restrict__ A_log,
                            const float* __restrict__ Dp) {
    int tid = blockIdx.x * blockDim.x + threadIdx.x;   // 24576
    int s = tid & (NSTATE - 1);
    int d = (tid >> 4) % DIM;
    int b = tid / (DIM * NSTATE);
    float A  = -__expf(A_log[d * NSTATE + s]);
    float Dd = Dp[d];
    const float* dtp  = g_dt + (size_t)b * LSEQ * DIM + d;
    const float* xcp  = g_xc + (size_t)b * LSEQ * DIM + d;
    const float* resp = g_xr + (size_t)b * LSEQ * (2 * DIM) + DIM + d;
    size_t ybase = (size_t)b * LSEQ * DIM + d;
    float h = 0.f;
    float e = __expf(A * dtp[0]);
    for (int l = 0; l < LSEQ; l++) {
        float enext = (l + 1 < LSEQ) ? __expf(A * dtp[(size_t)(l + 1) * DIM]) : 0.f;
        float xv = xcp[(size_t)l * DIM];
        h = h * e + xv;                        // only serial dependence
        e = enext;
        float sum = h;
        sum += __shfl_xor_sync(0xffffffffu, sum, 1);
        sum += __shfl_xor_sync(0xffffffffu, sum, 2);
        sum += __shfl_xor_sync(0xffffffffu, sum, 4);
        sum += __shfl_xor_sync(0xffffffffu, sum, 8);
        if (s == 0) {
            float r = resp[(size_t)l * 2 * DIM];
            float v = sum * Dd * (r * fast_sigmoid(r));
            split_store(g_ah_y, g_al_y, ybase + (size_t)l * DIM, v);
        }
    }
}

// ===== fp16 split mma.sync GEMM, 512 threads, 4-stage cp.async, NT terms ======
// NT=3: acc = AhBh + AhBl + AlBh (layer GEMMs, ~1e-5 accuracy)
// NT=2: acc = AhBh + AlBh       (head GEMM: A exact, B quant only, ~3e-4)
// 128x128 tile, BK=32, 16 warps 4(m)x4(n), warp tile 32x32.

#define NSTG 4

__device__ __forceinline__ void ldsm4(unsigned r[4], unsigned a) {
    asm volatile("ldmatrix.sync.aligned.m8n8.x4.shared.b16 {%0,%1,%2,%3}, [%4];"
                 : "=r"(r[0]), "=r"(r[1]), "=r"(r[2]), "=r"(r[3]) : "r"(a));
}
__device__ __forceinline__ void mma_f16(float c[4], const unsigned a[4],
                                        const unsigned b[2]) {
    asm volatile(
        "mma.sync.aligned.m16n8k16.row.col.f32.f16.f16.f32 "
        "{%0,%1,%2,%3}, {%4,%5,%6,%7}, {%8,%9}, {%0,%1,%2,%3};"
        : "+f"(c[0]), "+f"(c[1]), "+f"(c[2]), "+f"(c[3])
        : "r"(a[0]), "r"(a[1]), "r"(a[2]), "r"(a[3]), "r"(b[0]), "r"(b[1]));
}
__device__ __forceinline__ void cpa16(unsigned dst, const void* src, int sz) {
    asm volatile("cp.async.cg.shared.global [%0], [%1], 16, %2;"
                 :: "r"(dst), "l"(src), "r"(sz));
}

template <int MODE, int NT>
__global__ void __launch_bounds__(512)
gemm_mma(const __half* __restrict__ Ah, const __half* __restrict__ Al,
         const __half* __restrict__ Bh, const __half* __restrict__ Bl,
         const float* __restrict__ bias, float* __restrict__ C,
         int N, int K) {
    constexpr unsigned STAGE_B = (NT == 3) ? 40960u : 30720u;
    extern __shared__ char smc[];
    unsigned sbase = (unsigned)__cvta_generic_to_shared(smc);
    int tid = threadIdx.x, lane = tid & 31, warp = tid >> 5;
    int wm = warp >> 2, wn = warp & 3;            // 4x4 warp grid
    int bm = blockIdx.x * 128, bn = blockIdx.y * 128;

    // ldsm byte offsets within a stage (stride 40 halves = conflict-free)
    unsigned aoff[2][2];
#pragma unroll
    for (int mi = 0; mi < 2; mi++)
#pragma unroll
        for (int ks = 0; ks < 2; ks++) {
            int row = wm * 32 + mi * 16 + (lane & 15);
            int col = ks * 16 + ((lane & 16) ? 8 : 0);
            aoff[mi][ks] = (unsigned)(row * 40 + col) * 2;
        }
    unsigned boff[4];
#pragma unroll
    for (int ni = 0; ni < 4; ni++) {
        int row = wn * 32 + ni * 8 + (lane & 7);
        int col = (lane >> 3) * 8;
        boff[ni] = 20480u + (unsigned)(row * 40 + col) * 2;
    }

    // cp.async mapping: one 16B chunk per matrix per thread
    int r  = tid >> 2;               // 0..127
    int cc = (tid & 3) * 8;          // halfword offset 0,8,16,24

    float acc[2][4][4];
#pragma unroll
    for (int mi = 0; mi < 2; mi++)
#pragma unroll
        for (int ni = 0; ni < 4; ni++)
#pragma unroll
            for (int q = 0; q < 4; q++) acc[mi][ni][q] = 0.f;

    int T = K / 32;
    int brow = bn + r;
    int crow = brow < N ? brow : (N - 1);
    int bsz  = brow < N ? 16 : 0;

#define FETCH(s, kt) do {                                                      \
        int k0 = (kt) * 32;                                                    \
        unsigned dst = sbase + (unsigned)(s) * STAGE_B +                       \
                       (unsigned)(r * 40 + cc) * 2;                            \
        cpa16(dst,           Ah + (size_t)(bm + r) * K + k0 + cc, 16);         \
        cpa16(dst + 10240u,  Al + (size_t)(bm + r) * K + k0 + cc, 16);         \
        cpa16(dst + 20480u,  Bh + (size_t)crow * K + k0 + cc, bsz);            \
        if (NT == 3)                                                           \
            cpa16(dst + 30720u, Bl + (size_t)crow * K + k0 + cc, bsz);         \
    } while (0)

    FETCH(0, 0);
    asm volatile("cp.async.commit_group;" ::: "memory");
    FETCH(1, 1);
    asm volatile("cp.async.commit_group;" ::: "memory");
    FETCH(2, 2);
    asm volatile("cp.async.commit_group;" ::: "memory");

    for (int i = 0; i < T; i++) {
        asm volatile("cp.async.wait_group 2;" ::: "memory");  // stage i ready
        __syncthreads();

        if (i + 3 < T) FETCH((i + 3) & (NSTG - 1), i + 3);
        asm volatile("cp.async.commit_group;" ::: "memory");

        unsigned st = sbase + (unsigned)(i & (NSTG - 1)) * STAGE_B;
        unsigned Bhf[4][4], Blf[4][4];
#pragma unroll
        for (int ni = 0; ni < 4; ni++) {
            ldsm4(Bhf[ni], st + boff[ni]);
            if (NT == 3) ldsm4(Blf[ni], st + boff[ni] + 10240u);
        }
#pragma unroll
        for (int ks = 0; ks < 2; ks++) {
            unsigned Ahf[2][4], Alf[2][4];
#pragma unroll
            for (int mi = 0; mi < 2; mi++) {
                ldsm4(Ahf[mi], st + aoff[mi][ks]);
                ldsm4(Alf[mi], st + aoff[mi][ks] + 10240u);
            }
#pragma unroll
            for (int mi = 0; mi < 2; mi++)
#pragma unroll
                for (int ni = 0; ni < 4; ni++) {
                    mma_f16(acc[mi][ni], Ahf[mi], &Bhf[ni][2 * ks]);
                    mma_f16(acc[mi][ni], Alf[mi], &Bhf[ni][2 * ks]);
                    if (NT == 3)
                        mma_f16(acc[mi][ni], Ahf[mi], &Blf[ni][2 * ks]);
                }
        }
    }
#undef FETCH

    // epilogue
#pragma unroll
    for (int mi = 0; mi < 2; mi++) {
        int rr = bm + wm * 32 + mi * 16 + (lane >> 2);
#pragma unroll
        for (int ni = 0; ni < 4; ni++) {
            int c0 = bn + wn * 32 + ni * 8 + (lane & 3) * 2;
            float* p0 = C + (size_t)rr * N + c0;
            float* p1 = C + (size_t)(rr + 8) * N + c0;
            float v0 = acc[mi][ni][0], v1 = acc[mi][ni][1];
            float v2 = acc[mi][ni][2], v3 = acc[mi][ni][3];
            if (MODE == 1) {
                float b0 = (c0 < N) ? bias[c0] : 0.f;
                float b1 = (c0 + 1 < N) ? bias[c0 + 1] : 0.f;
                v0 = fast_sigmoid(v0 + b0); v1 = fast_sigmoid(v1 + b1);
                v2 = fast_sigmoid(v2 + b0); v3 = fast_sigmoid(v3 + b1);
            }
            if (MODE == 2) {
                if (c0 < N)     { p0[0] += v0; p1[0] += v2; }
                if (c0 + 1 < N) { p0[1] += v1; p1[1] += v3; }
            } else {
                if (c0 < N)     { p0[0] = v0; p1[0] = v2; }
                if (c0 + 1 < N) { p0[1] = v1; p1[1] = v3; }
            }
        }
    }
}

#define SMEM3 (NSTG * 40960)
#define SMEM2 (NSTG * 30720)

// ---------------- driver ---------------------------------------------------------
extern "C" void kernel_launch(void* const* d_in, const int* in_sizes, int n_in,
                              void* d_out, int out_size) {
    const int*   tokens = (const int*)  d_in[0];
    const float* emb    = (const float*)d_in[1];
    const float* ln_g   = (const float*)d_in[2];
    const float* ln_b   = (const float*)d_in[3];
    const float* in_w   = (const float*)d_in[4];
    const float* conv_w = (const float*)d_in[5];
    const float* conv_b = (const float*)d_in[6];
    const float* dt_w   = (const float*)d_in[7];
    const float* dt_b   = (const float*)d_in[8];
    const float* A_log  = (const float*)d_in[9];
    const float* D_par  = (const float*)d_in[10];
    const float* out_w  = (const float*)d_in[11];
    const float* lnf_g  = (const float*)d_in[12];
    const float* lnf_b  = (const float*)d_in[13];
    const float* head_w = (const float*)d_in[14];
    float* out = (float*)d_out;

    float *x, *xr, *xc, *dt;
    cudaGetSymbolAddress((void**)&x,  g_x);
    cudaGetSymbolAddress((void**)&xr, g_xr);
    cudaGetSymbolAddress((void**)&xc, g_xc);
    cudaGetSymbolAddress((void**)&dt, g_dt);
    __half *ah_xn, *al_xn, *ah_xc, *al_xc, *ah_y, *al_y;
    cudaGetSymbolAddress((void**)&ah_xn, g_ah_xn);
    cudaGetSymbolAddress((void**)&al_xn, g_al_xn);
    cudaGetSymbolAddress((void**)&ah_xc, g_ah_xc);
    cudaGetSymbolAddress((void**)&al_xc, g_al_xc);
    cudaGetSymbolAddress((void**)&ah_y,  g_ah_y);
    cudaGetSymbolAddress((void**)&al_y,  g_al_y);
    __half *wh_in, *wl_in, *wh_dt, *wl_dt, *wh_out, *wl_out, *wh_hd;
    cudaGetSymbolAddress((void**)&wh_in,  g_wh_in);
    cudaGetSymbolAddress((void**)&wl_in,  g_wl_in);
    cudaGetSymbolAddress((void**)&wh_dt,  g_wh_dt);
    cudaGetSymbolAddress((void**)&wl_dt,  g_wl_dt);
    cudaGetSymbolAddress((void**)&wh_out, g_wh_out);
    cudaGetSymbolAddress((void**)&wl_out, g_wl_out);
    cudaGetSymbolAddress((void**)&wh_hd,  g_wh_hd);

    cudaFuncSetAttribute(gemm_mma<0,3>, cudaFuncAttributeMaxDynamicSharedMemorySize, SMEM3);
    cudaFuncSetAttribute(gemm_mma<1,3>, cudaFuncAttributeMaxDynamicSharedMemorySize, SMEM3);
    cudaFuncSetAttribute(gemm_mma<2,3>, cudaFuncAttributeMaxDynamicSharedMemorySize, SMEM3);
    cudaFuncSetAttribute(gemm_mma<0,2>, cudaFuncAttributeMaxDynamicSharedMemorySize, SMEM2);

    int n4_in = 4 * 2 * DIM * DIM / 4, n4_dt = 4 * DIM * DIM / 4;
    int n4_hd = NVOC * DIM / 4;

    // launch order keeps a GEMM in the ncu capture window
    wsplit2_kernel<<<(n4_in + 255) / 256, 256>>>((const float4*)in_w,
                                                 (uint2*)wh_in, (uint2*)wl_in, n4_in);
    embed_kernel<<<BLD, 192>>>(tokens, emb);

    for (int l = 0; l < 4; l++) {
        ln_kernel<<<BLD, 256>>>(x, ln_g + l * DIM, ln_b + l * DIM, ah_xn, al_xn);
        gemm_mma<0,3><<<dim3(8, 12), 512, SMEM3>>>(
            ah_xn, al_xn, wh_in + (size_t)l * 2 * DIM * DIM,
            wl_in + (size_t)l * 2 * DIM * DIM, nullptr, xr, 2 * DIM, DIM);
        if (l == 0) {
            wsplit2_kernel<<<(n4_dt + 255) / 256, 256>>>((const float4*)dt_w,
                                                         (uint2*)wh_dt, (uint2*)wl_dt, n4_dt);
        }
        conv_silu_kernel<<<(BLD * DIM + 255) / 256, 256>>>(conv_w + l * DIM * 3,
                                                           conv_b + l * DIM);
        gemm_mma<1,3><<<dim3(8, 6), 512, SMEM3>>>(
            ah_xc, al_xc, wh_dt + (size_t)l * DIM * DIM,
            wl_dt + (size_t)l * DIM * DIM, dt_b + l * DIM, dt, DIM, DIM);
        if (l == 0) {
            wsplit2_kernel<<<(n4_dt + 255) / 256, 256>>>((const float4*)out_w,
                                                         (uint2*)wh_out, (uint2*)wl_out, n4_dt);
        }
        scan_kernel<<<192, 128>>>(A_log + l * DIM * NSTATE, D_par + l * DIM);
        gemm_mma<2,3><<<dim3(8, 6), 512, SMEM3>>>(
            ah_y, al_y, wh_out + (size_t)l * DIM * DIM,
            wl_out + (size_t)l * DIM * DIM, nullptr, x, DIM, DIM);
        if (l == 0) {
            wsplit1_kernel<<<(n4_hd + 255) / 256, 256>>>((const float4*)head_w,
                                                         (uint2*)wh_hd, n4_hd);
        }
    }

    ln_kernel<<<BLD, 256>>>(x, lnf_g, lnf_b, ah_xn, al_xn);
    // head: 2-term split-A (A exact; only head_w quantization error)
    gemm_mma<0,2><<<dim3(8, (NVOC + 127) / 128), 512, SMEM2>>>(
        ah_xn, al_xn, wh_hd, nullptr, nullptr, out, NVOC, DIM);
    (void)in_sizes; (void)n_in; (void)out_size;
}

// round 10
// speedup vs baseline: 1.1493x; 1.0581x over previous
#include <cuda_runtime.h>
#include <cuda_fp16.h>
#include <cstdint>

#define BLD   1024
#define DIM   768
#define LSEQ  512
#define NSTATE 16
#define NVOC  50257

// ---------------- fp32 scratch ----------------------------------------------
__device__ float g_x [BLD*DIM];
__device__ float g_xr[BLD*2*DIM];
__device__ float g_xc[BLD*DIM];
__device__ float g_dt[BLD*DIM];
// ---------------- split-fp16 activations -------------------------------------
__device__ __half g_ah_xn[BLD*DIM], g_al_xn[BLD*DIM];
__device__ __half g_ah_xc[BLD*DIM], g_al_xc[BLD*DIM];
__device__ __half g_ah_y [BLD*DIM], g_al_y [BLD*DIM];
// ---------------- fp16 weights (prepass output) ------------------------------
__device__ __half g_wh_in [4*2*DIM*DIM], g_wl_in [4*2*DIM*DIM];
__device__ __half g_wh_dt [4*DIM*DIM],   g_wl_dt [4*DIM*DIM];
__device__ __half g_wh_out[4*DIM*DIM],   g_wl_out[4*DIM*DIM];
__device__ __half g_wh_hd [NVOC*DIM];    // head: hi only (2-term split-A)

__device__ __forceinline__ float fast_sigmoid(float z) {
    return 1.0f / (1.0f + __expf(-z));
}
__device__ __forceinline__ void split_store(__half* ph, __half* pl, size_t i, float v) {
    __half h = __float2half_rn(v);
    ph[i] = h;
    pl[i] = __float2half_rn(v - __half2float(h));
}

// ---------------- weight prepasses --------------------------------------------
__global__ void wsplit2_kernel(const float4* __restrict__ src,
                               uint2* __restrict__ dh, uint2* __restrict__ dl,
                               int n4) {
    int i = blockIdx.x * blockDim.x + threadIdx.x;
    if (i >= n4) return;
    float4 v = src[i];
    __half2 h01 = __floats2half2_rn(v.x, v.y);
    __half2 h23 = __floats2half2_rn(v.z, v.w);
    float2 f01 = __half22float2(h01), f23 = __half22float2(h23);
    __half2 l01 = __floats2half2_rn(v.x - f01.x, v.y - f01.y);
    __half2 l23 = __floats2half2_rn(v.z - f23.x, v.w - f23.y);
    dh[i] = make_uint2(*(unsigned*)&h01, *(unsigned*)&h23);
    dl[i] = make_uint2(*(unsigned*)&l01, *(unsigned*)&l23);
}
__global__ void wsplit1_kernel(const float4* __restrict__ src,
                               uint2* __restrict__ dh, int n4) {
    int i = blockIdx.x * blockDim.x + threadIdx.x;
    if (i >= n4) return;
    float4 v = src[i];
    __half2 h01 = __floats2half2_rn(v.x, v.y);
    __half2 h23 = __floats2half2_rn(v.z, v.w);
    dh[i] = make_uint2(*(unsigned*)&h01, *(unsigned*)&h23);
}

// ---------------- embedding gather --------------------------------------------
__global__ void embed_kernel(const int* __restrict__ tokens,
                             const float* __restrict__ emb) {
    int row = blockIdx.x;
    int tok = tokens[row];
    const float4* src = (const float4*)(emb + (size_t)tok * DIM);
    float4* dst = (float4*)(g_x + (size_t)row * DIM);
    dst[threadIdx.x] = src[threadIdx.x];
}

// ---------------- layernorm -> split fp16 --------------------------------------
__global__ void ln_kernel(const float* __restrict__ x,
                          const float* __restrict__ g,
                          const float* __restrict__ b,
                          __half* __restrict__ oh, __half* __restrict__ ol) {
    int row = blockIdx.x;
    const float* xp = x + (size_t)row * DIM;
    float s = 0.f, s2 = 0.f;
    for (int i = threadIdx.x; i < DIM; i += 256) {
        float v = xp[i];
        s += v; s2 += v * v;
    }
#pragma unroll
    for (int o = 16; o; o >>= 1) {
        s  += __shfl_xor_sync(0xffffffffu, s,  o);
        s2 += __shfl_xor_sync(0xffffffffu, s2, o);
    }
    __shared__ float sh[16];
    int w = threadIdx.x >> 5, lane = threadIdx.x & 31;
    if (lane == 0) { sh[w] = s; sh[8 + w] = s2; }
    __syncthreads();
    s = 0.f; s2 = 0.f;
#pragma unroll
    for (int i = 0; i < 8; i++) { s += sh[i]; s2 += sh[8 + i]; }
    float m   = s * (1.0f / DIM);
    float var = s2 * (1.0f / DIM) - m * m;
    float inv = rsqrtf(var + 1e-5f);
    for (int i = threadIdx.x; i < DIM; i += 256) {
        float v = (xp[i] - m) * inv * g[i] + b[i];
        split_store(oh, ol, (size_t)row * DIM + i, v);
    }
}

// ---------------- depthwise conv(3) + silu -------------------------------------
__global__ void conv_silu_kernel(const float* __restrict__ cw,
                                 const float* __restrict__ cb) {
    int idx = blockIdx.x * blockDim.x + threadIdx.x;
    if (idx >= BLD * DIM) return;
    int d = idx % DIM;
    int l = (idx / DIM) % LSEQ;
    int b = idx / (DIM * LSEQ);
    const float* base = g_xr + (size_t)b * LSEQ * (2 * DIM);
    float xm = (l > 0)        ? base[(size_t)(l - 1) * 2 * DIM + d] : 0.f;
    float x0 =                  base[(size_t)l       * 2 * DIM + d];
    float xp = (l < LSEQ - 1) ? base[(size_t)(l + 1) * 2 * DIM + d] : 0.f;
    float z = xm * cw[d * 3 + 0] + x0 * cw[d * 3 + 1] + xp * cw[d * 3 + 2] + cb[d];
    float v = z * fast_sigmoid(z);
    g_xc[idx] = v;
    split_store(g_ah_xc, g_al_xc, idx, v);
}

// ---------------- selective scan (exp hoisted off the h-chain) -----------------
__global__ void scan_kernel(const float* __restrict__ A_log,
                            const float* __restrict__ Dp) {
    int tid = blockIdx.x * blockDim.x + threadIdx.x;   // 24576
    int s = tid & (NSTATE - 1);
    int d = (tid >> 4) % DIM;
    int b = tid / (DIM * NSTATE);
    float A  = -__expf(A_log[d * NSTATE + s]);
    float Dd = Dp[d];
    const float* dtp  = g_dt + (size_t)b * LSEQ * DIM + d;
    const float* xcp  = g_xc + (size_t)b * LSEQ * DIM + d;
    const float* resp = g_xr + (size_t)b * LSEQ * (2 * DIM) + DIM + d;
    size_t ybase = (size_t)b * LSEQ * DIM + d;
    float h = 0.f;
    float e = __expf(A * dtp[0]);
#pragma unroll 2
    for (int l = 0; l < LSEQ; l++) {
        float enext = (l + 1 < LSEQ) ? __expf(A * dtp[(size_t)(l + 1) * DIM]) : 0.f;
        float xv = xcp[(size_t)l * DIM];
        h = h * e + xv;                        // only serial dependence
        e = enext;
        float sum = h;
        sum += __shfl_xor_sync(0xffffffffu, sum, 1);
        sum += __shfl_xor_sync(0xffffffffu, sum, 2);
        sum += __shfl_xor_sync(0xffffffffu, sum, 4);
        sum += __shfl_xor_sync(0xffffffffu, sum, 8);
        if (s == 0) {
            float r = resp[(size_t)l * 2 * DIM];
            float v = sum * Dd * (r * fast_sigmoid(r));
            split_store(g_ah_y, g_al_y, ybase + (size_t)l * DIM, v);
        }
    }
}

// ---------------- shared MMA primitives -----------------------------------------
__device__ __forceinline__ void ldsm4(unsigned r[4], unsigned a) {
    asm volatile("ldmatrix.sync.aligned.m8n8.x4.shared.b16 {%0,%1,%2,%3}, [%4];"
                 : "=r"(r[0]), "=r"(r[1]), "=r"(r[2]), "=r"(r[3]) : "r"(a));
}
__device__ __forceinline__ void mma_f16(float c[4], const unsigned a[4],
                                        const unsigned b[2]) {
    asm volatile(
        "mma.sync.aligned.m16n8k16.row.col.f32.f16.f16.f32 "
        "{%0,%1,%2,%3}, {%4,%5,%6,%7}, {%8,%9}, {%0,%1,%2,%3};"
        : "+f"(c[0]), "+f"(c[1]), "+f"(c[2]), "+f"(c[3])
        : "r"(a[0]), "r"(a[1]), "r"(a[2]), "r"(a[3]), "r"(b[0]), "r"(b[1]));
}
__device__ __forceinline__ void cpa16(unsigned dst, const void* src, int sz) {
    asm volatile("cp.async.cg.shared.global [%0], [%1], 16, %2;"
                 :: "r"(dst), "l"(src), "r"(sz));
}

#define NSTG 4

// ===== 128x128-tile head GEMM: 512 thr, NT terms (head uses NT=2) ==============
template <int MODE, int NT>
__global__ void __launch_bounds__(512)
gemm_mma(const __half* __restrict__ Ah, const __half* __restrict__ Al,
         const __half* __restrict__ Bh, const __half* __restrict__ Bl,
         const float* __restrict__ bias, float* __restrict__ C,
         int N, int K) {
    constexpr unsigned STAGE_B = (NT == 3) ? 40960u : 30720u;
    extern __shared__ char smc[];
    unsigned sbase = (unsigned)__cvta_generic_to_shared(smc);
    int tid = threadIdx.x, lane = tid & 31, warp = tid >> 5;
    int wm = warp >> 2, wn = warp & 3;            // 4x4 warp grid
    int bm = blockIdx.x * 128, bn = blockIdx.y * 128;

    unsigned aoff[2][2];
#pragma unroll
    for (int mi = 0; mi < 2; mi++)
#pragma unroll
        for (int ks = 0; ks < 2; ks++) {
            int row = wm * 32 + mi * 16 + (lane & 15);
            int col = ks * 16 + ((lane & 16) ? 8 : 0);
            aoff[mi][ks] = (unsigned)(row * 40 + col) * 2;
        }
    unsigned boff[4];
#pragma unroll
    for (int ni = 0; ni < 4; ni++) {
        int row = wn * 32 + ni * 8 + (lane & 7);
        int col = (lane >> 3) * 8;
        boff[ni] = 20480u + (unsigned)(row * 40 + col) * 2;
    }

    int r  = tid >> 2;
    int cc = (tid & 3) * 8;

    float acc[2][4][4];
#pragma unroll
    for (int mi = 0; mi < 2; mi++)
#pragma unroll
        for (int ni = 0; ni < 4; ni++)
#pragma unroll
            for (int q = 0; q < 4; q++) acc[mi][ni][q] = 0.f;

    int T = K / 32;
    int brow = bn + r;
    int crow = brow < N ? brow : (N - 1);
    int bsz  = brow < N ? 16 : 0;

#define FETCH(s, kt) do {                                                      \
        int k0 = (kt) * 32;                                                    \
        unsigned dst = sbase + (unsigned)(s) * STAGE_B +                       \
                       (unsigned)(r * 40 + cc) * 2;                            \
        cpa16(dst,           Ah + (size_t)(bm + r) * K + k0 + cc, 16);         \
        cpa16(dst + 10240u,  Al + (size_t)(bm + r) * K + k0 + cc, 16);         \
        cpa16(dst + 20480u,  Bh + (size_t)crow * K + k0 + cc, bsz);            \
        if (NT == 3)                                                           \
            cpa16(dst + 30720u, Bl + (size_t)crow * K + k0 + cc, bsz);         \
    } while (0)

    FETCH(0, 0);
    asm volatile("cp.async.commit_group;" ::: "memory");
    FETCH(1, 1);
    asm volatile("cp.async.commit_group;" ::: "memory");
    FETCH(2, 2);
    asm volatile("cp.async.commit_group;" ::: "memory");

    for (int i = 0; i < T; i++) {
        asm volatile("cp.async.wait_group 2;" ::: "memory");
        __syncthreads();

        if (i + 3 < T) FETCH((i + 3) & (NSTG - 1), i + 3);
        asm volatile("cp.async.commit_group;" ::: "memory");

        unsigned st = sbase + (unsigned)(i & (NSTG - 1)) * STAGE_B;
        unsigned Bhf[4][4], Blf[4][4];
#pragma unroll
        for (int ni = 0; ni < 4; ni++) {
            ldsm4(Bhf[ni], st + boff[ni]);
            if (NT == 3) ldsm4(Blf[ni], st + boff[ni] + 10240u);
        }
#pragma unroll
        for (int ks = 0; ks < 2; ks++) {
            unsigned Ahf[2][4], Alf[2][4];
#pragma unroll
            for (int mi = 0; mi < 2; mi++) {
                ldsm4(Ahf[mi], st + aoff[mi][ks]);
                ldsm4(Alf[mi], st + aoff[mi][ks] + 10240u);
            }
#pragma unroll
            for (int mi = 0; mi < 2; mi++)
#pragma unroll
                for (int ni = 0; ni < 4; ni++) {
                    mma_f16(acc[mi][ni], Ahf[mi], &Bhf[ni][2 * ks]);
                    mma_f16(acc[mi][ni], Alf[mi], &Bhf[ni][2 * ks]);
                    if (NT == 3)
                        mma_f16(acc[mi][ni], Ahf[mi], &Blf[ni][2 * ks]);
                }
        }
    }
#undef FETCH

#pragma unroll
    for (int mi = 0; mi < 2; mi++) {
        int rr = bm + wm * 32 + mi * 16 + (lane >> 2);
#pragma unroll
        for (int ni = 0; ni < 4; ni++) {
            int c0 = bn + wn * 32 + ni * 8 + (lane & 3) * 2;
            float* p0 = C + (size_t)rr * N + c0;
            float* p1 = C + (size_t)(rr + 8) * N + c0;
            float v0 = acc[mi][ni][0], v1 = acc[mi][ni][1];
            float v2 = acc[mi][ni][2], v3 = acc[mi][ni][3];
            if (MODE == 1) {
                float b0 = (c0 < N) ? bias[c0] : 0.f;
                float b1 = (c0 + 1 < N) ? bias[c0 + 1] : 0.f;
                v0 = fast_sigmoid(v0 + b0); v1 = fast_sigmoid(v1 + b1);
                v2 = fast_sigmoid(v2 + b0); v3 = fast_sigmoid(v3 + b1);
            }
            if (MODE == 2) {
                if (c0 < N)     { p0[0] += v0; p1[0] += v2; }
                if (c0 + 1 < N) { p0[1] += v1; p1[1] += v3; }
            } else {
                if (c0 < N)     { p0[0] = v0; p1[0] = v2; }
                if (c0 + 1 < N) { p0[1] = v1; p1[1] = v3; }
            }
        }
    }
}

// ===== 64x64-tile layer GEMM: 256 thr, 8 warps 2(m)x4(n), warp 32x16, NT=3 =====
// Small tiles fill the chip (layer GEMMs were latency-bound at 128x128).
#define STAGE64 20480u           // Ah(5120) Al(5120) Bh(5120) Bl(5120)
#define SMEM64  (NSTG * 20480)

template <int MODE>
__global__ void __launch_bounds__(256)
gemm64(const __half* __restrict__ Ah, const __half* __restrict__ Al,
       const __half* __restrict__ Bh, const __half* __restrict__ Bl,
       const float* __restrict__ bias, float* __restrict__ C,
       int N, int K) {
    extern __shared__ char smc[];
    unsigned sbase = (unsigned)__cvta_generic_to_shared(smc);
    int tid = threadIdx.x, lane = tid & 31, warp = tid >> 5;
    int wm = warp >> 2, wn = warp & 3;            // 2x4 warp grid
    int bm = blockIdx.x * 64, bn = blockIdx.y * 64;

    unsigned aoff[2][2];
#pragma unroll
    for (int mi = 0; mi < 2; mi++)
#pragma unroll
        for (int ks = 0; ks < 2; ks++) {
            int row = wm * 32 + mi * 16 + (lane & 15);
            int col = ks * 16 + ((lane & 16) ? 8 : 0);
            aoff[mi][ks] = (unsigned)(row * 40 + col) * 2;
        }
    unsigned boff[2];
#pragma unroll
    for (int ni = 0; ni < 2; ni++) {
        int row = wn * 16 + ni * 8 + (lane & 7);
        int col = (lane >> 3) * 8;
        boff[ni] = 10240u + (unsigned)(row * 40 + col) * 2;
    }

    int r  = tid >> 2;               // 0..63
    int cc = (tid & 3) * 8;

    float acc[2][2][4];
#pragma unroll
    for (int mi = 0; mi < 2; mi++)
#pragma unroll
        for (int ni = 0; ni < 2; ni++)
#pragma unroll
            for (int q = 0; q < 4; q++) acc[mi][ni][q] = 0.f;

    int T = K / 32;

#define FETCH64(s, kt) do {                                                    \
        int k0 = (kt) * 32;                                                    \
        unsigned dst = sbase + (unsigned)(s) * STAGE64 +                       \
                       (unsigned)(r * 40 + cc) * 2;                            \
        cpa16(dst,           Ah + (size_t)(bm + r) * K + k0 + cc, 16);         \
        cpa16(dst + 5120u,   Al + (size_t)(bm + r) * K + k0 + cc, 16);         \
        cpa16(dst + 10240u,  Bh + (size_t)(bn + r) * K + k0 + cc, 16);         \
        cpa16(dst + 15360u,  Bl + (size_t)(bn + r) * K + k0 + cc, 16);         \
    } while (0)

    FETCH64(0, 0);
    asm volatile("cp.async.commit_group;" ::: "memory");
    FETCH64(1, 1);
    asm volatile("cp.async.commit_group;" ::: "memory");
    FETCH64(2, 2);
    asm volatile("cp.async.commit_group;" ::: "memory");

    for (int i = 0; i < T; i++) {
        asm volatile("cp.async.wait_group 2;" ::: "memory");
        __syncthreads();

        if (i + 3 < T) FETCH64((i + 3) & (NSTG - 1), i + 3);
        asm volatile("cp.async.commit_group;" ::: "memory");

        unsigned st = sbase + (unsigned)(i & (NSTG - 1)) * STAGE64;
        unsigned Bhf[2][4], Blf[2][4];
#pragma unroll
        for (int ni = 0; ni < 2; ni++) {
            ldsm4(Bhf[ni], st + boff[ni]);
            ldsm4(Blf[ni], st + boff[ni] + 5120u);
        }
#pragma unroll
        for (int ks = 0; ks < 2; ks++) {
            unsigned Ahf[2][4], Alf[2][4];
#pragma unroll
            for (int mi = 0; mi < 2; mi++) {
                ldsm4(Ahf[mi], st + aoff[mi][ks]);
                ldsm4(Alf[mi], st + aoff[mi][ks] + 5120u);
            }
#pragma unroll
            for (int mi = 0; mi < 2; mi++)
#pragma unroll
                for (int ni = 0; ni < 2; ni++) {
                    mma_f16(acc[mi][ni], Ahf[mi], &Bhf[ni][2 * ks]);
                    mma_f16(acc[mi][ni], Alf[mi], &Bhf[ni][2 * ks]);
                    mma_f16(acc[mi][ni], Ahf[mi], &Blf[ni][2 * ks]);
                }
        }
    }
#undef FETCH64

#pragma unroll
    for (int mi = 0; mi < 2; mi++) {
        int rr = bm + wm * 32 + mi * 16 + (lane >> 2);
#pragma unroll
        for (int ni = 0; ni < 2; ni++) {
            int c0 = bn + wn * 16 + ni * 8 + (lane & 3) * 2;
            float* p0 = C + (size_t)rr * N + c0;
            float* p1 = C + (size_t)(rr + 8) * N + c0;
            float v0 = acc[mi][ni][0], v1 = acc[mi][ni][1];
            float v2 = acc[mi][ni][2], v3 = acc[mi][ni][3];
            if (MODE == 1) {
                float b0 = bias[c0], b1 = bias[c0 + 1];
                v0 = fast_sigmoid(v0 + b0); v1 = fast_sigmoid(v1 + b1);
                v2 = fast_sigmoid(v2 + b0); v3 = fast_sigmoid(v3 + b1);
            }
            if (MODE == 2) {
                p0[0] += v0; p0[1] += v1; p1[0] += v2; p1[1] += v3;
            } else {
                p0[0] = v0; p0[1] = v1; p1[0] = v2; p1[1] = v3;
            }
        }
    }
}

#define SMEM2 (NSTG * 30720)

// ---------------- driver ---------------------------------------------------------
extern "C" void kernel_launch(void* const* d_in, const int* in_sizes, int n_in,
                              void* d_out, int out_size) {
    const int*   tokens = (const int*)  d_in[0];
    const float* emb    = (const float*)d_in[1];
    const float* ln_g   = (const float*)d_in[2];
    const float* ln_b   = (const float*)d_in[3];
    const float* in_w   = (const float*)d_in[4];
    const float* conv_w = (const float*)d_in[5];
    const float* conv_b = (const float*)d_in[6];
    const float* dt_w   = (const float*)d_in[7];
    const float* dt_b   = (const float*)d_in[8];
    const float* A_log  = (const float*)d_in[9];
    const float* D_par  = (const float*)d_in[10];
    const float* out_w  = (const float*)d_in[11];
    const float* lnf_g  = (const float*)d_in[12];
    const float* lnf_b  = (const float*)d_in[13];
    const float* head_w = (const float*)d_in[14];
    float* out = (float*)d_out;

    float *x, *xr, *xc, *dt;
    cudaGetSymbolAddress((void**)&x,  g_x);
    cudaGetSymbolAddress((void**)&xr, g_xr);
    cudaGetSymbolAddress((void**)&xc, g_xc);
    cudaGetSymbolAddress((void**)&dt, g_dt);
    __half *ah_xn, *al_xn, *ah_xc, *al_xc, *ah_y, *al_y;
    cudaGetSymbolAddress((void**)&ah_xn, g_ah_xn);
    cudaGetSymbolAddress((void**)&al_xn, g_al_xn);
    cudaGetSymbolAddress((void**)&ah_xc, g_ah_xc);
    cudaGetSymbolAddress((void**)&al_xc, g_al_xc);
    cudaGetSymbolAddress((void**)&ah_y,  g_ah_y);
    cudaGetSymbolAddress((void**)&al_y,  g_al_y);
    __half *wh_in, *wl_in, *wh_dt, *wl_dt, *wh_out, *wl_out, *wh_hd;
    cudaGetSymbolAddress((void**)&wh_in,  g_wh_in);
    cudaGetSymbolAddress((void**)&wl_in,  g_wl_in);
    cudaGetSymbolAddress((void**)&wh_dt,  g_wh_dt);
    cudaGetSymbolAddress((void**)&wl_dt,  g_wl_dt);
    cudaGetSymbolAddress((void**)&wh_out, g_wh_out);
    cudaGetSymbolAddress((void**)&wl_out, g_wl_out);
    cudaGetSymbolAddress((void**)&wh_hd,  g_wh_hd);

    cudaFuncSetAttribute(gemm64<0>, cudaFuncAttributeMaxDynamicSharedMemorySize, SMEM64);
    cudaFuncSetAttribute(gemm64<1>, cudaFuncAttributeMaxDynamicSharedMemorySize, SMEM64);
    cudaFuncSetAttribute(gemm64<2>, cudaFuncAttributeMaxDynamicSharedMemorySize, SMEM64);
    cudaFuncSetAttribute(gemm_mma<0,2>, cudaFuncAttributeMaxDynamicSharedMemorySize, SMEM2);

    int n4_in = 4 * 2 * DIM * DIM / 4, n4_dt = 4 * DIM * DIM / 4;
    int n4_hd = NVOC * DIM / 4;

    // launch order keeps a GEMM in the ncu capture window
    wsplit2_kernel<<<(n4_in + 255) / 256, 256>>>((const float4*)in_w,
                                                 (uint2*)wh_in, (uint2*)wl_in, n4_in);
    embed_kernel<<<BLD, 192>>>(tokens, emb);

    for (int l = 0; l < 4; l++) {
        ln_kernel<<<BLD, 256>>>(x, ln_g + l * DIM, ln_b + l * DIM, ah_xn, al_xn);
        gemm64<0><<<dim3(16, 24), 256, SMEM64>>>(
            ah_xn, al_xn, wh_in + (size_t)l * 2 * DIM * DIM,
            wl_in + (size_t)l * 2 * DIM * DIM, nullptr, xr, 2 * DIM, DIM);
        if (l == 0) {
            wsplit2_kernel<<<(n4_dt + 255) / 256, 256>>>((const float4*)dt_w,
                                                         (uint2*)wh_dt, (uint2*)wl_dt, n4_dt);
        }
        conv_silu_kernel<<<(BLD * DIM + 255) / 256, 256>>>(conv_w + l * DIM * 3,
                                                           conv_b + l * DIM);
        gemm64<1><<<dim3(16, 12), 256, SMEM64>>>(
            ah_xc, al_xc, wh_dt + (size_t)l * DIM * DIM,
            wl_dt + (size_t)l * DIM * DIM, dt_b + l * DIM, dt, DIM, DIM);
        if (l == 0) {
            wsplit2_kernel<<<(n4_dt + 255) / 256, 256>>>((const float4*)out_w,
                                                         (uint2*)wh_out, (uint2*)wl_out, n4_dt);
        }
        scan_kernel<<<192, 128>>>(A_log + l * DIM * NSTATE, D_par + l * DIM);
        gemm64<2><<<dim3(16, 12), 256, SMEM64>>>(
            ah_y, al_y, wh_out + (size_t)l * DIM * DIM,
            wl_out + (size_t)l * DIM * DIM, nullptr, x, DIM, DIM);
        if (l == 0) {
            wsplit1_kernel<<<(n4_hd + 255) / 256, 256>>>((const float4*)head_w,
                                                         (uint2*)wh_hd, n4_hd);
        }
    }

    ln_kernel<<<BLD, 256>>>(x, lnf_g, lnf_b, ah_xn, al_xn);
    // head: 2-term split-A (A exact; only head_w quantization error)
    gemm_mma<0,2><<<dim3(8, (NVOC + 127) / 128), 512, SMEM2>>>(
        ah_xn, al_xn, wh_hd, nullptr, nullptr, out, NVOC, DIM);
    (void)in_sizes; (void)n_in; (void)out_size;
}

// round 11
// speedup vs baseline: 1.2519x; 1.0892x over previous
#include <cuda_runtime.h>
#include <cuda_fp16.h>
#include <cstdint>

#define BLD   1024
#define DIM   768
#define LSEQ  512
#define NSTATE 16
#define NVOC  50257

// ---------------- fp32 scratch ----------------------------------------------
__device__ float g_x [BLD*DIM];
__device__ float g_xr[BLD*2*DIM];
__device__ float g_xc[BLD*DIM];
__device__ float g_dt[BLD*DIM];
// ---------------- split-fp16 activations -------------------------------------
__device__ __half g_ah_xn[BLD*DIM], g_al_xn[BLD*DIM];
__device__ __half g_ah_xc[BLD*DIM], g_al_xc[BLD*DIM];
__device__ __half g_ah_y [BLD*DIM], g_al_y [BLD*DIM];
// ---------------- fp16 weights (prepass output) ------------------------------
__device__ __half g_wh_in [4*2*DIM*DIM], g_wl_in [4*2*DIM*DIM];
__device__ __half g_wh_dt [4*DIM*DIM],   g_wl_dt [4*DIM*DIM];
__device__ __half g_wh_out[4*DIM*DIM],   g_wl_out[4*DIM*DIM];
__device__ __half g_wh_hd [NVOC*DIM];    // head: hi only (1-term)

__device__ __forceinline__ float fast_sigmoid(float z) {
    return 1.0f / (1.0f + __expf(-z));
}
__device__ __forceinline__ void split_store(__half* ph, __half* pl, size_t i, float v) {
    __half h = __float2half_rn(v);
    ph[i] = h;
    pl[i] = __float2half_rn(v - __half2float(h));
}

// ---------------- weight prepasses --------------------------------------------
__global__ void wsplit2_kernel(const float4* __restrict__ src,
                               uint2* __restrict__ dh, uint2* __restrict__ dl,
                               int n4) {
    int i = blockIdx.x * blockDim.x + threadIdx.x;
    if (i >= n4) return;
    float4 v = src[i];
    __half2 h01 = __floats2half2_rn(v.x, v.y);
    __half2 h23 = __floats2half2_rn(v.z, v.w);
    float2 f01 = __half22float2(h01), f23 = __half22float2(h23);
    __half2 l01 = __floats2half2_rn(v.x - f01.x, v.y - f01.y);
    __half2 l23 = __floats2half2_rn(v.z - f23.x, v.w - f23.y);
    dh[i] = make_uint2(*(unsigned*)&h01, *(unsigned*)&h23);
    dl[i] = make_uint2(*(unsigned*)&l01, *(unsigned*)&l23);
}
__global__ void wsplit1_kernel(const float4* __restrict__ src,
                               uint2* __restrict__ dh, int n4) {
    int i = blockIdx.x * blockDim.x + threadIdx.x;
    if (i >= n4) return;
    float4 v = src[i];
    __half2 h01 = __floats2half2_rn(v.x, v.y);
    __half2 h23 = __floats2half2_rn(v.z, v.w);
    dh[i] = make_uint2(*(unsigned*)&h01, *(unsigned*)&h23);
}

// ---------------- embedding gather --------------------------------------------
__global__ void embed_kernel(const int* __restrict__ tokens,
                             const float* __restrict__ emb) {
    int row = blockIdx.x;
    int tok = tokens[row];
    const float4* src = (const float4*)(emb + (size_t)tok * DIM);
    float4* dst = (float4*)(g_x + (size_t)row * DIM);
    dst[threadIdx.x] = src[threadIdx.x];
}

// ---------------- layernorm -> split fp16 --------------------------------------
__global__ void ln_kernel(const float* __restrict__ x,
                          const float* __restrict__ g,
                          const float* __restrict__ b,
                          __half* __restrict__ oh, __half* __restrict__ ol) {
    int row = blockIdx.x;
    const float* xp = x + (size_t)row * DIM;
    float s = 0.f, s2 = 0.f;
    for (int i = threadIdx.x; i < DIM; i += 256) {
        float v = xp[i];
        s += v; s2 += v * v;
    }
#pragma unroll
    for (int o = 16; o; o >>= 1) {
        s  += __shfl_xor_sync(0xffffffffu, s,  o);
        s2 += __shfl_xor_sync(0xffffffffu, s2, o);
    }
    __shared__ float sh[16];
    int w = threadIdx.x >> 5, lane = threadIdx.x & 31;
    if (lane == 0) { sh[w] = s; sh[8 + w] = s2; }
    __syncthreads();
    s = 0.f; s2 = 0.f;
#pragma unroll
    for (int i = 0; i < 8; i++) { s += sh[i]; s2 += sh[8 + i]; }
    float m   = s * (1.0f / DIM);
    float var = s2 * (1.0f / DIM) - m * m;
    float inv = rsqrtf(var + 1e-5f);
    for (int i = threadIdx.x; i < DIM; i += 256) {
        float v = (xp[i] - m) * inv * g[i] + b[i];
        split_store(oh, ol, (size_t)row * DIM + i, v);
    }
}

// ---------------- depthwise conv(3) + silu -------------------------------------
__global__ void conv_silu_kernel(const float* __restrict__ cw,
                                 const float* __restrict__ cb) {
    int idx = blockIdx.x * blockDim.x + threadIdx.x;
    if (idx >= BLD * DIM) return;
    int d = idx % DIM;
    int l = (idx / DIM) % LSEQ;
    int b = idx / (DIM * LSEQ);
    const float* base = g_xr + (size_t)b * LSEQ * (2 * DIM);
    float xm = (l > 0)        ? base[(size_t)(l - 1) * 2 * DIM + d] : 0.f;
    float x0 =                  base[(size_t)l       * 2 * DIM + d];
    float xp = (l < LSEQ - 1) ? base[(size_t)(l + 1) * 2 * DIM + d] : 0.f;
    float z = xm * cw[d * 3 + 0] + x0 * cw[d * 3 + 1] + xp * cw[d * 3 + 2] + cb[d];
    float v = z * fast_sigmoid(z);
    g_xc[idx] = v;
    split_store(g_ah_xc, g_al_xc, idx, v);
}

// ---------------- selective scan (exp hoisted off the h-chain) -----------------
__global__ void scan_kernel(const float* __restrict__ A_log,
                            const float* __restrict__ Dp) {
    int tid = blockIdx.x * blockDim.x + threadIdx.x;   // 24576
    int s = tid & (NSTATE - 1);
    int d = (tid >> 4) % DIM;
    int b = tid / (DIM * NSTATE);
    float A  = -__expf(A_log[d * NSTATE + s]);
    float Dd = Dp[d];
    const float* dtp  = g_dt + (size_t)b * LSEQ * DIM + d;
    const float* xcp  = g_xc + (size_t)b * LSEQ * DIM + d;
    const float* resp = g_xr + (size_t)b * LSEQ * (2 * DIM) + DIM + d;
    size_t ybase = (size_t)b * LSEQ * DIM + d;
    float h = 0.f;
    float e = __expf(A * dtp[0]);
#pragma unroll 2
    for (int l = 0; l < LSEQ; l++) {
        float enext = (l + 1 < LSEQ) ? __expf(A * dtp[(size_t)(l + 1) * DIM]) : 0.f;
        float xv = xcp[(size_t)l * DIM];
        h = h * e + xv;                        // only serial dependence
        e = enext;
        float sum = h;
        sum += __shfl_xor_sync(0xffffffffu, sum, 1);
        sum += __shfl_xor_sync(0xffffffffu, sum, 2);
        sum += __shfl_xor_sync(0xffffffffu, sum, 4);
        sum += __shfl_xor_sync(0xffffffffu, sum, 8);
        if (s == 0) {
            float r = resp[(size_t)l * 2 * DIM];
            float v = sum * Dd * (r * fast_sigmoid(r));
            split_store(g_ah_y, g_al_y, ybase + (size_t)l * DIM, v);
        }
    }
}

// ---------------- shared MMA primitives -----------------------------------------
__device__ __forceinline__ void ldsm4(unsigned r[4], unsigned a) {
    asm volatile("ldmatrix.sync.aligned.m8n8.x4.shared.b16 {%0,%1,%2,%3}, [%4];"
                 : "=r"(r[0]), "=r"(r[1]), "=r"(r[2]), "=r"(r[3]) : "r"(a));
}
__device__ __forceinline__ void mma_f16(float c[4], const unsigned a[4],
                                        const unsigned b[2]) {
    asm volatile(
        "mma.sync.aligned.m16n8k16.row.col.f32.f16.f16.f32 "
        "{%0,%1,%2,%3}, {%4,%5,%6,%7}, {%8,%9}, {%0,%1,%2,%3};"
        : "+f"(c[0]), "+f"(c[1]), "+f"(c[2]), "+f"(c[3])
        : "r"(a[0]), "r"(a[1]), "r"(a[2]), "r"(a[3]), "r"(b[0]), "r"(b[1]));
}
__device__ __forceinline__ void cpa16(unsigned dst, const void* src, int sz) {
    asm volatile("cp.async.cg.shared.global [%0], [%1], 16, %2;"
                 :: "r"(dst), "l"(src), "r"(sz));
}

#define NSTG 4

// ===== 128x128-tile GEMM: 512 thr, NT terms (head uses NT=1) ===================
// NT=1: acc = AhBh              (head: both sides fp16-quantized)
// NT=2: acc = AhBh + AlBh       (A exact)
// NT=3: acc = AhBh + AhBl + AlBh
template <int MODE, int NT>
__global__ void __launch_bounds__(512)
gemm_mma(const __half* __restrict__ Ah, const __half* __restrict__ Al,
         const __half* __restrict__ Bh, const __half* __restrict__ Bl,
         const float* __restrict__ bias, float* __restrict__ C,
         int N, int K) {
    constexpr unsigned STAGE_B = (NT == 3) ? 40960u : (NT == 2) ? 30720u : 20480u;
    constexpr unsigned BOFF    = (NT == 1) ? 10240u : 20480u;
    extern __shared__ char smc[];
    unsigned sbase = (unsigned)__cvta_generic_to_shared(smc);
    int tid = threadIdx.x, lane = tid & 31, warp = tid >> 5;
    int wm = warp >> 2, wn = warp & 3;            // 4x4 warp grid
    int bm = blockIdx.x * 128, bn = blockIdx.y * 128;

    unsigned aoff[2][2];
#pragma unroll
    for (int mi = 0; mi < 2; mi++)
#pragma unroll
        for (int ks = 0; ks < 2; ks++) {
            int row = wm * 32 + mi * 16 + (lane & 15);
            int col = ks * 16 + ((lane & 16) ? 8 : 0);
            aoff[mi][ks] = (unsigned)(row * 40 + col) * 2;
        }
    unsigned boff[4];
#pragma unroll
    for (int ni = 0; ni < 4; ni++) {
        int row = wn * 32 + ni * 8 + (lane & 7);
        int col = (lane >> 3) * 8;
        boff[ni] = BOFF + (unsigned)(row * 40 + col) * 2;
    }

    int r  = tid >> 2;
    int cc = (tid & 3) * 8;

    float acc[2][4][4];
#pragma unroll
    for (int mi = 0; mi < 2; mi++)
#pragma unroll
        for (int ni = 0; ni < 4; ni++)
#pragma unroll
            for (int q = 0; q < 4; q++) acc[mi][ni][q] = 0.f;

    int T = K / 32;
    int brow = bn + r;
    int crow = brow < N ? brow : (N - 1);
    int bsz  = brow < N ? 16 : 0;

#define FETCH(s, kt) do {                                                      \
        int k0 = (kt) * 32;                                                    \
        unsigned dst = sbase + (unsigned)(s) * STAGE_B +                       \
                       (unsigned)(r * 40 + cc) * 2;                            \
        cpa16(dst,          Ah + (size_t)(bm + r) * K + k0 + cc, 16);          \
        if (NT >= 2)                                                           \
            cpa16(dst + 10240u, Al + (size_t)(bm + r) * K + k0 + cc, 16);      \
        cpa16(dst + BOFF,   Bh + (size_t)crow * K + k0 + cc, bsz);             \
        if (NT == 3)                                                           \
            cpa16(dst + 30720u, Bl + (size_t)crow * K + k0 + cc, bsz);         \
    } while (0)

    FETCH(0, 0);
    asm volatile("cp.async.commit_group;" ::: "memory");
    FETCH(1, 1);
    asm volatile("cp.async.commit_group;" ::: "memory");
    FETCH(2, 2);
    asm volatile("cp.async.commit_group;" ::: "memory");

    for (int i = 0; i < T; i++) {
        asm volatile("cp.async.wait_group 2;" ::: "memory");
        __syncthreads();

        if (i + 3 < T) FETCH((i + 3) & (NSTG - 1), i + 3);
        asm volatile("cp.async.commit_group;" ::: "memory");

        unsigned st = sbase + (unsigned)(i & (NSTG - 1)) * STAGE_B;
        unsigned Bhf[4][4], Blf[4][4];
#pragma unroll
        for (int ni = 0; ni < 4; ni++) {
            ldsm4(Bhf[ni], st + boff[ni]);
            if (NT == 3) ldsm4(Blf[ni], st + boff[ni] + 10240u);
        }
#pragma unroll
        for (int ks = 0; ks < 2; ks++) {
            unsigned Ahf[2][4], Alf[2][4];
#pragma unroll
            for (int mi = 0; mi < 2; mi++) {
                ldsm4(Ahf[mi], st + aoff[mi][ks]);
                if (NT >= 2) ldsm4(Alf[mi], st + aoff[mi][ks] + 10240u);
            }
#pragma unroll
            for (int mi = 0; mi < 2; mi++)
#pragma unroll
                for (int ni = 0; ni < 4; ni++) {
                    mma_f16(acc[mi][ni], Ahf[mi], &Bhf[ni][2 * ks]);
                    if (NT >= 2)
                        mma_f16(acc[mi][ni], Alf[mi], &Bhf[ni][2 * ks]);
                    if (NT == 3)
                        mma_f16(acc[mi][ni], Ahf[mi], &Blf[ni][2 * ks]);
                }
        }
    }
#undef FETCH

#pragma unroll
    for (int mi = 0; mi < 2; mi++) {
        int rr = bm + wm * 32 + mi * 16 + (lane >> 2);
#pragma unroll
        for (int ni = 0; ni < 4; ni++) {
            int c0 = bn + wn * 32 + ni * 8 + (lane & 3) * 2;
            float* p0 = C + (size_t)rr * N + c0;
            float* p1 = C + (size_t)(rr + 8) * N + c0;
            float v0 = acc[mi][ni][0], v1 = acc[mi][ni][1];
            float v2 = acc[mi][ni][2], v3 = acc[mi][ni][3];
            if (MODE == 1) {
                float b0 = (c0 < N) ? bias[c0] : 0.f;
                float b1 = (c0 + 1 < N) ? bias[c0 + 1] : 0.f;
                v0 = fast_sigmoid(v0 + b0); v1 = fast_sigmoid(v1 + b1);
                v2 = fast_sigmoid(v2 + b0); v3 = fast_sigmoid(v3 + b1);
            }
            if (MODE == 2) {
                if (c0 < N)     { p0[0] += v0; p1[0] += v2; }
                if (c0 + 1 < N) { p0[1] += v1; p1[1] += v3; }
            } else {
                if (c0 < N)     { p0[0] = v0; p1[0] = v2; }
                if (c0 + 1 < N) { p0[1] = v1; p1[1] = v3; }
            }
        }
    }
}

// ===== 64x64-tile layer GEMM: 256 thr, 8 warps 2(m)x4(n), warp 32x16, NT=3 =====
#define STAGE64 20480u           // Ah(5120) Al(5120) Bh(5120) Bl(5120)
#define SMEM64  (NSTG * 20480)

template <int MODE>
__global__ void __launch_bounds__(256)
gemm64(const __half* __restrict__ Ah, const __half* __restrict__ Al,
       const __half* __restrict__ Bh, const __half* __restrict__ Bl,
       const float* __restrict__ bias, float* __restrict__ C,
       int N, int K) {
    extern __shared__ char smc[];
    unsigned sbase = (unsigned)__cvta_generic_to_shared(smc);
    int tid = threadIdx.x, lane = tid & 31, warp = tid >> 5;
    int wm = warp >> 2, wn = warp & 3;            // 2x4 warp grid
    int bm = blockIdx.x * 64, bn = blockIdx.y * 64;

    unsigned aoff[2][2];
#pragma unroll
    for (int mi = 0; mi < 2; mi++)
#pragma unroll
        for (int ks = 0; ks < 2; ks++) {
            int row = wm * 32 + mi * 16 + (lane & 15);
            int col = ks * 16 + ((lane & 16) ? 8 : 0);
            aoff[mi][ks] = (unsigned)(row * 40 + col) * 2;
        }
    unsigned boff[2];
#pragma unroll
    for (int ni = 0; ni < 2; ni++) {
        int row = wn * 16 + ni * 8 + (lane & 7);
        int col = (lane >> 3) * 8;
        boff[ni] = 10240u + (unsigned)(row * 40 + col) * 2;
    }

    int r  = tid >> 2;               // 0..63
    int cc = (tid & 3) * 8;

    float acc[2][2][4];
#pragma unroll
    for (int mi = 0; mi < 2; mi++)
#pragma unroll
        for (int ni = 0; ni < 2; ni++)
#pragma unroll
            for (int q = 0; q < 4; q++) acc[mi][ni][q] = 0.f;

    int T = K / 32;

#define FETCH64(s, kt) do {                                                    \
        int k0 = (kt) * 32;                                                    \
        unsigned dst = sbase + (unsigned)(s) * STAGE64 +                       \
                       (unsigned)(r * 40 + cc) * 2;                            \
        cpa16(dst,           Ah + (size_t)(bm + r) * K + k0 + cc, 16);         \
        cpa16(dst + 5120u,   Al + (size_t)(bm + r) * K + k0 + cc, 16);         \
        cpa16(dst + 10240u,  Bh + (size_t)(bn + r) * K + k0 + cc, 16);         \
        cpa16(dst + 15360u,  Bl + (size_t)(bn + r) * K + k0 + cc, 16);         \
    } while (0)

    FETCH64(0, 0);
    asm volatile("cp.async.commit_group;" ::: "memory");
    FETCH64(1, 1);
    asm volatile("cp.async.commit_group;" ::: "memory");
    FETCH64(2, 2);
    asm volatile("cp.async.commit_group;" ::: "memory");

    for (int i = 0; i < T; i++) {
        asm volatile("cp.async.wait_group 2;" ::: "memory");
        __syncthreads();

        if (i + 3 < T) FETCH64((i + 3) & (NSTG - 1), i + 3);
        asm volatile("cp.async.commit_group;" ::: "memory");

        unsigned st = sbase + (unsigned)(i & (NSTG - 1)) * STAGE64;
        unsigned Bhf[2][4], Blf[2][4];
#pragma unroll
        for (int ni = 0; ni < 2; ni++) {
            ldsm4(Bhf[ni], st + boff[ni]);
            ldsm4(Blf[ni], st + boff[ni] + 5120u);
        }
#pragma unroll
        for (int ks = 0; ks < 2; ks++) {
            unsigned Ahf[2][4], Alf[2][4];
#pragma unroll
            for (int mi = 0; mi < 2; mi++) {
                ldsm4(Ahf[mi], st + aoff[mi][ks]);
                ldsm4(Alf[mi], st + aoff[mi][ks] + 5120u);
            }
#pragma unroll
            for (int mi = 0; mi < 2; mi++)
#pragma unroll
                for (int ni = 0; ni < 2; ni++) {
                    mma_f16(acc[mi][ni], Ahf[mi], &Bhf[ni][2 * ks]);
                    mma_f16(acc[mi][ni], Alf[mi], &Bhf[ni][2 * ks]);
                    mma_f16(acc[mi][ni], Ahf[mi], &Blf[ni][2 * ks]);
                }
        }
    }
#undef FETCH64

#pragma unroll
    for (int mi = 0; mi < 2; mi++) {
        int rr = bm + wm * 32 + mi * 16 + (lane >> 2);
#pragma unroll
        for (int ni = 0; ni < 2; ni++) {
            int c0 = bn + wn * 16 + ni * 8 + (lane & 3) * 2;
            float* p0 = C + (size_t)rr * N + c0;
            float* p1 = C + (size_t)(rr + 8) * N + c0;
            float v0 = acc[mi][ni][0], v1 = acc[mi][ni][1];
            float v2 = acc[mi][ni][2], v3 = acc[mi][ni][3];
            if (MODE == 1) {
                float b0 = bias[c0], b1 = bias[c0 + 1];
                v0 = fast_sigmoid(v0 + b0); v1 = fast_sigmoid(v1 + b1);
                v2 = fast_sigmoid(v2 + b0); v3 = fast_sigmoid(v3 + b1);
            }
            if (MODE == 2) {
                p0[0] += v0; p0[1] += v1; p1[0] += v2; p1[1] += v3;
            } else {
                p0[0] = v0; p0[1] = v1; p1[0] = v2; p1[1] = v3;
            }
        }
    }
}

#define SMEM1 (NSTG * 20480)

// ---------------- driver ---------------------------------------------------------
extern "C" void kernel_launch(void* const* d_in, const int* in_sizes, int n_in,
                              void* d_out, int out_size) {
    const int*   tokens = (const int*)  d_in[0];
    const float* emb    = (const float*)d_in[1];
    const float* ln_g   = (const float*)d_in[2];
    const float* ln_b   = (const float*)d_in[3];
    const float* in_w   = (const float*)d_in[4];
    const float* conv_w = (const float*)d_in[5];
    const float* conv_b = (const float*)d_in[6];
    const float* dt_w   = (const float*)d_in[7];
    const float* dt_b   = (const float*)d_in[8];
    const float* A_log  = (const float*)d_in[9];
    const float* D_par  = (const float*)d_in[10];
    const float* out_w  = (const float*)d_in[11];
    const float* lnf_g  = (const float*)d_in[12];
    const float* lnf_b  = (const float*)d_in[13];
    const float* head_w = (const float*)d_in[14];
    float* out = (float*)d_out;

    float *x, *xr, *xc, *dt;
    cudaGetSymbolAddress((void**)&x,  g_x);
    cudaGetSymbolAddress((void**)&xr, g_xr);
    cudaGetSymbolAddress((void**)&xc, g_xc);
    cudaGetSymbolAddress((void**)&dt, g_dt);
    __half *ah_xn, *al_xn, *ah_xc, *al_xc, *ah_y, *al_y;
    cudaGetSymbolAddress((void**)&ah_xn, g_ah_xn);
    cudaGetSymbolAddress((void**)&al_xn, g_al_xn);
    cudaGetSymbolAddress((void**)&ah_xc, g_ah_xc);
    cudaGetSymbolAddress((void**)&al_xc, g_al_xc);
    cudaGetSymbolAddress((void**)&ah_y,  g_ah_y);
    cudaGetSymbolAddress((void**)&al_y,  g_al_y);
    __half *wh_in, *wl_in, *wh_dt, *wl_dt, *wh_out, *wl_out, *wh_hd;
    cudaGetSymbolAddress((void**)&wh_in,  g_wh_in);
    cudaGetSymbolAddress((void**)&wl_in,  g_wl_in);
    cudaGetSymbolAddress((void**)&wh_dt,  g_wh_dt);
    cudaGetSymbolAddress((void**)&wl_dt,  g_wl_dt);
    cudaGetSymbolAddress((void**)&wh_out, g_wh_out);
    cudaGetSymbolAddress((void**)&wl_out, g_wl_out);
    cudaGetSymbolAddress((void**)&wh_hd,  g_wh_hd);

    cudaFuncSetAttribute(gemm64<0>, cudaFuncAttributeMaxDynamicSharedMemorySize, SMEM64);
    cudaFuncSetAttribute(gemm64<1>, cudaFuncAttributeMaxDynamicSharedMemorySize, SMEM64);
    cudaFuncSetAttribute(gemm64<2>, cudaFuncAttributeMaxDynamicSharedMemorySize, SMEM64);
    cudaFuncSetAttribute(gemm_mma<0,1>, cudaFuncAttributeMaxDynamicSharedMemorySize, SMEM1);

    int n4_in = 4 * 2 * DIM * DIM / 4, n4_dt = 4 * DIM * DIM / 4;
    int n4_hd = NVOC * DIM / 4;

    // launch order keeps a GEMM in the ncu capture window
    wsplit2_kernel<<<(n4_in + 255) / 256, 256>>>((const float4*)in_w,
                                                 (uint2*)wh_in, (uint2*)wl_in, n4_in);
    embed_kernel<<<BLD, 192>>>(tokens, emb);

    for (int l = 0; l < 4; l++) {
        ln_kernel<<<BLD, 256>>>(x, ln_g + l * DIM, ln_b + l * DIM, ah_xn, al_xn);
        gemm64<0><<<dim3(16, 24), 256, SMEM64>>>(
            ah_xn, al_xn, wh_in + (size_t)l * 2 * DIM * DIM,
            wl_in + (size_t)l * 2 * DIM * DIM, nullptr, xr, 2 * DIM, DIM);
        if (l == 0) {
            wsplit2_kernel<<<(n4_dt + 255) / 256, 256>>>((const float4*)dt_w,
                                                         (uint2*)wh_dt, (uint2*)wl_dt, n4_dt);
        }
        conv_silu_kernel<<<(BLD * DIM + 255) / 256, 256>>>(conv_w + l * DIM * 3,
                                                           conv_b + l * DIM);
        gemm64<1><<<dim3(16, 12), 256, SMEM64>>>(
            ah_xc, al_xc, wh_dt + (size_t)l * DIM * DIM,
            wl_dt + (size_t)l * DIM * DIM, dt_b + l * DIM, dt, DIM, DIM);
        if (l == 0) {
            wsplit2_kernel<<<(n4_dt + 255) / 256, 256>>>((const float4*)out_w,
                                                         (uint2*)wh_out, (uint2*)wl_out, n4_dt);
        }
        scan_kernel<<<192, 128>>>(A_log + l * DIM * NSTATE, D_par + l * DIM);
        gemm64<2><<<dim3(16, 12), 256, SMEM64>>>(
            ah_y, al_y, wh_out + (size_t)l * DIM * DIM,
            wl_out + (size_t)l * DIM * DIM, nullptr, x, DIM, DIM);
        if (l == 0) {
            wsplit1_kernel<<<(n4_hd + 255) / 256, 256>>>((const float4*)head_w,
                                                         (uint2*)wh_hd, n4_hd);
        }
    }

    ln_kernel<<<BLD, 256>>>(x, lnf_g, lnf_b, ah_xn, al_xn);
    // head: 1-term fp16 (last op, errors don't compound; ~2.9e-4 predicted)
    gemm_mma<0,1><<<dim3(8, (NVOC + 127) / 128), 512, SMEM1>>>(
        ah_xn, nullptr, wh_hd, nullptr, nullptr, out, NVOC, DIM);
    (void)in_sizes; (void)n_in; (void)out_size;
}

// round 12
// speedup vs baseline: 2.2049x; 1.7613x over previous
#include <cuda_runtime.h>
#include <cuda_fp16.h>
#include <cstdint>

#define BLD   1024
#define DIM   768
#define LSEQ  512
#define NSTATE 16
#define NVOC  50257

// ---------------- fp32 scratch ----------------------------------------------
__device__ float g_x [BLD*DIM];
__device__ float g_xr[BLD*2*DIM];
__device__ float g_xc[BLD*DIM];
__device__ float g_dt[BLD*DIM];
// ---------------- split-fp16 activations -------------------------------------
__device__ __half g_ah_xn[BLD*DIM], g_al_xn[BLD*DIM];
__device__ __half g_ah_xc[BLD*DIM], g_al_xc[BLD*DIM];
__device__ __half g_ah_y [BLD*DIM], g_al_y [BLD*DIM];
// ---------------- fp16 weights (prepass output) ------------------------------
__device__ __half g_wh_in [4*2*DIM*DIM], g_wl_in [4*2*DIM*DIM];
__device__ __half g_wh_dt [4*DIM*DIM],   g_wl_dt [4*DIM*DIM];
__device__ __half g_wh_out[4*DIM*DIM],   g_wl_out[4*DIM*DIM];
__device__ __half g_wh_hd [NVOC*DIM];    // head: hi only (1-term)

__device__ __forceinline__ float fast_sigmoid(float z) {
    return 1.0f / (1.0f + __expf(-z));
}
__device__ __forceinline__ void split_store(__half* ph, __half* pl, size_t i, float v) {
    __half h = __float2half_rn(v);
    ph[i] = h;
    pl[i] = __float2half_rn(v - __half2float(h));
}

// ---------------- weight prepasses --------------------------------------------
__global__ void wsplit2_kernel(const float4* __restrict__ src,
                               uint2* __restrict__ dh, uint2* __restrict__ dl,
                               int n4) {
    int i = blockIdx.x * blockDim.x + threadIdx.x;
    if (i >= n4) return;
    float4 v = src[i];
    __half2 h01 = __floats2half2_rn(v.x, v.y);
    __half2 h23 = __floats2half2_rn(v.z, v.w);
    float2 f01 = __half22float2(h01), f23 = __half22float2(h23);
    __half2 l01 = __floats2half2_rn(v.x - f01.x, v.y - f01.y);
    __half2 l23 = __floats2half2_rn(v.z - f23.x, v.w - f23.y);
    dh[i] = make_uint2(*(unsigned*)&h01, *(unsigned*)&h23);
    dl[i] = make_uint2(*(unsigned*)&l01, *(unsigned*)&l23);
}
__global__ void wsplit1_kernel(const float4* __restrict__ src,
                               uint2* __restrict__ dh, int n4) {
    int i = blockIdx.x * blockDim.x + threadIdx.x;
    if (i >= n4) return;
    float4 v = src[i];
    __half2 h01 = __floats2half2_rn(v.x, v.y);
    __half2 h23 = __floats2half2_rn(v.z, v.w);
    dh[i] = make_uint2(*(unsigned*)&h01, *(unsigned*)&h23);
}

// ---------------- embedding gather --------------------------------------------
__global__ void embed_kernel(const int* __restrict__ tokens,
                             const float* __restrict__ emb) {
    int row = blockIdx.x;
    int tok = tokens[row];
    const float4* src = (const float4*)(emb + (size_t)tok * DIM);
    float4* dst = (float4*)(g_x + (size_t)row * DIM);
    dst[threadIdx.x] = src[threadIdx.x];
}

// ---------------- layernorm -> split fp16 --------------------------------------
__global__ void ln_kernel(const float* __restrict__ x,
                          const float* __restrict__ g,
                          const float* __restrict__ b,
                          __half* __restrict__ oh, __half* __restrict__ ol) {
    int row = blockIdx.x;
    const float* xp = x + (size_t)row * DIM;
    float s = 0.f, s2 = 0.f;
    for (int i = threadIdx.x; i < DIM; i += 256) {
        float v = xp[i];
        s += v; s2 += v * v;
    }
#pragma unroll
    for (int o = 16; o; o >>= 1) {
        s  += __shfl_xor_sync(0xffffffffu, s,  o);
        s2 += __shfl_xor_sync(0xffffffffu, s2, o);
    }
    __shared__ float sh[16];
    int w = threadIdx.x >> 5, lane = threadIdx.x & 31;
    if (lane == 0) { sh[w] = s; sh[8 + w] = s2; }
    __syncthreads();
    s = 0.f; s2 = 0.f;
#pragma unroll
    for (int i = 0; i < 8; i++) { s += sh[i]; s2 += sh[8 + i]; }
    float m   = s * (1.0f / DIM);
    float var = s2 * (1.0f / DIM) - m * m;
    float inv = rsqrtf(var + 1e-5f);
    for (int i = threadIdx.x; i < DIM; i += 256) {
        float v = (xp[i] - m) * inv * g[i] + b[i];
        split_store(oh, ol, (size_t)row * DIM + i, v);
    }
}

// ---------------- depthwise conv(3) + silu -------------------------------------
__global__ void conv_silu_kernel(const float* __restrict__ cw,
                                 const float* __restrict__ cb) {
    int idx = blockIdx.x * blockDim.x + threadIdx.x;
    if (idx >= BLD * DIM) return;
    int d = idx % DIM;
    int l = (idx / DIM) % LSEQ;
    int b = idx / (DIM * LSEQ);
    const float* base = g_xr + (size_t)b * LSEQ * (2 * DIM);
    float xm = (l > 0)        ? base[(size_t)(l - 1) * 2 * DIM + d] : 0.f;
    float x0 =                  base[(size_t)l       * 2 * DIM + d];
    float xp = (l < LSEQ - 1) ? base[(size_t)(l + 1) * 2 * DIM + d] : 0.f;
    float z = xm * cw[d * 3 + 0] + x0 * cw[d * 3 + 1] + xp * cw[d * 3 + 2] + cb[d];
    float v = z * fast_sigmoid(z);
    g_xc[idx] = v;
    split_store(g_ah_xc, g_al_xc, idx, v);
}

// ------- selective scan: software-pipelined loads, pure-FMA h-chain ------------
#define SCH 8
__global__ void scan_kernel(const float* __restrict__ A_log,
                            const float* __restrict__ Dp) {
    int tid = blockIdx.x * blockDim.x + threadIdx.x;   // 24576
    int s = tid & (NSTATE - 1);
    int d = (tid >> 4) % DIM;
    int b = tid / (DIM * NSTATE);
    float A  = -__expf(A_log[d * NSTATE + s]);
    float Dd = Dp[d];
    const float* dtp  = g_dt + (size_t)b * LSEQ * DIM + d;
    const float* xcp  = g_xc + (size_t)b * LSEQ * DIM + d;
    const float* resp = g_xr + (size_t)b * LSEQ * (2 * DIM) + DIM + d;
    size_t ybase = (size_t)b * LSEQ * DIM + d;

    float dbuf[2][SCH], xbuf[2][SCH], rbuf[2][SCH];
#pragma unroll
    for (int c = 0; c < SCH; c++) {
        dbuf[0][c] = dtp[(size_t)c * DIM];
        xbuf[0][c] = xcp[(size_t)c * DIM];
        rbuf[0][c] = resp[(size_t)c * 2 * DIM];   // broadcast across 16 lanes
    }
    float h = 0.f;

#define SCAN_CHUNK(BUF, L0)                                                    \
    _Pragma("unroll")                                                          \
    for (int c = 0; c < SCH; c++) {                                            \
        float e = __expf(A * dbuf[BUF][c]);                                    \
        h = h * e + xbuf[BUF][c];                                              \
        float sum = h;                                                         \
        sum += __shfl_xor_sync(0xffffffffu, sum, 1);                           \
        sum += __shfl_xor_sync(0xffffffffu, sum, 2);                           \
        sum += __shfl_xor_sync(0xffffffffu, sum, 4);                           \
        sum += __shfl_xor_sync(0xffffffffu, sum, 8);                           \
        if (s == 0) {                                                          \
            float r = rbuf[BUF][c];                                            \
            float v = sum * Dd * (r * fast_sigmoid(r));                        \
            split_store(g_ah_y, g_al_y, ybase + (size_t)((L0) + c) * DIM, v);  \
        }                                                                      \
    }
#define SCAN_PREF(BUF, CH)                                                     \
    if ((CH) < LSEQ / SCH) {                                                   \
        int base = (CH) * SCH;                                                 \
        _Pragma("unroll")                                                      \
        for (int c = 0; c < SCH; c++) {                                        \
            dbuf[BUF][c] = dtp[(size_t)(base + c) * DIM];                      \
            xbuf[BUF][c] = xcp[(size_t)(base + c) * DIM];                      \
            rbuf[BUF][c] = resp[(size_t)(base + c) * 2 * DIM];                 \
        }                                                                      \
    }

#pragma unroll 1
    for (int ch = 0; ch < LSEQ / SCH; ch += 2) {
        SCAN_PREF(1, ch + 1);            // prefetch next chunk (off-chain)
        SCAN_CHUNK(0, ch * SCH);         // compute current
        SCAN_PREF(0, ch + 2);
        SCAN_CHUNK(1, (ch + 1) * SCH);
    }
#undef SCAN_CHUNK
#undef SCAN_PREF
}

// ---------------- shared MMA primitives -----------------------------------------
__device__ __forceinline__ void ldsm4(unsigned r[4], unsigned a) {
    asm volatile("ldmatrix.sync.aligned.m8n8.x4.shared.b16 {%0,%1,%2,%3}, [%4];"
                 : "=r"(r[0]), "=r"(r[1]), "=r"(r[2]), "=r"(r[3]) : "r"(a));
}
__device__ __forceinline__ void mma_f16(float c[4], const unsigned a[4],
                                        const unsigned b[2]) {
    asm volatile(
        "mma.sync.aligned.m16n8k16.row.col.f32.f16.f16.f32 "
        "{%0,%1,%2,%3}, {%4,%5,%6,%7}, {%8,%9}, {%0,%1,%2,%3};"
        : "+f"(c[0]), "+f"(c[1]), "+f"(c[2]), "+f"(c[3])
        : "r"(a[0]), "r"(a[1]), "r"(a[2]), "r"(a[3]), "r"(b[0]), "r"(b[1]));
}
__device__ __forceinline__ void cpa16(unsigned dst, const void* src, int sz) {
    asm volatile("cp.async.cg.shared.global [%0], [%1], 16, %2;"
                 :: "r"(dst), "l"(src), "r"(sz));
}

#define NSTG 4

// ===== 128x128-tile GEMM: 512 thr, NT terms (head uses NT=1) ===================
template <int MODE, int NT>
__global__ void __launch_bounds__(512)
gemm_mma(const __half* __restrict__ Ah, const __half* __restrict__ Al,
         const __half* __restrict__ Bh, const __half* __restrict__ Bl,
         const float* __restrict__ bias, float* __restrict__ C,
         int N, int K) {
    constexpr unsigned STAGE_B = (NT == 3) ? 40960u : (NT == 2) ? 30720u : 20480u;
    constexpr unsigned BOFF    = (NT == 1) ? 10240u : 20480u;
    extern __shared__ char smc[];
    unsigned sbase = (unsigned)__cvta_generic_to_shared(smc);
    int tid = threadIdx.x, lane = tid & 31, warp = tid >> 5;
    int wm = warp >> 2, wn = warp & 3;            // 4x4 warp grid
    int bm = blockIdx.x * 128, bn = blockIdx.y * 128;

    unsigned aoff[2][2];
#pragma unroll
    for (int mi = 0; mi < 2; mi++)
#pragma unroll
        for (int ks = 0; ks < 2; ks++) {
            int row = wm * 32 + mi * 16 + (lane & 15);
            int col = ks * 16 + ((lane & 16) ? 8 : 0);
            aoff[mi][ks] = (unsigned)(row * 40 + col) * 2;
        }
    unsigned boff[4];
#pragma unroll
    for (int ni = 0; ni < 4; ni++) {
        int row = wn * 32 + ni * 8 + (lane & 7);
        int col = (lane >> 3) * 8;
        boff[ni] = BOFF + (unsigned)(row * 40 + col) * 2;
    }

    int r  = tid >> 2;
    int cc = (tid & 3) * 8;

    float acc[2][4][4];
#pragma unroll
    for (int mi = 0; mi < 2; mi++)
#pragma unroll
        for (int ni = 0; ni < 4; ni++)
#pragma unroll
            for (int q = 0; q < 4; q++) acc[mi][ni][q] = 0.f;

    int T = K / 32;
    int brow = bn + r;
    int crow = brow < N ? brow : (N - 1);
    int bsz  = brow < N ? 16 : 0;

#define FETCH(s, kt) do {                                                      \
        int k0 = (kt) * 32;                                                    \
        unsigned dst = sbase + (unsigned)(s) * STAGE_B +                       \
                       (unsigned)(r * 40 + cc) * 2;                            \
        cpa16(dst,          Ah + (size_t)(bm + r) * K + k0 + cc, 16);          \
        if (NT >= 2)                                                           \
            cpa16(dst + 10240u, Al + (size_t)(bm + r) * K + k0 + cc, 16);      \
        cpa16(dst + BOFF,   Bh + (size_t)crow * K + k0 + cc, bsz);             \
        if (NT == 3)                                                           \
            cpa16(dst + 30720u, Bl + (size_t)crow * K + k0 + cc, bsz);         \
    } while (0)

    FETCH(0, 0);
    asm volatile("cp.async.commit_group;" ::: "memory");
    FETCH(1, 1);
    asm volatile("cp.async.commit_group;" ::: "memory");
    FETCH(2, 2);
    asm volatile("cp.async.commit_group;" ::: "memory");

    for (int i = 0; i < T; i++) {
        asm volatile("cp.async.wait_group 2;" ::: "memory");
        __syncthreads();

        if (i + 3 < T) FETCH((i + 3) & (NSTG - 1), i + 3);
        asm volatile("cp.async.commit_group;" ::: "memory");

        unsigned st = sbase + (unsigned)(i & (NSTG - 1)) * STAGE_B;
        unsigned Bhf[4][4], Blf[4][4];
#pragma unroll
        for (int ni = 0; ni < 4; ni++) {
            ldsm4(Bhf[ni], st + boff[ni]);
            if (NT == 3) ldsm4(Blf[ni], st + boff[ni] + 10240u);
        }
#pragma unroll
        for (int ks = 0; ks < 2; ks++) {
            unsigned Ahf[2][4], Alf[2][4];
#pragma unroll
            for (int mi = 0; mi < 2; mi++) {
                ldsm4(Ahf[mi], st + aoff[mi][ks]);
                if (NT >= 2) ldsm4(Alf[mi], st + aoff[mi][ks] + 10240u);
            }
#pragma unroll
            for (int mi = 0; mi < 2; mi++)
#pragma unroll
                for (int ni = 0; ni < 4; ni++) {
                    mma_f16(acc[mi][ni], Ahf[mi], &Bhf[ni][2 * ks]);
                    if (NT >= 2)
                        mma_f16(acc[mi][ni], Alf[mi], &Bhf[ni][2 * ks]);
                    if (NT == 3)
                        mma_f16(acc[mi][ni], Ahf[mi], &Blf[ni][2 * ks]);
                }
        }
    }
#undef FETCH

#pragma unroll
    for (int mi = 0; mi < 2; mi++) {
        int rr = bm + wm * 32 + mi * 16 + (lane >> 2);
#pragma unroll
        for (int ni = 0; ni < 4; ni++) {
            int c0 = bn + wn * 32 + ni * 8 + (lane & 3) * 2;
            float* p0 = C + (size_t)rr * N + c0;
            float* p1 = C + (size_t)(rr + 8) * N + c0;
            float v0 = acc[mi][ni][0], v1 = acc[mi][ni][1];
            float v2 = acc[mi][ni][2], v3 = acc[mi][ni][3];
            if (MODE == 1) {
                float b0 = (c0 < N) ? bias[c0] : 0.f;
                float b1 = (c0 + 1 < N) ? bias[c0 + 1] : 0.f;
                v0 = fast_sigmoid(v0 + b0); v1 = fast_sigmoid(v1 + b1);
                v2 = fast_sigmoid(v2 + b0); v3 = fast_sigmoid(v3 + b1);
            }
            if (MODE == 2) {
                if (c0 < N)     { p0[0] += v0; p1[0] += v2; }
                if (c0 + 1 < N) { p0[1] += v1; p1[1] += v3; }
            } else {
                if (c0 < N)     { p0[0] = v0; p1[0] = v2; }
                if (c0 + 1 < N) { p0[1] = v1; p1[1] = v3; }
            }
        }
    }
}

// ===== 64x64-tile layer GEMM: 256 thr, 8 warps 2(m)x4(n), warp 32x16, NT=3 =====
#define STAGE64 20480u           // Ah(5120) Al(5120) Bh(5120) Bl(5120)
#define SMEM64  (NSTG * 20480)

template <int MODE>
__global__ void __launch_bounds__(256)
gemm64(const __half* __restrict__ Ah, const __half* __restrict__ Al,
       const __half* __restrict__ Bh, const __half* __restrict__ Bl,
       const float* __restrict__ bias, float* __restrict__ C,
       int N, int K) {
    extern __shared__ char smc[];
    unsigned sbase = (unsigned)__cvta_generic_to_shared(smc);
    int tid = threadIdx.x, lane = tid & 31, warp = tid >> 5;
    int wm = warp >> 2, wn = warp & 3;            // 2x4 warp grid
    int bm = blockIdx.x * 64, bn = blockIdx.y * 64;

    unsigned aoff[2][2];
#pragma unroll
    for (int mi = 0; mi < 2; mi++)
#pragma unroll
        for (int ks = 0; ks < 2; ks++) {
            int row = wm * 32 + mi * 16 + (lane & 15);
            int col = ks * 16 + ((lane & 16) ? 8 : 0);
            aoff[mi][ks] = (unsigned)(row * 40 + col) * 2;
        }
    unsigned boff[2];
#pragma unroll
    for (int ni = 0; ni < 2; ni++) {
        int row = wn * 16 + ni * 8 + (lane & 7);
        int col = (lane >> 3) * 8;
        boff[ni] = 10240u + (unsigned)(row * 40 + col) * 2;
    }

    int r  = tid >> 2;               // 0..63
    int cc = (tid & 3) * 8;

    float acc[2][2][4];
#pragma unroll
    for (int mi = 0; mi < 2; mi++)
#pragma unroll
        for (int ni = 0; ni < 2; ni++)
#pragma unroll
            for (int q = 0; q < 4; q++) acc[mi][ni][q] = 0.f;

    int T = K / 32;

#define FETCH64(s, kt) do {                                                    \
        int k0 = (kt) * 32;                                                    \
        unsigned dst = sbase + (unsigned)(s) * STAGE64 +                       \
                       (unsigned)(r * 40 + cc) * 2;                            \
        cpa16(dst,           Ah + (size_t)(bm + r) * K + k0 + cc, 16);         \
        cpa16(dst + 5120u,   Al + (size_t)(bm + r) * K + k0 + cc, 16);         \
        cpa16(dst + 10240u,  Bh + (size_t)(bn + r) * K + k0 + cc, 16);         \
        cpa16(dst + 15360u,  Bl + (size_t)(bn + r) * K + k0 + cc, 16);         \
    } while (0)

    FETCH64(0, 0);
    asm volatile("cp.async.commit_group;" ::: "memory");
    FETCH64(1, 1);
    asm volatile("cp.async.commit_group;" ::: "memory");
    FETCH64(2, 2);
    asm volatile("cp.async.commit_group;" ::: "memory");

    for (int i = 0; i < T; i++) {
        asm volatile("cp.async.wait_group 2;" ::: "memory");
        __syncthreads();

        if (i + 3 < T) FETCH64((i + 3) & (NSTG - 1), i + 3);
        asm volatile("cp.async.commit_group;" ::: "memory");

        unsigned st = sbase + (unsigned)(i & (NSTG - 1)) * STAGE64;
        unsigned Bhf[2][4], Blf[2][4];
#pragma unroll
        for (int ni = 0; ni < 2; ni++) {
            ldsm4(Bhf[ni], st + boff[ni]);
            ldsm4(Blf[ni], st + boff[ni] + 5120u);
        }
#pragma unroll
        for (int ks = 0; ks < 2; ks++) {
            unsigned Ahf[2][4], Alf[2][4];
#pragma unroll
            for (int mi = 0; mi < 2; mi++) {
                ldsm4(Ahf[mi], st + aoff[mi][ks]);
                ldsm4(Alf[mi], st + aoff[mi][ks] + 5120u);
            }
#pragma unroll
            for (int mi = 0; mi < 2; mi++)
#pragma unroll
                for (int ni = 0; ni < 2; ni++) {
                    mma_f16(acc[mi][ni], Ahf[mi], &Bhf[ni][2 * ks]);
                    mma_f16(acc[mi][ni], Alf[mi], &Bhf[ni][2 * ks]);
                    mma_f16(acc[mi][ni], Ahf[mi], &Blf[ni][2 * ks]);
                }
        }
    }
#undef FETCH64

#pragma unroll
    for (int mi = 0; mi < 2; mi++) {
        int rr = bm + wm * 32 + mi * 16 + (lane >> 2);
#pragma unroll
        for (int ni = 0; ni < 2; ni++) {
            int c0 = bn + wn * 16 + ni * 8 + (lane & 3) * 2;
            float* p0 = C + (size_t)rr * N + c0;
            float* p1 = C + (size_t)(rr + 8) * N + c0;
            float v0 = acc[mi][ni][0], v1 = acc[mi][ni][1];
            float v2 = acc[mi][ni][2], v3 = acc[mi][ni][3];
            if (MODE == 1) {
                float b0 = bias[c0], b1 = bias[c0 + 1];
                v0 = fast_sigmoid(v0 + b0); v1 = fast_sigmoid(v1 + b1);
                v2 = fast_sigmoid(v2 + b0); v3 = fast_sigmoid(v3 + b1);
            }
            if (MODE == 2) {
                p0[0] += v0; p0[1] += v1; p1[0] += v2; p1[1] += v3;
            } else {
                p0[0] = v0; p0[1] = v1; p1[0] = v2; p1[1] = v3;
            }
        }
    }
}

#define SMEM1 (NSTG * 20480)

// ---------------- driver ---------------------------------------------------------
extern "C" void kernel_launch(void* const* d_in, const int* in_sizes, int n_in,
                              void* d_out, int out_size) {
    const int*   tokens = (const int*)  d_in[0];
    const float* emb    = (const float*)d_in[1];
    const float* ln_g   = (const float*)d_in[2];
    const float* ln_b   = (const float*)d_in[3];
    const float* in_w   = (const float*)d_in[4];
    const float* conv_w = (const float*)d_in[5];
    const float* conv_b = (const float*)d_in[6];
    const float* dt_w   = (const float*)d_in[7];
    const float* dt_b   = (const float*)d_in[8];
    const float* A_log  = (const float*)d_in[9];
    const float* D_par  = (const float*)d_in[10];
    const float* out_w  = (const float*)d_in[11];
    const float* lnf_g  = (const float*)d_in[12];
    const float* lnf_b  = (const float*)d_in[13];
    const float* head_w = (const float*)d_in[14];
    float* out = (float*)d_out;

    float *x, *xr, *xc, *dt;
    cudaGetSymbolAddress((void**)&x,  g_x);
    cudaGetSymbolAddress((void**)&xr, g_xr);
    cudaGetSymbolAddress((void**)&xc, g_xc);
    cudaGetSymbolAddress((void**)&dt, g_dt);
    __half *ah_xn, *al_xn, *ah_xc, *al_xc, *ah_y, *al_y;
    cudaGetSymbolAddress((void**)&ah_xn, g_ah_xn);
    cudaGetSymbolAddress((void**)&al_xn, g_al_xn);
    cudaGetSymbolAddress((void**)&ah_xc, g_ah_xc);
    cudaGetSymbolAddress((void**)&al_xc, g_al_xc);
    cudaGetSymbolAddress((void**)&ah_y,  g_ah_y);
    cudaGetSymbolAddress((void**)&al_y,  g_al_y);
    __half *wh_in, *wl_in, *wh_dt, *wl_dt, *wh_out, *wl_out, *wh_hd;
    cudaGetSymbolAddress((void**)&wh_in,  g_wh_in);
    cudaGetSymbolAddress((void**)&wl_in,  g_wl_in);
    cudaGetSymbolAddress((void**)&wh_dt,  g_wh_dt);
    cudaGetSymbolAddress((void**)&wl_dt,  g_wl_dt);
    cudaGetSymbolAddress((void**)&wh_out, g_wh_out);
    cudaGetSymbolAddress((void**)&wl_out, g_wl_out);
    cudaGetSymbolAddress((void**)&wh_hd,  g_wh_hd);

    cudaFuncSetAttribute(gemm64<0>, cudaFuncAttributeMaxDynamicSharedMemorySize, SMEM64);
    cudaFuncSetAttribute(gemm64<1>, cudaFuncAttributeMaxDynamicSharedMemorySize, SMEM64);
    cudaFuncSetAttribute(gemm64<2>, cudaFuncAttributeMaxDynamicSharedMemorySize, SMEM64);
    cudaFuncSetAttribute(gemm_mma<0,1>, cudaFuncAttributeMaxDynamicSharedMemorySize, SMEM1);

    int n4_in = 4 * 2 * DIM * DIM / 4, n4_dt = 4 * DIM * DIM / 4;
    int n4_hd = NVOC * DIM / 4;

    // launch order keeps a GEMM in the ncu capture window
    wsplit2_kernel<<<(n4_in + 255) / 256, 256>>>((const float4*)in_w,
                                                 (uint2*)wh_in, (uint2*)wl_in, n4_in);
    embed_kernel<<<BLD, 192>>>(tokens, emb);

    for (int l = 0; l < 4; l++) {
        ln_kernel<<<BLD, 256>>>(x, ln_g + l * DIM, ln_b + l * DIM, ah_xn, al_xn);
        gemm64<0><<<dim3(16, 24), 256, SMEM64>>>(
            ah_xn, al_xn, wh_in + (size_t)l * 2 * DIM * DIM,
            wl_in + (size_t)l * 2 * DIM * DIM, nullptr, xr, 2 * DIM, DIM);
        if (l == 0) {
            wsplit2_kernel<<<(n4_dt + 255) / 256, 256>>>((const float4*)dt_w,
                                                         (uint2*)wh_dt, (uint2*)wl_dt, n4_dt);
        }
        conv_silu_kernel<<<(BLD * DIM + 255) / 256, 256>>>(conv_w + l * DIM * 3,
                                                           conv_b + l * DIM);
        gemm64<1><<<dim3(16, 12), 256, SMEM64>>>(
            ah_xc, al_xc, wh_dt + (size_t)l * DIM * DIM,
            wl_dt + (size_t)l * DIM * DIM, dt_b + l * DIM, dt, DIM, DIM);
        if (l == 0) {
            wsplit2_kernel<<<(n4_dt + 255) / 256, 256>>>((const float4*)out_w,
                                                         (uint2*)wh_out, (uint2*)wl_out, n4_dt);
        }
        scan_kernel<<<192, 128>>>(A_log + l * DIM * NSTATE, D_par + l * DIM);
        gemm64<2><<<dim3(16, 12), 256, SMEM64>>>(
            ah_y, al_y, wh_out + (size_t)l * DIM * DIM,
            wl_out + (size_t)l * DIM * DIM, nullptr, x, DIM, DIM);
        if (l == 0) {
            wsplit1_kernel<<<(n4_hd + 255) / 256, 256>>>((const float4*)head_w,
                                                         (uint2*)wh_hd, n4_hd);
        }
    }

    ln_kernel<<<BLD, 256>>>(x, lnf_g, lnf_b, ah_xn, al_xn);
    // head: 1-term fp16 (last op, errors don't compound)
    gemm_mma<0,1><<<dim3(8, (NVOC + 127) / 128), 512, SMEM1>>>(
        ah_xn, nullptr, wh_hd, nullptr, nullptr, out, NVOC, DIM);
    (void)in_sizes; (void)n_in; (void)out_size;
}

// round 13
// speedup vs baseline: 2.3748x; 1.0770x over previous
#include <cuda_runtime.h>
#include <cuda_fp16.h>
#include <cstdint>

#define BLD   1024
#define DIM   768
#define LSEQ  512
#define NSTATE 16
#define NVOC  50257

// ---------------- fp32 scratch ----------------------------------------------
__device__ float g_x [BLD*DIM];
__device__ float g_xr[BLD*2*DIM];
__device__ float g_xc[BLD*DIM];
__device__ float g_dt[BLD*DIM];
// ---------------- split-fp16 activations -------------------------------------
__device__ __half g_ah_xn[BLD*DIM], g_al_xn[BLD*DIM];
__device__ __half g_ah_xc[BLD*DIM], g_al_xc[BLD*DIM];
__device__ __half g_ah_y [BLD*DIM], g_al_y [BLD*DIM];
// ---------------- fp16 weights (hi only — NT2 layers / NT1 head) --------------
__device__ __half g_wh_in [4*2*DIM*DIM];
__device__ __half g_wh_dt [4*DIM*DIM];
__device__ __half g_wh_out[4*DIM*DIM];
__device__ __half g_wh_hd [NVOC*DIM];

__device__ __forceinline__ float fast_sigmoid(float z) {
    return 1.0f / (1.0f + __expf(-z));
}
__device__ __forceinline__ void split_store(__half* ph, __half* pl, size_t i, float v) {
    __half h = __float2half_rn(v);
    ph[i] = h;
    pl[i] = __float2half_rn(v - __half2float(h));
}

// ---------------- weight fp16 prepass (hi only) --------------------------------
__global__ void wsplit1_kernel(const float4* __restrict__ src,
                               uint2* __restrict__ dh, int n4) {
    int i = blockIdx.x * blockDim.x + threadIdx.x;
    if (i >= n4) return;
    float4 v = src[i];
    __half2 h01 = __floats2half2_rn(v.x, v.y);
    __half2 h23 = __floats2half2_rn(v.z, v.w);
    dh[i] = make_uint2(*(unsigned*)&h01, *(unsigned*)&h23);
}

// ---------------- embedding gather --------------------------------------------
__global__ void embed_kernel(const int* __restrict__ tokens,
                             const float* __restrict__ emb) {
    int row = blockIdx.x;
    int tok = tokens[row];
    const float4* src = (const float4*)(emb + (size_t)tok * DIM);
    float4* dst = (float4*)(g_x + (size_t)row * DIM);
    dst[threadIdx.x] = src[threadIdx.x];
}

// ---------------- layernorm -> split fp16 --------------------------------------
__global__ void ln_kernel(const float* __restrict__ x,
                          const float* __restrict__ g,
                          const float* __restrict__ b,
                          __half* __restrict__ oh, __half* __restrict__ ol) {
    int row = blockIdx.x;
    const float* xp = x + (size_t)row * DIM;
    float s = 0.f, s2 = 0.f;
    for (int i = threadIdx.x; i < DIM; i += 256) {
        float v = xp[i];
        s += v; s2 += v * v;
    }
#pragma unroll
    for (int o = 16; o; o >>= 1) {
        s  += __shfl_xor_sync(0xffffffffu, s,  o);
        s2 += __shfl_xor_sync(0xffffffffu, s2, o);
    }
    __shared__ float sh[16];
    int w = threadIdx.x >> 5, lane = threadIdx.x & 31;
    if (lane == 0) { sh[w] = s; sh[8 + w] = s2; }
    __syncthreads();
    s = 0.f; s2 = 0.f;
#pragma unroll
    for (int i = 0; i < 8; i++) { s += sh[i]; s2 += sh[8 + i]; }
    float m   = s * (1.0f / DIM);
    float var = s2 * (1.0f / DIM) - m * m;
    float inv = rsqrtf(var + 1e-5f);
    for (int i = threadIdx.x; i < DIM; i += 256) {
        float v = (xp[i] - m) * inv * g[i] + b[i];
        split_store(oh, ol, (size_t)row * DIM + i, v);
    }
}

// ---------------- depthwise conv(3) + silu -------------------------------------
__global__ void conv_silu_kernel(const float* __restrict__ cw,
                                 const float* __restrict__ cb) {
    int idx = blockIdx.x * blockDim.x + threadIdx.x;
    if (idx >= BLD * DIM) return;
    int d = idx % DIM;
    int l = (idx / DIM) % LSEQ;
    int b = idx / (DIM * LSEQ);
    const float* base = g_xr + (size_t)b * LSEQ * (2 * DIM);
    float xm = (l > 0)        ? base[(size_t)(l - 1) * 2 * DIM + d] : 0.f;
    float x0 =                  base[(size_t)l       * 2 * DIM + d];
    float xp = (l < LSEQ - 1) ? base[(size_t)(l + 1) * 2 * DIM + d] : 0.f;
    float z = xm * cw[d * 3 + 0] + x0 * cw[d * 3 + 1] + xp * cw[d * 3 + 2] + cb[d];
    float v = z * fast_sigmoid(z);
    g_xc[idx] = v;
    split_store(g_ah_xc, g_al_xc, idx, v);
}

// ------- selective scan: software-pipelined loads, pure-FMA h-chain ------------
#define SCH 8
__global__ void scan_kernel(const float* __restrict__ A_log,
                            const float* __restrict__ Dp) {
    int tid = blockIdx.x * blockDim.x + threadIdx.x;   // 24576
    int s = tid & (NSTATE - 1);
    int d = (tid >> 4) % DIM;
    int b = tid / (DIM * NSTATE);
    float A  = -__expf(A_log[d * NSTATE + s]);
    float Dd = Dp[d];
    const float* dtp  = g_dt + (size_t)b * LSEQ * DIM + d;
    const float* xcp  = g_xc + (size_t)b * LSEQ * DIM + d;
    const float* resp = g_xr + (size_t)b * LSEQ * (2 * DIM) + DIM + d;
    size_t ybase = (size_t)b * LSEQ * DIM + d;

    float dbuf[2][SCH], xbuf[2][SCH], rbuf[2][SCH];
#pragma unroll
    for (int c = 0; c < SCH; c++) {
        dbuf[0][c] = dtp[(size_t)c * DIM];
        xbuf[0][c] = xcp[(size_t)c * DIM];
        rbuf[0][c] = resp[(size_t)c * 2 * DIM];
    }
    float h = 0.f;

#define SCAN_CHUNK(BUF, L0)                                                    \
    _Pragma("unroll")                                                          \
    for (int c = 0; c < SCH; c++) {                                            \
        float e = __expf(A * dbuf[BUF][c]);                                    \
        h = h * e + xbuf[BUF][c];                                              \
        float sum = h;                                                         \
        sum += __shfl_xor_sync(0xffffffffu, sum, 1);                           \
        sum += __shfl_xor_sync(0xffffffffu, sum, 2);                           \
        sum += __shfl_xor_sync(0xffffffffu, sum, 4);                           \
        sum += __shfl_xor_sync(0xffffffffu, sum, 8);                           \
        if (s == 0) {                                                          \
            float r = rbuf[BUF][c];                                            \
            float v = sum * Dd * (r * fast_sigmoid(r));                        \
            split_store(g_ah_y, g_al_y, ybase + (size_t)((L0) + c) * DIM, v);  \
        }                                                                      \
    }
#define SCAN_PREF(BUF, CH)                                                     \
    if ((CH) < LSEQ / SCH) {                                                   \
        int base = (CH) * SCH;                                                 \
        _Pragma("unroll")                                                      \
        for (int c = 0; c < SCH; c++) {                                        \
            dbuf[BUF][c] = dtp[(size_t)(base + c) * DIM];                      \
            xbuf[BUF][c] = xcp[(size_t)(base + c) * DIM];                      \
            rbuf[BUF][c] = resp[(size_t)(base + c) * 2 * DIM];                 \
        }                                                                      \
    }

#pragma unroll 1
    for (int ch = 0; ch < LSEQ / SCH; ch += 2) {
        SCAN_PREF(1, ch + 1);
        SCAN_CHUNK(0, ch * SCH);
        SCAN_PREF(0, ch + 2);
        SCAN_CHUNK(1, (ch + 1) * SCH);
    }
#undef SCAN_CHUNK
#undef SCAN_PREF
}

// ---------------- shared MMA primitives -----------------------------------------
__device__ __forceinline__ void ldsm4(unsigned r[4], unsigned a) {
    asm volatile("ldmatrix.sync.aligned.m8n8.x4.shared.b16 {%0,%1,%2,%3}, [%4];"
                 : "=r"(r[0]), "=r"(r[1]), "=r"(r[2]), "=r"(r[3]) : "r"(a));
}
__device__ __forceinline__ void mma_f16(float c[4], const unsigned a[4],
                                        const unsigned b[2]) {
    asm volatile(
        "mma.sync.aligned.m16n8k16.row.col.f32.f16.f16.f32 "
        "{%0,%1,%2,%3}, {%4,%5,%6,%7}, {%8,%9}, {%0,%1,%2,%3};"
        : "+f"(c[0]), "+f"(c[1]), "+f"(c[2]), "+f"(c[3])
        : "r"(a[0]), "r"(a[1]), "r"(a[2]), "r"(a[3]), "r"(b[0]), "r"(b[1]));
}
__device__ __forceinline__ void cpa16(unsigned dst, const void* src, int sz) {
    asm volatile("cp.async.cg.shared.global [%0], [%1], 16, %2;"
                 :: "r"(dst), "l"(src), "r"(sz));
}

#define NSTG 4

// ===== 128x128-tile head GEMM: 512 thr, NT=1 (AhBh only) =======================
template <int MODE>
__global__ void __launch_bounds__(512)
gemm_head(const __half* __restrict__ Ah, const __half* __restrict__ Bh,
          float* __restrict__ C, int N, int K) {
    constexpr unsigned STAGE_B = 20480u;
    extern __shared__ char smc[];
    unsigned sbase = (unsigned)__cvta_generic_to_shared(smc);
    int tid = threadIdx.x, lane = tid & 31, warp = tid >> 5;
    int wm = warp >> 2, wn = warp & 3;            // 4x4 warp grid
    int bm = blockIdx.x * 128, bn = blockIdx.y * 128;

    unsigned aoff[2][2];
#pragma unroll
    for (int mi = 0; mi < 2; mi++)
#pragma unroll
        for (int ks = 0; ks < 2; ks++) {
            int row = wm * 32 + mi * 16 + (lane & 15);
            int col = ks * 16 + ((lane & 16) ? 8 : 0);
            aoff[mi][ks] = (unsigned)(row * 40 + col) * 2;
        }
    unsigned boff[4];
#pragma unroll
    for (int ni = 0; ni < 4; ni++) {
        int row = wn * 32 + ni * 8 + (lane & 7);
        int col = (lane >> 3) * 8;
        boff[ni] = 10240u + (unsigned)(row * 40 + col) * 2;
    }

    int r  = tid >> 2;
    int cc = (tid & 3) * 8;

    float acc[2][4][4];
#pragma unroll
    for (int mi = 0; mi < 2; mi++)
#pragma unroll
        for (int ni = 0; ni < 4; ni++)
#pragma unroll
            for (int q = 0; q < 4; q++) acc[mi][ni][q] = 0.f;

    int T = K / 32;
    int brow = bn + r;
    int crow = brow < N ? brow : (N - 1);
    int bsz  = brow < N ? 16 : 0;

#define FETCH(s, kt) do {                                                      \
        int k0 = (kt) * 32;                                                    \
        unsigned dst = sbase + (unsigned)(s) * STAGE_B +                       \
                       (unsigned)(r * 40 + cc) * 2;                            \
        cpa16(dst,           Ah + (size_t)(bm + r) * K + k0 + cc, 16);         \
        cpa16(dst + 10240u,  Bh + (size_t)crow * K + k0 + cc, bsz);            \
    } while (0)

    FETCH(0, 0);
    asm volatile("cp.async.commit_group;" ::: "memory");
    FETCH(1, 1);
    asm volatile("cp.async.commit_group;" ::: "memory");
    FETCH(2, 2);
    asm volatile("cp.async.commit_group;" ::: "memory");

    for (int i = 0; i < T; i++) {
        asm volatile("cp.async.wait_group 2;" ::: "memory");
        __syncthreads();

        if (i + 3 < T) FETCH((i + 3) & (NSTG - 1), i + 3);
        asm volatile("cp.async.commit_group;" ::: "memory");

        unsigned st = sbase + (unsigned)(i & (NSTG - 1)) * STAGE_B;
        unsigned Bf[4][4];
#pragma unroll
        for (int ni = 0; ni < 4; ni++) ldsm4(Bf[ni], st + boff[ni]);
#pragma unroll
        for (int ks = 0; ks < 2; ks++) {
            unsigned Af[2][4];
#pragma unroll
            for (int mi = 0; mi < 2; mi++) ldsm4(Af[mi], st + aoff[mi][ks]);
#pragma unroll
            for (int mi = 0; mi < 2; mi++)
#pragma unroll
                for (int ni = 0; ni < 4; ni++)
                    mma_f16(acc[mi][ni], Af[mi], &Bf[ni][2 * ks]);
        }
    }
#undef FETCH

#pragma unroll
    for (int mi = 0; mi < 2; mi++) {
        int rr = bm + wm * 32 + mi * 16 + (lane >> 2);
#pragma unroll
        for (int ni = 0; ni < 4; ni++) {
            int c0 = bn + wn * 32 + ni * 8 + (lane & 3) * 2;
            float* p0 = C + (size_t)rr * N + c0;
            float* p1 = C + (size_t)(rr + 8) * N + c0;
            if (c0 < N)     { p0[0] = acc[mi][ni][0]; p1[0] = acc[mi][ni][2]; }
            if (c0 + 1 < N) { p0[1] = acc[mi][ni][1]; p1[1] = acc[mi][ni][3]; }
        }
    }
}

// ===== 64x64-tile layer GEMM: 256 thr, NT=2 (= (Ah+Al)*Bh, activations exact) ==
#define STAGE64 15360u           // Ah(5120) Al(5120) Bh(5120)
#define SMEM64  (NSTG * 15360)

template <int MODE>
__global__ void __launch_bounds__(256)
gemm64(const __half* __restrict__ Ah, const __half* __restrict__ Al,
       const __half* __restrict__ Bh,
       const float* __restrict__ bias, float* __restrict__ C,
       int N, int K) {
    extern __shared__ char smc[];
    unsigned sbase = (unsigned)__cvta_generic_to_shared(smc);
    int tid = threadIdx.x, lane = tid & 31, warp = tid >> 5;
    int wm = warp >> 2, wn = warp & 3;            // 2x4 warp grid
    int bm = blockIdx.x * 64, bn = blockIdx.y * 64;

    unsigned aoff[2][2];
#pragma unroll
    for (int mi = 0; mi < 2; mi++)
#pragma unroll
        for (int ks = 0; ks < 2; ks++) {
            int row = wm * 32 + mi * 16 + (lane & 15);
            int col = ks * 16 + ((lane & 16) ? 8 : 0);
            aoff[mi][ks] = (unsigned)(row * 40 + col) * 2;
        }
    unsigned boff[2];
#pragma unroll
    for (int ni = 0; ni < 2; ni++) {
        int row = wn * 16 + ni * 8 + (lane & 7);
        int col = (lane >> 3) * 8;
        boff[ni] = 10240u + (unsigned)(row * 40 + col) * 2;
    }

    int r  = tid >> 2;               // 0..63
    int cc = (tid & 3) * 8;

    float acc[2][2][4];
#pragma unroll
    for (int mi = 0; mi < 2; mi++)
#pragma unroll
        for (int ni = 0; ni < 2; ni++)
#pragma unroll
            for (int q = 0; q < 4; q++) acc[mi][ni][q] = 0.f;

    int T = K / 32;

#define FETCH64(s, kt) do {                                                    \
        int k0 = (kt) * 32;                                                    \
        unsigned dst = sbase + (unsigned)(s) * STAGE64 +                       \
                       (unsigned)(r * 40 + cc) * 2;                            \
        cpa16(dst,           Ah + (size_t)(bm + r) * K + k0 + cc, 16);         \
        cpa16(dst + 5120u,   Al + (size_t)(bm + r) * K + k0 + cc, 16);         \
        cpa16(dst + 10240u,  Bh + (size_t)(bn + r) * K + k0 + cc, 16);         \
    } while (0)

    FETCH64(0, 0);
    asm volatile("cp.async.commit_group;" ::: "memory");
    FETCH64(1, 1);
    asm volatile("cp.async.commit_group;" ::: "memory");
    FETCH64(2, 2);
    asm volatile("cp.async.commit_group;" ::: "memory");

    for (int i = 0; i < T; i++) {
        asm volatile("cp.async.wait_group 2;" ::: "memory");
        __syncthreads();

        if (i + 3 < T) FETCH64((i + 3) & (NSTG - 1), i + 3);
        asm volatile("cp.async.commit_group;" ::: "memory");

        unsigned st = sbase + (unsigned)(i & (NSTG - 1)) * STAGE64;
        unsigned Bhf[2][4];
#pragma unroll
        for (int ni = 0; ni < 2; ni++) ldsm4(Bhf[ni], st + boff[ni]);
#pragma unroll
        for (int ks = 0; ks < 2; ks++) {
            unsigned Ahf[2][4], Alf[2][4];
#pragma unroll
            for (int mi = 0; mi < 2; mi++) {
                ldsm4(Ahf[mi], st + aoff[mi][ks]);
                ldsm4(Alf[mi], st + aoff[mi][ks] + 5120u);
            }
#pragma unroll
            for (int mi = 0; mi < 2; mi++)
#pragma unroll
                for (int ni = 0; ni < 2; ni++) {
                    mma_f16(acc[mi][ni], Ahf[mi], &Bhf[ni][2 * ks]);
                    mma_f16(acc[mi][ni], Alf[mi], &Bhf[ni][2 * ks]);
                }
        }
    }
#undef FETCH64

#pragma unroll
    for (int mi = 0; mi < 2; mi++) {
        int rr = bm + wm * 32 + mi * 16 + (lane >> 2);
#pragma unroll
        for (int ni = 0; ni < 2; ni++) {
            int c0 = bn + wn * 16 + ni * 8 + (lane & 3) * 2;
            float* p0 = C + (size_t)rr * N + c0;
            float* p1 = C + (size_t)(rr + 8) * N + c0;
            float v0 = acc[mi][ni][0], v1 = acc[mi][ni][1];
            float v2 = acc[mi][ni][2], v3 = acc[mi][ni][3];
            if (MODE == 1) {
                float b0 = bias[c0], b1 = bias[c0 + 1];
                v0 = fast_sigmoid(v0 + b0); v1 = fast_sigmoid(v1 + b1);
                v2 = fast_sigmoid(v2 + b0); v3 = fast_sigmoid(v3 + b1);
            }
            if (MODE == 2) {
                p0[0] += v0; p0[1] += v1; p1[0] += v2; p1[1] += v3;
            } else {
                p0[0] = v0; p0[1] = v1; p1[0] = v2; p1[1] = v3;
            }
        }
    }
}

#define SMEMH (NSTG * 20480)

// ---------------- driver ---------------------------------------------------------
extern "C" void kernel_launch(void* const* d_in, const int* in_sizes, int n_in,
                              void* d_out, int out_size) {
    const int*   tokens = (const int*)  d_in[0];
    const float* emb    = (const float*)d_in[1];
    const float* ln_g   = (const float*)d_in[2];
    const float* ln_b   = (const float*)d_in[3];
    const float* in_w   = (const float*)d_in[4];
    const float* conv_w = (const float*)d_in[5];
    const float* conv_b = (const float*)d_in[6];
    const float* dt_w   = (const float*)d_in[7];
    const float* dt_b   = (const float*)d_in[8];
    const float* A_log  = (const float*)d_in[9];
    const float* D_par  = (const float*)d_in[10];
    const float* out_w  = (const float*)d_in[11];
    const float* lnf_g  = (const float*)d_in[12];
    const float* lnf_b  = (const float*)d_in[13];
    const float* head_w = (const float*)d_in[14];
    float* out = (float*)d_out;

    float *x, *xr, *xc, *dt;
    cudaGetSymbolAddress((void**)&x,  g_x);
    cudaGetSymbolAddress((void**)&xr, g_xr);
    cudaGetSymbolAddress((void**)&xc, g_xc);
    cudaGetSymbolAddress((void**)&dt, g_dt);
    __half *ah_xn, *al_xn, *ah_xc, *al_xc, *ah_y, *al_y;
    cudaGetSymbolAddress((void**)&ah_xn, g_ah_xn);
    cudaGetSymbolAddress((void**)&al_xn, g_al_xn);
    cudaGetSymbolAddress((void**)&ah_xc, g_ah_xc);
    cudaGetSymbolAddress((void**)&al_xc, g_al_xc);
    cudaGetSymbolAddress((void**)&ah_y,  g_ah_y);
    cudaGetSymbolAddress((void**)&al_y,  g_al_y);
    __half *wh_in, *wh_dt, *wh_out, *wh_hd;
    cudaGetSymbolAddress((void**)&wh_in,  g_wh_in);
    cudaGetSymbolAddress((void**)&wh_dt,  g_wh_dt);
    cudaGetSymbolAddress((void**)&wh_out, g_wh_out);
    cudaGetSymbolAddress((void**)&wh_hd,  g_wh_hd);

    cudaFuncSetAttribute(gemm64<0>, cudaFuncAttributeMaxDynamicSharedMemorySize, SMEM64);
    cudaFuncSetAttribute(gemm64<1>, cudaFuncAttributeMaxDynamicSharedMemorySize, SMEM64);
    cudaFuncSetAttribute(gemm64<2>, cudaFuncAttributeMaxDynamicSharedMemorySize, SMEM64);
    cudaFuncSetAttribute(gemm_head<0>, cudaFuncAttributeMaxDynamicSharedMemorySize, SMEMH);

    int n4_in = 4 * 2 * DIM * DIM / 4, n4_dt = 4 * DIM * DIM / 4;
    int n4_hd = NVOC * DIM / 4;

    wsplit1_kernel<<<(n4_in + 255) / 256, 256>>>((const float4*)in_w,
                                                 (uint2*)wh_in, n4_in);
    embed_kernel<<<BLD, 192>>>(tokens, emb);

    for (int l = 0; l < 4; l++) {
        ln_kernel<<<BLD, 256>>>(x, ln_g + l * DIM, ln_b + l * DIM, ah_xn, al_xn);
        gemm64<0><<<dim3(16, 24), 256, SMEM64>>>(
            ah_xn, al_xn, wh_in + (size_t)l * 2 * DIM * DIM,
            nullptr, xr, 2 * DIM, DIM);
        if (l == 0) {
            wsplit1_kernel<<<(n4_dt + 255) / 256, 256>>>((const float4*)dt_w,
                                                         (uint2*)wh_dt, n4_dt);
        }
        conv_silu_kernel<<<(BLD * DIM + 255) / 256, 256>>>(conv_w + l * DIM * 3,
                                                           conv_b + l * DIM);
        gemm64<1><<<dim3(16, 12), 256, SMEM64>>>(
            ah_xc, al_xc, wh_dt + (size_t)l * DIM * DIM,
            dt_b + l * DIM, dt, DIM, DIM);
        if (l == 0) {
            wsplit1_kernel<<<(n4_dt + 255) / 256, 256>>>((const float4*)out_w,
                                                         (uint2*)wh_out, n4_dt);
        }
        scan_kernel<<<192, 128>>>(A_log + l * DIM * NSTATE, D_par + l * DIM);
        gemm64<2><<<dim3(16, 12), 256, SMEM64>>>(
            ah_y, al_y, wh_out + (size_t)l * DIM * DIM,
            nullptr, x, DIM, DIM);
        if (l == 0) {
            wsplit1_kernel<<<(n4_hd + 255) / 256, 256>>>((const float4*)head_w,
                                                         (uint2*)wh_hd, n4_hd);
        }
    }

    ln_kernel<<<BLD, 256>>>(x, lnf_g, lnf_b, ah_xn, al_xn);
    // head: 1-term fp16 (last op, errors don't compound)
    gemm_head<0><<<dim3(8, (NVOC + 127) / 128), 512, SMEMH>>>(
        ah_xn, wh_hd, out, NVOC, DIM);
    (void)in_sizes; (void)n_in; (void)out_size;
}

// round 14
// speedup vs baseline: 2.8513x; 1.2007x over previous
#include <cuda_runtime.h>
#include <cuda_fp16.h>
#include <cstdint>

#define BLD   1024
#define DIM   768
#define LSEQ  512
#define NSTATE 16
#define NVOC  50257

// ---------------- fp32 scratch ----------------------------------------------
__device__ float g_x [BLD*DIM];
__device__ float g_xr[BLD*2*DIM];
__device__ float g_xc[BLD*DIM];
__device__ float g_dt[BLD*DIM];
// ---------------- split-fp16 activations -------------------------------------
__device__ __half g_ah_xn[BLD*DIM], g_al_xn[BLD*DIM];
__device__ __half g_ah_xc[BLD*DIM], g_al_xc[BLD*DIM];
__device__ __half g_ah_y [BLD*DIM], g_al_y [BLD*DIM];
// ---------------- fp16 weights (hi only — NT2 layers / NT1 head) --------------
__device__ __half g_wh_in [4*2*DIM*DIM];
__device__ __half g_wh_dt [4*DIM*DIM];
__device__ __half g_wh_out[4*DIM*DIM];
__device__ __half g_wh_hd [NVOC*DIM];

__device__ __forceinline__ float fast_sigmoid(float z) {
    return 1.0f / (1.0f + __expf(-z));
}
__device__ __forceinline__ void split_store(__half* ph, __half* pl, size_t i, float v) {
    __half h = __float2half_rn(v);
    ph[i] = h;
    pl[i] = __float2half_rn(v - __half2float(h));
}

// ---------------- weight fp16 prepass (hi only) --------------------------------
__global__ void wsplit1_kernel(const float4* __restrict__ src,
                               uint2* __restrict__ dh, int n4) {
    int i = blockIdx.x * blockDim.x + threadIdx.x;
    if (i >= n4) return;
    float4 v = src[i];
    __half2 h01 = __floats2half2_rn(v.x, v.y);
    __half2 h23 = __floats2half2_rn(v.z, v.w);
    dh[i] = make_uint2(*(unsigned*)&h01, *(unsigned*)&h23);
}

// ---------------- embedding gather --------------------------------------------
__global__ void embed_kernel(const int* __restrict__ tokens,
                             const float* __restrict__ emb) {
    int row = blockIdx.x;
    int tok = tokens[row];
    const float4* src = (const float4*)(emb + (size_t)tok * DIM);
    float4* dst = (float4*)(g_x + (size_t)row * DIM);
    dst[threadIdx.x] = src[threadIdx.x];
}

// ---------------- layernorm -> split fp16 --------------------------------------
__global__ void ln_kernel(const float* __restrict__ x,
                          const float* __restrict__ g,
                          const float* __restrict__ b,
                          __half* __restrict__ oh, __half* __restrict__ ol) {
    int row = blockIdx.x;
    const float* xp = x + (size_t)row * DIM;
    float s = 0.f, s2 = 0.f;
    for (int i = threadIdx.x; i < DIM; i += 256) {
        float v = xp[i];
        s += v; s2 += v * v;
    }
#pragma unroll
    for (int o = 16; o; o >>= 1) {
        s  += __shfl_xor_sync(0xffffffffu, s,  o);
        s2 += __shfl_xor_sync(0xffffffffu, s2, o);
    }
    __shared__ float sh[16];
    int w = threadIdx.x >> 5, lane = threadIdx.x & 31;
    if (lane == 0) { sh[w] = s; sh[8 + w] = s2; }
    __syncthreads();
    s = 0.f; s2 = 0.f;
#pragma unroll
    for (int i = 0; i < 8; i++) { s += sh[i]; s2 += sh[8 + i]; }
    float m   = s * (1.0f / DIM);
    float var = s2 * (1.0f / DIM) - m * m;
    float inv = rsqrtf(var + 1e-5f);
    for (int i = threadIdx.x; i < DIM; i += 256) {
        float v = (xp[i] - m) * inv * g[i] + b[i];
        split_store(oh, ol, (size_t)row * DIM + i, v);
    }
}

// ---------------- depthwise conv(3) + silu -------------------------------------
__global__ void conv_silu_kernel(const float* __restrict__ cw,
                                 const float* __restrict__ cb) {
    int idx = blockIdx.x * blockDim.x + threadIdx.x;
    if (idx >= BLD * DIM) return;
    int d = idx % DIM;
    int l = (idx / DIM) % LSEQ;
    int b = idx / (DIM * LSEQ);
    const float* base = g_xr + (size_t)b * LSEQ * (2 * DIM);
    float xm = (l > 0)        ? base[(size_t)(l - 1) * 2 * DIM + d] : 0.f;
    float x0 =                  base[(size_t)l       * 2 * DIM + d];
    float xp = (l < LSEQ - 1) ? base[(size_t)(l + 1) * 2 * DIM + d] : 0.f;
    float z = xm * cw[d * 3 + 0] + x0 * cw[d * 3 + 1] + xp * cw[d * 3 + 2] + cb[d];
    float v = z * fast_sigmoid(z);
    g_xc[idx] = v;
    split_store(g_ah_xc, g_al_xc, idx, v);
}

// ------- selective scan: pipelined loads + BATCHED shfl reductions -------------
// h-chain is pure FMA; the 8 butterfly reductions of a chunk run interleaved so
// their shfl latencies overlap instead of serializing per step.
#define SCH 8
__global__ void scan_kernel(const float* __restrict__ A_log,
                            const float* __restrict__ Dp) {
    int tid = blockIdx.x * blockDim.x + threadIdx.x;   // 24576
    int s = tid & (NSTATE - 1);
    int d = (tid >> 4) % DIM;
    int b = tid / (DIM * NSTATE);
    float A  = -__expf(A_log[d * NSTATE + s]);
    float Dd = Dp[d];
    const float* dtp  = g_dt + (size_t)b * LSEQ * DIM + d;
    const float* xcp  = g_xc + (size_t)b * LSEQ * DIM + d;
    const float* resp = g_xr + (size_t)b * LSEQ * (2 * DIM) + DIM + d;
    size_t ybase = (size_t)b * LSEQ * DIM + d;

    float dbuf[2][SCH], xbuf[2][SCH], rbuf[2][SCH];
#pragma unroll
    for (int c = 0; c < SCH; c++) {
        dbuf[0][c] = dtp[(size_t)c * DIM];
        xbuf[0][c] = xcp[(size_t)c * DIM];
        rbuf[0][c] = resp[(size_t)c * 2 * DIM];
    }
    float h = 0.f;

#define SCAN_CHUNK(BUF, L0) do {                                               \
        float sums[SCH];                                                       \
        _Pragma("unroll")                                                      \
        for (int c = 0; c < SCH; c++) {                                        \
            float e = __expf(A * dbuf[BUF][c]);                                \
            h = h * e + xbuf[BUF][c];                                          \
            sums[c] = h;                                                       \
        }                                                                      \
        _Pragma("unroll")                                                      \
        for (int o = 1; o <= 8; o <<= 1) {                                     \
            _Pragma("unroll")                                                  \
            for (int c = 0; c < SCH; c++)                                      \
                sums[c] += __shfl_xor_sync(0xffffffffu, sums[c], o);           \
        }                                                                      \
        if (s == 0) {                                                          \
            _Pragma("unroll")                                                  \
            for (int c = 0; c < SCH; c++) {                                    \
                float r = rbuf[BUF][c];                                        \
                float v = sums[c] * Dd * (r * fast_sigmoid(r));                \
                split_store(g_ah_y, g_al_y,                                    \
                            ybase + (size_t)((L0) + c) * DIM, v);              \
            }                                                                  \
        }                                                                      \
    } while (0)
#define SCAN_PREF(BUF, CH)                                                     \
    if ((CH) < LSEQ / SCH) {                                                   \
        int base = (CH) * SCH;                                                 \
        _Pragma("unroll")                                                      \
        for (int c = 0; c < SCH; c++) {                                        \
            dbuf[BUF][c] = dtp[(size_t)(base + c) * DIM];                      \
            xbuf[BUF][c] = xcp[(size_t)(base + c) * DIM];                      \
            rbuf[BUF][c] = resp[(size_t)(base + c) * 2 * DIM];                 \
        }                                                                      \
    }

#pragma unroll 1
    for (int ch = 0; ch < LSEQ / SCH; ch += 2) {
        SCAN_PREF(1, ch + 1);
        SCAN_CHUNK(0, ch * SCH);
        SCAN_PREF(0, ch + 2);
        SCAN_CHUNK(1, (ch + 1) * SCH);
    }
#undef SCAN_CHUNK
#undef SCAN_PREF
}

// ---------------- shared MMA primitives -----------------------------------------
__device__ __forceinline__ void ldsm4(unsigned r[4], unsigned a) {
    asm volatile("ldmatrix.sync.aligned.m8n8.x4.shared.b16 {%0,%1,%2,%3}, [%4];"
                 : "=r"(r[0]), "=r"(r[1]), "=r"(r[2]), "=r"(r[3]) : "r"(a));
}
__device__ __forceinline__ void mma_f16(float c[4], const unsigned a[4],
                                        const unsigned b[2]) {
    asm volatile(
        "mma.sync.aligned.m16n8k16.row.col.f32.f16.f16.f32 "
        "{%0,%1,%2,%3}, {%4,%5,%6,%7}, {%8,%9}, {%0,%1,%2,%3};"
        : "+f"(c[0]), "+f"(c[1]), "+f"(c[2]), "+f"(c[3])
        : "r"(a[0]), "r"(a[1]), "r"(a[2]), "r"(a[3]), "r"(b[0]), "r"(b[1]));
}
__device__ __forceinline__ void cpa16(unsigned dst, const void* src, int sz) {
    asm volatile("cp.async.cg.shared.global [%0], [%1], 16, %2;"
                 :: "r"(dst), "l"(src), "r"(sz));
}

#define NSTG 4

// ===== 128x128-tile head GEMM: 512 thr, NT=1 (AhBh only) =======================
template <int MODE>
__global__ void __launch_bounds__(512)
gemm_head(const __half* __restrict__ Ah, const __half* __restrict__ Bh,
          float* __restrict__ C, int N, int K) {
    constexpr unsigned STAGE_B = 20480u;
    extern __shared__ char smc[];
    unsigned sbase = (unsigned)__cvta_generic_to_shared(smc);
    int tid = threadIdx.x, lane = tid & 31, warp = tid >> 5;
    int wm = warp >> 2, wn = warp & 3;            // 4x4 warp grid
    int bm = blockIdx.x * 128, bn = blockIdx.y * 128;

    unsigned aoff[2][2];
#pragma unroll
    for (int mi = 0; mi < 2; mi++)
#pragma unroll
        for (int ks = 0; ks < 2; ks++) {
            int row = wm * 32 + mi * 16 + (lane & 15);
            int col = ks * 16 + ((lane & 16) ? 8 : 0);
            aoff[mi][ks] = (unsigned)(row * 40 + col) * 2;
        }
    unsigned boff[4];
#pragma unroll
    for (int ni = 0; ni < 4; ni++) {
        int row = wn * 32 + ni * 8 + (lane & 7);
        int col = (lane >> 3) * 8;
        boff[ni] = 10240u + (unsigned)(row * 40 + col) * 2;
    }

    int r  = tid >> 2;
    int cc = (tid & 3) * 8;

    float acc[2][4][4];
#pragma unroll
    for (int mi = 0; mi < 2; mi++)
#pragma unroll
        for (int ni = 0; ni < 4; ni++)
#pragma unroll
            for (int q = 0; q < 4; q++) acc[mi][ni][q] = 0.f;

    int T = K / 32;
    int brow = bn + r;
    int crow = brow < N ? brow : (N - 1);
    int bsz  = brow < N ? 16 : 0;

#define FETCH(s, kt) do {                                                      \
        int k0 = (kt) * 32;                                                    \
        unsigned dst = sbase + (unsigned)(s) * STAGE_B +                       \
                       (unsigned)(r * 40 + cc) * 2;                            \
        cpa16(dst,           Ah + (size_t)(bm + r) * K + k0 + cc, 16);         \
        cpa16(dst + 10240u,  Bh + (size_t)crow * K + k0 + cc, bsz);            \
    } while (0)

    FETCH(0, 0);
    asm volatile("cp.async.commit_group;" ::: "memory");
    FETCH(1, 1);
    asm volatile("cp.async.commit_group;" ::: "memory");
    FETCH(2, 2);
    asm volatile("cp.async.commit_group;" ::: "memory");

    for (int i = 0; i < T; i++) {
        asm volatile("cp.async.wait_group 2;" ::: "memory");
        __syncthreads();

        if (i + 3 < T) FETCH((i + 3) & (NSTG - 1), i + 3);
        asm volatile("cp.async.commit_group;" ::: "memory");

        unsigned st = sbase + (unsigned)(i & (NSTG - 1)) * STAGE_B;
        unsigned Bf[4][4];
#pragma unroll
        for (int ni = 0; ni < 4; ni++) ldsm4(Bf[ni], st + boff[ni]);
#pragma unroll
        for (int ks = 0; ks < 2; ks++) {
            unsigned Af[2][4];
#pragma unroll
            for (int mi = 0; mi < 2; mi++) ldsm4(Af[mi], st + aoff[mi][ks]);
#pragma unroll
            for (int mi = 0; mi < 2; mi++)
#pragma unroll
                for (int ni = 0; ni < 4; ni++)
                    mma_f16(acc[mi][ni], Af[mi], &Bf[ni][2 * ks]);
        }
    }
#undef FETCH

#pragma unroll
    for (int mi = 0; mi < 2; mi++) {
        int rr = bm + wm * 32 + mi * 16 + (lane >> 2);
#pragma unroll
        for (int ni = 0; ni < 4; ni++) {
            int c0 = bn + wn * 32 + ni * 8 + (lane & 3) * 2;
            float* p0 = C + (size_t)rr * N + c0;
            float* p1 = C + (size_t)(rr + 8) * N + c0;
            if (c0 < N)     { p0[0] = acc[mi][ni][0]; p1[0] = acc[mi][ni][2]; }
            if (c0 + 1 < N) { p0[1] = acc[mi][ni][1]; p1[1] = acc[mi][ni][3]; }
        }
    }
}

// ===== 64x64-tile layer GEMM: 256 thr, NT=2 (= (Ah+Al)*Bh, activations exact) ==
#define STAGE64 15360u           // Ah(5120) Al(5120) Bh(5120)
#define SMEM64  (NSTG * 15360)

template <int MODE>
__global__ void __launch_bounds__(256)
gemm64(const __half* __restrict__ Ah, const __half* __restrict__ Al,
       const __half* __restrict__ Bh,
       const float* __restrict__ bias, float* __restrict__ C,
       int N, int K) {
    extern __shared__ char smc[];
    unsigned sbase = (unsigned)__cvta_generic_to_shared(smc);
    int tid = threadIdx.x, lane = tid & 31, warp = tid >> 5;
    int wm = warp >> 2, wn = warp & 3;            // 2x4 warp grid
    int bm = blockIdx.x * 64, bn = blockIdx.y * 64;

    unsigned aoff[2][2];
#pragma unroll
    for (int mi = 0; mi < 2; mi++)
#pragma unroll
        for (int ks = 0; ks < 2; ks++) {
            int row = wm * 32 + mi * 16 + (lane & 15);
            int col = ks * 16 + ((lane & 16) ? 8 : 0);
            aoff[mi][ks] = (unsigned)(row * 40 + col) * 2;
        }
    unsigned boff[2];
#pragma unroll
    for (int ni = 0; ni < 2; ni++) {
        int row = wn * 16 + ni * 8 + (lane & 7);
        int col = (lane >> 3) * 8;
        boff[ni] = 10240u + (unsigned)(row * 40 + col) * 2;
    }

    int r  = tid >> 2;               // 0..63
    int cc = (tid & 3) * 8;

    float acc[2][2][4];
#pragma unroll
    for (int mi = 0; mi < 2; mi++)
#pragma unroll
        for (int ni = 0; ni < 2; ni++)
#pragma unroll
            for (int q = 0; q < 4; q++) acc[mi][ni][q] = 0.f;

    int T = K / 32;

#define FETCH64(s, kt) do {                                                    \
        int k0 = (kt) * 32;                                                    \
        unsigned dst = sbase + (unsigned)(s) * STAGE64 +                       \
                       (unsigned)(r * 40 + cc) * 2;                            \
        cpa16(dst,           Ah + (size_t)(bm + r) * K + k0 + cc, 16);         \
        cpa16(dst + 5120u,   Al + (size_t)(bm + r) * K + k0 + cc, 16);         \
        cpa16(dst + 10240u,  Bh + (size_t)(bn + r) * K + k0 + cc, 16);         \
    } while (0)

    FETCH64(0, 0);
    asm volatile("cp.async.commit_group;" ::: "memory");
    FETCH64(1, 1);
    asm volatile("cp.async.commit_group;" ::: "memory");
    FETCH64(2, 2);
    asm volatile("cp.async.commit_group;" ::: "memory");

    for (int i = 0; i < T; i++) {
        asm volatile("cp.async.wait_group 2;" ::: "memory");
        __syncthreads();

        if (i + 3 < T) FETCH64((i + 3) & (NSTG - 1), i + 3);
        asm volatile("cp.async.commit_group;" ::: "memory");

        unsigned st = sbase + (unsigned)(i & (NSTG - 1)) * STAGE64;
        unsigned Bhf[2][4];
#pragma unroll
        for (int ni = 0; ni < 2; ni++) ldsm4(Bhf[ni], st + boff[ni]);
#pragma unroll
        for (int ks = 0; ks < 2; ks++) {
            unsigned Ahf[2][4], Alf[2][4];
#pragma unroll
            for (int mi = 0; mi < 2; mi++) {
                ldsm4(Ahf[mi], st + aoff[mi][ks]);
                ldsm4(Alf[mi], st + aoff[mi][ks] + 5120u);
            }
#pragma unroll
            for (int mi = 0; mi < 2; mi++)
#pragma unroll
                for (int ni = 0; ni < 2; ni++) {
                    mma_f16(acc[mi][ni], Ahf[mi], &Bhf[ni][2 * ks]);
                    mma_f16(acc[mi][ni], Alf[mi], &Bhf[ni][2 * ks]);
                }
        }
    }
#undef FETCH64

#pragma unroll
    for (int mi = 0; mi < 2; mi++) {
        int rr = bm + wm * 32 + mi * 16 + (lane >> 2);
#pragma unroll
        for (int ni = 0; ni < 2; ni++) {
            int c0 = bn + wn * 16 + ni * 8 + (lane & 3) * 2;
            float* p0 = C + (size_t)rr * N + c0;
            float* p1 = C + (size_t)(rr + 8) * N + c0;
            float v0 = acc[mi][ni][0], v1 = acc[mi][ni][1];
            float v2 = acc[mi][ni][2], v3 = acc[mi][ni][3];
            if (MODE == 1) {
                float b0 = bias[c0], b1 = bias[c0 + 1];
                v0 = fast_sigmoid(v0 + b0); v1 = fast_sigmoid(v1 + b1);
                v2 = fast_sigmoid(v2 + b0); v3 = fast_sigmoid(v3 + b1);
            }
            if (MODE == 2) {
                p0[0] += v0; p0[1] += v1; p1[0] += v2; p1[1] += v3;
            } else {
                p0[0] = v0; p0[1] = v1; p1[0] = v2; p1[1] = v3;
            }
        }
    }
}

#define SMEMH (NSTG * 20480)

// ---------------- driver ---------------------------------------------------------
extern "C" void kernel_launch(void* const* d_in, const int* in_sizes, int n_in,
                              void* d_out, int out_size) {
    const int*   tokens = (const int*)  d_in[0];
    const float* emb    = (const float*)d_in[1];
    const float* ln_g   = (const float*)d_in[2];
    const float* ln_b   = (const float*)d_in[3];
    const float* in_w   = (const float*)d_in[4];
    const float* conv_w = (const float*)d_in[5];
    const float* conv_b = (const float*)d_in[6];
    const float* dt_w   = (const float*)d_in[7];
    const float* dt_b   = (const float*)d_in[8];
    const float* A_log  = (const float*)d_in[9];
    const float* D_par  = (const float*)d_in[10];
    const float* out_w  = (const float*)d_in[11];
    const float* lnf_g  = (const float*)d_in[12];
    const float* lnf_b  = (const float*)d_in[13];
    const float* head_w = (const float*)d_in[14];
    float* out = (float*)d_out;

    float *x, *xr, *xc, *dt;
    cudaGetSymbolAddress((void**)&x,  g_x);
    cudaGetSymbolAddress((void**)&xr, g_xr);
    cudaGetSymbolAddress((void**)&xc, g_xc);
    cudaGetSymbolAddress((void**)&dt, g_dt);
    __half *ah_xn, *al_xn, *ah_xc, *al_xc, *ah_y, *al_y;
    cudaGetSymbolAddress((void**)&ah_xn, g_ah_xn);
    cudaGetSymbolAddress((void**)&al_xn, g_al_xn);
    cudaGetSymbolAddress((void**)&ah_xc, g_ah_xc);
    cudaGetSymbolAddress((void**)&al_xc, g_al_xc);
    cudaGetSymbolAddress((void**)&ah_y,  g_ah_y);
    cudaGetSymbolAddress((void**)&al_y,  g_al_y);
    __half *wh_in, *wh_dt, *wh_out, *wh_hd;
    cudaGetSymbolAddress((void**)&wh_in,  g_wh_in);
    cudaGetSymbolAddress((void**)&wh_dt,  g_wh_dt);
    cudaGetSymbolAddress((void**)&wh_out, g_wh_out);
    cudaGetSymbolAddress((void**)&wh_hd,  g_wh_hd);

    cudaFuncSetAttribute(gemm64<0>, cudaFuncAttributeMaxDynamicSharedMemorySize, SMEM64);
    cudaFuncSetAttribute(gemm64<1>, cudaFuncAttributeMaxDynamicSharedMemorySize, SMEM64);
    cudaFuncSetAttribute(gemm64<2>, cudaFuncAttributeMaxDynamicSharedMemorySize, SMEM64);
    cudaFuncSetAttribute(gemm_head<0>, cudaFuncAttributeMaxDynamicSharedMemorySize, SMEMH);

    int n4_in = 4 * 2 * DIM * DIM / 4, n4_dt = 4 * DIM * DIM / 4;
    int n4_hd = NVOC * DIM / 4;

    wsplit1_kernel<<<(n4_in + 255) / 256, 256>>>((const float4*)in_w,
                                                 (uint2*)wh_in, n4_in);
    embed_kernel<<<BLD, 192>>>(tokens, emb);

    for (int l = 0; l < 4; l++) {
        ln_kernel<<<BLD, 256>>>(x, ln_g + l * DIM, ln_b + l * DIM, ah_xn, al_xn);
        gemm64<0><<<dim3(16, 24), 256, SMEM64>>>(
            ah_xn, al_xn, wh_in + (size_t)l * 2 * DIM * DIM,
            nullptr, xr, 2 * DIM, DIM);
        if (l == 0) {
            wsplit1_kernel<<<(n4_dt + 255) / 256, 256>>>((const float4*)dt_w,
                                                         (uint2*)wh_dt, n4_dt);
        }
        conv_silu_kernel<<<(BLD * DIM + 255) / 256, 256>>>(conv_w + l * DIM * 3,
                                                           conv_b + l * DIM);
        gemm64<1><<<dim3(16, 12), 256, SMEM64>>>(
            ah_xc, al_xc, wh_dt + (size_t)l * DIM * DIM,
            dt_b + l * DIM, dt, DIM, DIM);
        if (l == 0) {
            wsplit1_kernel<<<(n4_dt + 255) / 256, 256>>>((const float4*)out_w,
                                                         (uint2*)wh_out, n4_dt);
        }
        scan_kernel<<<192, 128>>>(A_log + l * DIM * NSTATE, D_par + l * DIM);
        gemm64<2><<<dim3(16, 12), 256, SMEM64>>>(
            ah_y, al_y, wh_out + (size_t)l * DIM * DIM,
            nullptr, x, DIM, DIM);
        if (l == 0) {
            wsplit1_kernel<<<(n4_hd + 255) / 256, 256>>>((const float4*)head_w,
                                                         (uint2*)wh_hd, n4_hd);
        }
    }

    ln_kernel<<<BLD, 256>>>(x, lnf_g, lnf_b, ah_xn, al_xn);
    // head: 1-term fp16 (last op, errors don't compound)
    gemm_head<0><<<dim3(8, (NVOC + 127) / 128), 512, SMEMH>>>(
        ah_xn, wh_hd, out, NVOC, DIM);
    (void)in_sizes; (void)n_in; (void)out_size;
}

// round 15
// speedup vs baseline: 2.8583x; 1.0025x over previous
#include <cuda_runtime.h>
#include <cuda_fp16.h>
#include <cstdint>

#define BLD   1024
#define DIM   768
#define LSEQ  512
#define NSTATE 16
#define NVOC  50257

// ---------------- fp32 scratch ----------------------------------------------
__device__ float g_x [BLD*DIM];
__device__ float g_xr[BLD*2*DIM];
__device__ float g_xc[BLD*DIM];
__device__ float g_dt[BLD*DIM];
// ---------------- split-fp16 activations -------------------------------------
__device__ __half g_ah_xn[BLD*DIM], g_al_xn[BLD*DIM];
__device__ __half g_ah_xc[BLD*DIM], g_al_xc[BLD*DIM];
__device__ __half g_ah_y [BLD*DIM], g_al_y [BLD*DIM];
// ---------------- fp16 weights (hi only — NT2 layers / NT1 head) --------------
__device__ __half g_wh_in [4*2*DIM*DIM];
__device__ __half g_wh_dt [4*DIM*DIM];
__device__ __half g_wh_out[4*DIM*DIM];
__device__ __half g_wh_hd [NVOC*DIM];

__device__ __forceinline__ float fast_sigmoid(float z) {
    return 1.0f / (1.0f + __expf(-z));
}
__device__ __forceinline__ void split_store(__half* ph, __half* pl, size_t i, float v) {
    __half h = __float2half_rn(v);
    ph[i] = h;
    pl[i] = __float2half_rn(v - __half2float(h));
}

// ---------------- merged weight fp16 prepass (all 4 tensors, one launch) -------
#define N4_IN  (4 * 2 * DIM * DIM / 4)
#define N4_DT  (4 * DIM * DIM / 4)
#define N4_HD  (NVOC * DIM / 4)
#define N4_TOT (N4_IN + 2 * N4_DT + N4_HD)

__global__ void wsplit_all_kernel(const float4* __restrict__ in_w,
                                  const float4* __restrict__ dt_w,
                                  const float4* __restrict__ out_w,
                                  const float4* __restrict__ head_w,
                                  uint2* __restrict__ d_in, uint2* __restrict__ d_dt,
                                  uint2* __restrict__ d_out, uint2* __restrict__ d_hd) {
    int i = blockIdx.x * blockDim.x + threadIdx.x;
    if (i >= N4_TOT) return;
    const float4* src;
    uint2* dst;
    int j = i;
    if (j < N4_HD) {                       // head first (largest, starts earliest)
        src = head_w; dst = d_hd;
    } else if ((j -= N4_HD) < N4_IN) {
        src = in_w; dst = d_in;
    } else if ((j -= N4_IN) < N4_DT) {
        src = dt_w; dst = d_dt;
    } else {
        j -= N4_DT;
        src = out_w; dst = d_out;
    }
    float4 v = src[j];
    __half2 h01 = __floats2half2_rn(v.x, v.y);
    __half2 h23 = __floats2half2_rn(v.z, v.w);
    dst[j] = make_uint2(*(unsigned*)&h01, *(unsigned*)&h23);
}

// ---------------- layernorm -> split fp16 (optionally fused embed gather) ------
template <int EMBED>
__global__ void ln_kernel(const float* __restrict__ x,
                          const int* __restrict__ tokens,
                          const float* __restrict__ emb,
                          const float* __restrict__ g,
                          const float* __restrict__ b,
                          __half* __restrict__ oh, __half* __restrict__ ol) {
    int row = blockIdx.x;
    const float* xp;
    if (EMBED) {
        int tok = tokens[row];
        xp = emb + (size_t)tok * DIM;
        // persist embedding into g_x for the residual stream
        float4* dst = (float4*)(g_x + (size_t)row * DIM);
        const float4* src = (const float4*)xp;
        for (int i = threadIdx.x; i < DIM / 4; i += 256) dst[i] = src[i];
    } else {
        xp = x + (size_t)row * DIM;
    }
    float s = 0.f, s2 = 0.f;
    for (int i = threadIdx.x; i < DIM; i += 256) {
        float v = xp[i];
        s += v; s2 += v * v;
    }
#pragma unroll
    for (int o = 16; o; o >>= 1) {
        s  += __shfl_xor_sync(0xffffffffu, s,  o);
        s2 += __shfl_xor_sync(0xffffffffu, s2, o);
    }
    __shared__ float sh[16];
    int w = threadIdx.x >> 5, lane = threadIdx.x & 31;
    if (lane == 0) { sh[w] = s; sh[8 + w] = s2; }
    __syncthreads();
    s = 0.f; s2 = 0.f;
#pragma unroll
    for (int i = 0; i < 8; i++) { s += sh[i]; s2 += sh[8 + i]; }
    float m   = s * (1.0f / DIM);
    float var = s2 * (1.0f / DIM) - m * m;
    float inv = rsqrtf(var + 1e-5f);
    for (int i = threadIdx.x; i < DIM; i += 256) {
        float v = (xp[i] - m) * inv * g[i] + b[i];
        split_store(oh, ol, (size_t)row * DIM + i, v);
    }
}

// ---------------- depthwise conv(3) + silu -------------------------------------
__global__ void conv_silu_kernel(const float* __restrict__ cw,
                                 const float* __restrict__ cb) {
    int idx = blockIdx.x * blockDim.x + threadIdx.x;
    if (idx >= BLD * DIM) return;
    int d = idx % DIM;
    int l = (idx / DIM) % LSEQ;
    int b = idx / (DIM * LSEQ);
    const float* base = g_xr + (size_t)b * LSEQ * (2 * DIM);
    float xm = (l > 0)        ? base[(size_t)(l - 1) * 2 * DIM + d] : 0.f;
    float x0 =                  base[(size_t)l       * 2 * DIM + d];
    float xp = (l < LSEQ - 1) ? base[(size_t)(l + 1) * 2 * DIM + d] : 0.f;
    float z = xm * cw[d * 3 + 0] + x0 * cw[d * 3 + 1] + xp * cw[d * 3 + 2] + cb[d];
    float v = z * fast_sigmoid(z);
    g_xc[idx] = v;
    split_store(g_ah_xc, g_al_xc, idx, v);
}

// ------- selective scan: pipelined loads + BATCHED shfl reductions -------------
// 96 blocks x 256 threads = exactly one wave across the chip.
#define SCH 8
__global__ void scan_kernel(const float* __restrict__ A_log,
                            const float* __restrict__ Dp) {
    int tid = blockIdx.x * blockDim.x + threadIdx.x;   // 24576
    int s = tid & (NSTATE - 1);
    int d = (tid >> 4) % DIM;
    int b = tid / (DIM * NSTATE);
    float A  = -__expf(A_log[d * NSTATE + s]);
    float Dd = Dp[d];
    const float* dtp  = g_dt + (size_t)b * LSEQ * DIM + d;
    const float* xcp  = g_xc + (size_t)b * LSEQ * DIM + d;
    const float* resp = g_xr + (size_t)b * LSEQ * (2 * DIM) + DIM + d;
    size_t ybase = (size_t)b * LSEQ * DIM + d;

    float dbuf[2][SCH], xbuf[2][SCH], rbuf[2][SCH];
#pragma unroll
    for (int c = 0; c < SCH; c++) {
        dbuf[0][c] = dtp[(size_t)c * DIM];
        xbuf[0][c] = xcp[(size_t)c * DIM];
        rbuf[0][c] = resp[(size_t)c * 2 * DIM];
    }
    float h = 0.f;

#define SCAN_CHUNK(BUF, L0) do {                                               \
        float sums[SCH];                                                       \
        _Pragma("unroll")                                                      \
        for (int c = 0; c < SCH; c++) {                                        \
            float e = __expf(A * dbuf[BUF][c]);                                \
            h = h * e + xbuf[BUF][c];                                          \
            sums[c] = h;                                                       \
        }                                                                      \
        _Pragma("unroll")                                                      \
        for (int o = 1; o <= 8; o <<= 1) {                                     \
            _Pragma("unroll")                                                  \
            for (int c = 0; c < SCH; c++)                                      \
                sums[c] += __shfl_xor_sync(0xffffffffu, sums[c], o);           \
        }                                                                      \
        if (s == 0) {                                                          \
            _Pragma("unroll")                                                  \
            for (int c = 0; c < SCH; c++) {                                    \
                float r = rbuf[BUF][c];                                        \
                float v = sums[c] * Dd * (r * fast_sigmoid(r));                \
                split_store(g_ah_y, g_al_y,                                    \
                            ybase + (size_t)((L0) + c) * DIM, v);              \
            }                                                                  \
        }                                                                      \
    } while (0)
#define SCAN_PREF(BUF, CH)                                                     \
    if ((CH) < LSEQ / SCH) {                                                   \
        int base = (CH) * SCH;                                                 \
        _Pragma("unroll")                                                      \
        for (int c = 0; c < SCH; c++) {                                        \
            dbuf[BUF][c] = dtp[(size_t)(base + c) * DIM];                      \
            xbuf[BUF][c] = xcp[(size_t)(base + c) * DIM];                      \
            rbuf[BUF][c] = resp[(size_t)(base + c) * 2 * DIM];                 \
        }                                                                      \
    }

#pragma unroll 1
    for (int ch = 0; ch < LSEQ / SCH; ch += 2) {
        SCAN_PREF(1, ch + 1);
        SCAN_CHUNK(0, ch * SCH);
        SCAN_PREF(0, ch + 2);
        SCAN_CHUNK(1, (ch + 1) * SCH);
    }
#undef SCAN_CHUNK
#undef SCAN_PREF
}

// ---------------- shared MMA primitives -----------------------------------------
__device__ __forceinline__ void ldsm4(unsigned r[4], unsigned a) {
    asm volatile("ldmatrix.sync.aligned.m8n8.x4.shared.b16 {%0,%1,%2,%3}, [%4];"
                 : "=r"(r[0]), "=r"(r[1]), "=r"(r[2]), "=r"(r[3]) : "r"(a));
}
__device__ __forceinline__ void mma_f16(float c[4], const unsigned a[4],
                                        const unsigned b[2]) {
    asm volatile(
        "mma.sync.aligned.m16n8k16.row.col.f32.f16.f16.f32 "
        "{%0,%1,%2,%3}, {%4,%5,%6,%7}, {%8,%9}, {%0,%1,%2,%3};"
        : "+f"(c[0]), "+f"(c[1]), "+f"(c[2]), "+f"(c[3])
        : "r"(a[0]), "r"(a[1]), "r"(a[2]), "r"(a[3]), "r"(b[0]), "r"(b[1]));
}
__device__ __forceinline__ void cpa16(unsigned dst, const void* src, int sz) {
    asm volatile("cp.async.cg.shared.global [%0], [%1], 16, %2;"
                 :: "r"(dst), "l"(src), "r"(sz));
}

#define NSTG 4

// ===== 128x128-tile head GEMM: 512 thr, NT=1 (AhBh only) =======================
template <int MODE>
__global__ void __launch_bounds__(512)
gemm_head(const __half* __restrict__ Ah, const __half* __restrict__ Bh,
          float* __restrict__ C, int N, int K) {
    constexpr unsigned STAGE_B = 20480u;
    extern __shared__ char smc[];
    unsigned sbase = (unsigned)__cvta_generic_to_shared(smc);
    int tid = threadIdx.x, lane = tid & 31, warp = tid >> 5;
    int wm = warp >> 2, wn = warp & 3;            // 4x4 warp grid
    int bm = blockIdx.x * 128, bn = blockIdx.y * 128;

    unsigned aoff[2][2];
#pragma unroll
    for (int mi = 0; mi < 2; mi++)
#pragma unroll
        for (int ks = 0; ks < 2; ks++) {
            int row = wm * 32 + mi * 16 + (lane & 15);
            int col = ks * 16 + ((lane & 16) ? 8 : 0);
            aoff[mi][ks] = (unsigned)(row * 40 + col) * 2;
        }
    unsigned boff[4];
#pragma unroll
    for (int ni = 0; ni < 4; ni++) {
        int row = wn * 32 + ni * 8 + (lane & 7);
        int col = (lane >> 3) * 8;
        boff[ni] = 10240u + (unsigned)(row * 40 + col) * 2;
    }

    int r  = tid >> 2;
    int cc = (tid & 3) * 8;

    float acc[2][4][4];
#pragma unroll
    for (int mi = 0; mi < 2; mi++)
#pragma unroll
        for (int ni = 0; ni < 4; ni++)
#pragma unroll
            for (int q = 0; q < 4; q++) acc[mi][ni][q] = 0.f;

    int T = K / 32;
    int brow = bn + r;
    int crow = brow < N ? brow : (N - 1);
    int bsz  = brow < N ? 16 : 0;

#define FETCH(s, kt) do {                                                      \
        int k0 = (kt) * 32;                                                    \
        unsigned dst = sbase + (unsigned)(s) * STAGE_B +                       \
                       (unsigned)(r * 40 + cc) * 2;                            \
        cpa16(dst,           Ah + (size_t)(bm + r) * K + k0 + cc, 16);         \
        cpa16(dst + 10240u,  Bh + (size_t)crow * K + k0 + cc, bsz);            \
    } while (0)

    FETCH(0, 0);
    asm volatile("cp.async.commit_group;" ::: "memory");
    FETCH(1, 1);
    asm volatile("cp.async.commit_group;" ::: "memory");
    FETCH(2, 2);
    asm volatile("cp.async.commit_group;" ::: "memory");

    for (int i = 0; i < T; i++) {
        asm volatile("cp.async.wait_group 2;" ::: "memory");
        __syncthreads();

        if (i + 3 < T) FETCH((i + 3) & (NSTG - 1), i + 3);
        asm volatile("cp.async.commit_group;" ::: "memory");

        unsigned st = sbase + (unsigned)(i & (NSTG - 1)) * STAGE_B;
        unsigned Bf[4][4];
#pragma unroll
        for (int ni = 0; ni < 4; ni++) ldsm4(Bf[ni], st + boff[ni]);
#pragma unroll
        for (int ks = 0; ks < 2; ks++) {
            unsigned Af[2][4];
#pragma unroll
            for (int mi = 0; mi < 2; mi++) ldsm4(Af[mi], st + aoff[mi][ks]);
#pragma unroll
            for (int mi = 0; mi < 2; mi++)
#pragma unroll
                for (int ni = 0; ni < 4; ni++)
                    mma_f16(acc[mi][ni], Af[mi], &Bf[ni][2 * ks]);
        }
    }
#undef FETCH

#pragma unroll
    for (int mi = 0; mi < 2; mi++) {
        int rr = bm + wm * 32 + mi * 16 + (lane >> 2);
#pragma unroll
        for (int ni = 0; ni < 4; ni++) {
            int c0 = bn + wn * 32 + ni * 8 + (lane & 3) * 2;
            float* p0 = C + (size_t)rr * N + c0;
            float* p1 = C + (size_t)(rr + 8) * N + c0;
            if (c0 < N)     { p0[0] = acc[mi][ni][0]; p1[0] = acc[mi][ni][2]; }
            if (c0 + 1 < N) { p0[1] = acc[mi][ni][1]; p1[1] = acc[mi][ni][3]; }
        }
    }
}

// ===== 64x64-tile layer GEMM: 256 thr, NT=2 (= (Ah+Al)*Bh, activations exact) ==
#define STAGE64 15360u           // Ah(5120) Al(5120) Bh(5120)
#define SMEM64  (NSTG * 15360)

template <int MODE>
__global__ void __launch_bounds__(256)
gemm64(const __half* __restrict__ Ah, const __half* __restrict__ Al,
       const __half* __restrict__ Bh,
       const float* __restrict__ bias, float* __restrict__ C,
       int N, int K) {
    extern __shared__ char smc[];
    unsigned sbase = (unsigned)__cvta_generic_to_shared(smc);
    int tid = threadIdx.x, lane = tid & 31, warp = tid >> 5;
    int wm = warp >> 2, wn = warp & 3;            // 2x4 warp grid
    int bm = blockIdx.x * 64, bn = blockIdx.y * 64;

    unsigned aoff[2][2];
#pragma unroll
    for (int mi = 0; mi < 2; mi++)
#pragma unroll
        for (int ks = 0; ks < 2; ks++) {
            int row = wm * 32 + mi * 16 + (lane & 15);
            int col = ks * 16 + ((lane & 16) ? 8 : 0);
            aoff[mi][ks] = (unsigned)(row * 40 + col) * 2;
        }
    unsigned boff[2];
#pragma unroll
    for (int ni = 0; ni < 2; ni++) {
        int row = wn * 16 + ni * 8 + (lane & 7);
        int col = (lane >> 3) * 8;
        boff[ni] = 10240u + (unsigned)(row * 40 + col) * 2;
    }

    int r  = tid >> 2;               // 0..63
    int cc = (tid & 3) * 8;

    float acc[2][2][4];
#pragma unroll
    for (int mi = 0; mi < 2; mi++)
#pragma unroll
        for (int ni = 0; ni < 2; ni++)
#pragma unroll
            for (int q = 0; q < 4; q++) acc[mi][ni][q] = 0.f;

    int T = K / 32;

#define FETCH64(s, kt) do {                                                    \
        int k0 = (kt) * 32;                                                    \
        unsigned dst = sbase + (unsigned)(s) * STAGE64 +                       \
                       (unsigned)(r * 40 + cc) * 2;                            \
        cpa16(dst,           Ah + (size_t)(bm + r) * K + k0 + cc, 16);         \
        cpa16(dst + 5120u,   Al + (size_t)(bm + r) * K + k0 + cc, 16);         \
        cpa16(dst + 10240u,  Bh + (size_t)(bn + r) * K + k0 + cc, 16);         \
    } while (0)

    FETCH64(0, 0);
    asm volatile("cp.async.commit_group;" ::: "memory");
    FETCH64(1, 1);
    asm volatile("cp.async.commit_group;" ::: "memory");
    FETCH64(2, 2);
    asm volatile("cp.async.commit_group;" ::: "memory");

    for (int i = 0; i < T; i++) {
        asm volatile("cp.async.wait_group 2;" ::: "memory");
        __syncthreads();

        if (i + 3 < T) FETCH64((i + 3) & (NSTG - 1), i + 3);
        asm volatile("cp.async.commit_group;" ::: "memory");

        unsigned st = sbase + (unsigned)(i & (NSTG - 1)) * STAGE64;
        unsigned Bhf[2][4];
#pragma unroll
        for (int ni = 0; ni < 2; ni++) ldsm4(Bhf[ni], st + boff[ni]);
#pragma unroll
        for (int ks = 0; ks < 2; ks++) {
            unsigned Ahf[2][4], Alf[2][4];
#pragma unroll
            for (int mi = 0; mi < 2; mi++) {
                ldsm4(Ahf[mi], st + aoff[mi][ks]);
                ldsm4(Alf[mi], st + aoff[mi][ks] + 5120u);
            }
#pragma unroll
            for (int mi = 0; mi < 2; mi++)
#pragma unroll
                for (int ni = 0; ni < 2; ni++) {
                    mma_f16(acc[mi][ni], Ahf[mi], &Bhf[ni][2 * ks]);
                    mma_f16(acc[mi][ni], Alf[mi], &Bhf[ni][2 * ks]);
                }
        }
    }
#undef FETCH64

#pragma unroll
    for (int mi = 0; mi < 2; mi++) {
        int rr = bm + wm * 32 + mi * 16 + (lane >> 2);
#pragma unroll
        for (int ni = 0; ni < 2; ni++) {
            int c0 = bn + wn * 16 + ni * 8 + (lane & 3) * 2;
            float* p0 = C + (size_t)rr * N + c0;
            float* p1 = C + (size_t)(rr + 8) * N + c0;
            float v0 = acc[mi][ni][0], v1 = acc[mi][ni][1];
            float v2 = acc[mi][ni][2], v3 = acc[mi][ni][3];
            if (MODE == 1) {
                float b0 = bias[c0], b1 = bias[c0 + 1];
                v0 = fast_sigmoid(v0 + b0); v1 = fast_sigmoid(v1 + b1);
                v2 = fast_sigmoid(v2 + b0); v3 = fast_sigmoid(v3 + b1);
            }
            if (MODE == 2) {
                p0[0] += v0; p0[1] += v1; p1[0] += v2; p1[1] += v3;
            } else {
                p0[0] = v0; p0[1] = v1; p1[0] = v2; p1[1] = v3;
            }
        }
    }
}

#define SMEMH (NSTG * 20480)

// ---------------- driver ---------------------------------------------------------
extern "C" void kernel_launch(void* const* d_in, const int* in_sizes, int n_in,
                              void* d_out, int out_size) {
    const int*   tokens = (const int*)  d_in[0];
    const float* emb    = (const float*)d_in[1];
    const float* ln_g   = (const float*)d_in[2];
    const float* ln_b   = (const float*)d_in[3];
    const float* in_w   = (const float*)d_in[4];
    const float* conv_w = (const float*)d_in[5];
    const float* conv_b = (const float*)d_in[6];
    const float* dt_w   = (const float*)d_in[7];
    const float* dt_b   = (const float*)d_in[8];
    const float* A_log  = (const float*)d_in[9];
    const float* D_par  = (const float*)d_in[10];
    const float* out_w  = (const float*)d_in[11];
    const float* lnf_g  = (const float*)d_in[12];
    const float* lnf_b  = (const float*)d_in[13];
    const float* head_w = (const float*)d_in[14];
    float* out = (float*)d_out;

    float *x, *xr, *xc, *dt;
    cudaGetSymbolAddress((void**)&x,  g_x);
    cudaGetSymbolAddress((void**)&xr, g_xr);
    cudaGetSymbolAddress((void**)&xc, g_xc);
    cudaGetSymbolAddress((void**)&dt, g_dt);
    __half *ah_xn, *al_xn, *ah_xc, *al_xc, *ah_y, *al_y;
    cudaGetSymbolAddress((void**)&ah_xn, g_ah_xn);
    cudaGetSymbolAddress((void**)&al_xn, g_al_xn);
    cudaGetSymbolAddress((void**)&ah_xc, g_ah_xc);
    cudaGetSymbolAddress((void**)&al_xc, g_al_xc);
    cudaGetSymbolAddress((void**)&ah_y,  g_ah_y);
    cudaGetSymbolAddress((void**)&al_y,  g_al_y);
    __half *wh_in, *wh_dt, *wh_out, *wh_hd;
    cudaGetSymbolAddress((void**)&wh_in,  g_wh_in);
    cudaGetSymbolAddress((void**)&wh_dt,  g_wh_dt);
    cudaGetSymbolAddress((void**)&wh_out, g_wh_out);
    cudaGetSymbolAddress((void**)&wh_hd,  g_wh_hd);

    cudaFuncSetAttribute(gemm64<0>, cudaFuncAttributeMaxDynamicSharedMemorySize, SMEM64);
    cudaFuncSetAttribute(gemm64<1>, cudaFuncAttributeMaxDynamicSharedMemorySize, SMEM64);
    cudaFuncSetAttribute(gemm64<2>, cudaFuncAttributeMaxDynamicSharedMemorySize, SMEM64);
    cudaFuncSetAttribute(gemm_head<0>, cudaFuncAttributeMaxDynamicSharedMemorySize, SMEMH);

    // single merged prepass: all four weight tensors in one full-chip wave
    wsplit_all_kernel<<<(N4_TOT + 255) / 256, 256>>>(
        (const float4*)in_w, (const float4*)dt_w,
        (const float4*)out_w, (const float4*)head_w,
        (uint2*)wh_in, (uint2*)wh_dt, (uint2*)wh_out, (uint2*)wh_hd);

    for (int l = 0; l < 4; l++) {
        if (l == 0) {
            // fused embed + LN (writes g_x and split-fp16 xn)
            ln_kernel<1><<<BLD, 256>>>(nullptr, tokens, emb,
                                       ln_g, ln_b, ah_xn, al_xn);
        } else {
            ln_kernel<0><<<BLD, 256>>>(x, nullptr, nullptr,
                                       ln_g + l * DIM, ln_b + l * DIM,
                                       ah_xn, al_xn);
        }
        gemm64<0><<<dim3(16, 24), 256, SMEM64>>>(
            ah_xn, al_xn, wh_in + (size_t)l * 2 * DIM * DIM,
            nullptr, xr, 2 * DIM, DIM);
        conv_silu_kernel<<<(BLD * DIM + 255) / 256, 256>>>(conv_w + l * DIM * 3,
                                                           conv_b + l * DIM);
        gemm64<1><<<dim3(16, 12), 256, SMEM64>>>(
            ah_xc, al_xc, wh_dt + (size_t)l * DIM * DIM,
            dt_b + l * DIM, dt, DIM, DIM);
        scan_kernel<<<96, 256>>>(A_log + l * DIM * NSTATE, D_par + l * DIM);
        gemm64<2><<<dim3(16, 12), 256, SMEM64>>>(
            ah_y, al_y, wh_out + (size_t)l * DIM * DIM,
            nullptr, x, DIM, DIM);
    }

    ln_kernel<0><<<BLD, 256>>>(x, nullptr, nullptr, lnf_g, lnf_b, ah_xn, al_xn);
    // head: 1-term fp16 (last op, errors don't compound)
    gemm_head<0><<<dim3(8, (NVOC + 127) / 128), 512, SMEMH>>>(
        ah_xn, wh_hd, out, NVOC, DIM);
    (void)in_sizes; (void)n_in; (void)out_size;
}